// round 2
// baseline (speedup 1.0000x reference)
#include <cuda_runtime.h>
#include <math.h>
#include <stdint.h>

// Problem constants
#define B_   4
#define S_   1024
#define D_   1024
#define H_   16
#define DK_  64
#define DFF_ 4096
#define NR_  4096          // B*S rows
#define BH_  64            // B*H

// ---------------------------------------------------------------------------
// Scratch (device globals; zero-init .bss — no allocations)
// ---------------------------------------------------------------------------
__device__ float g_q  [(size_t)NR_ * D_];
__device__ float g_k  [(size_t)NR_ * D_];
__device__ float g_v  [(size_t)NR_ * D_];
__device__ float g_sc [(size_t)BH_ * S_ * S_];   // attention scores / probs (256 MB)
__device__ float g_ctx[(size_t)NR_ * D_];
__device__ float g_t1 [(size_t)NR_ * D_];        // attn_out, then ffn out
__device__ float g_x1 [(size_t)NR_ * D_];
__device__ float g_ffh[(size_t)NR_ * DFF_];      // relu(x1@w1+b1)

// ---------------------------------------------------------------------------
// Generic GEMM: C[M,N] = A[M,K] @ B[K,N] + bias[N]   (optional ReLU)
// 128x128 tile, Ktile=16, 256 threads, 8x8 per-thread register blocking.
// Requires M%128==0, N%128==0, K%16==0 (true for all uses here).
// ---------------------------------------------------------------------------
__global__ __launch_bounds__(256)
void gemm_bias_kernel(const float* __restrict__ A,
                      const float* __restrict__ Bm,
                      const float* __restrict__ bias,
                      float* __restrict__ C,
                      int M, int N, int K, int relu)
{
    __shared__ float At[128][20];   // [m][kk], padded (16B-aligned float4 rows)
    __shared__ float Bs[16][132];   // [kk][n]

    const int tid = threadIdx.x;
    const int tx  = tid & 15;       // n-group
    const int ty  = tid >> 4;       // m-group
    const int m0  = blockIdx.y * 128;
    const int n0  = blockIdx.x * 128;

    float acc[8][8];
#pragma unroll
    for (int r = 0; r < 8; r++)
#pragma unroll
        for (int c = 0; c < 8; c++) acc[r][c] = 0.f;

    for (int k0 = 0; k0 < K; k0 += 16) {
#pragma unroll
        for (int l = 0; l < 8; l++) {
            int i  = tid + l * 256;            // 0..2047
            int m  = i >> 4, kk = i & 15;
            At[m][kk] = A[(size_t)(m0 + m) * K + (k0 + kk)];
            int kk2 = i >> 7, n = i & 127;
            Bs[kk2][n] = Bm[(size_t)(k0 + kk2) * N + (n0 + n)];
        }
        __syncthreads();

#pragma unroll
        for (int kc = 0; kc < 4; kc++) {
            float at[8][4];
#pragma unroll
            for (int r = 0; r < 8; r++) {
                float4 t = *(const float4*)&At[ty * 8 + r][kc * 4];
                at[r][0] = t.x; at[r][1] = t.y; at[r][2] = t.z; at[r][3] = t.w;
            }
#pragma unroll
            for (int u = 0; u < 4; u++) {
                float4 blo = *(const float4*)&Bs[kc * 4 + u][tx * 8];
                float4 bhi = *(const float4*)&Bs[kc * 4 + u][tx * 8 + 4];
#pragma unroll
                for (int r = 0; r < 8; r++) {
                    float a = at[r][u];
                    acc[r][0] += a * blo.x;  acc[r][1] += a * blo.y;
                    acc[r][2] += a * blo.z;  acc[r][3] += a * blo.w;
                    acc[r][4] += a * bhi.x;  acc[r][5] += a * bhi.y;
                    acc[r][6] += a * bhi.z;  acc[r][7] += a * bhi.w;
                }
            }
        }
        __syncthreads();
    }

    float4 blo = *(const float4*)&bias[n0 + tx * 8];
    float4 bhi = *(const float4*)&bias[n0 + tx * 8 + 4];
#pragma unroll
    for (int r = 0; r < 8; r++) {
        int m = m0 + ty * 8 + r;
        float4 o0, o1;
        o0.x = acc[r][0] + blo.x; o0.y = acc[r][1] + blo.y;
        o0.z = acc[r][2] + blo.z; o0.w = acc[r][3] + blo.w;
        o1.x = acc[r][4] + bhi.x; o1.y = acc[r][5] + bhi.y;
        o1.z = acc[r][6] + bhi.z; o1.w = acc[r][7] + bhi.w;
        if (relu) {
            o0.x = fmaxf(o0.x, 0.f); o0.y = fmaxf(o0.y, 0.f);
            o0.z = fmaxf(o0.z, 0.f); o0.w = fmaxf(o0.w, 0.f);
            o1.x = fmaxf(o1.x, 0.f); o1.y = fmaxf(o1.y, 0.f);
            o1.z = fmaxf(o1.z, 0.f); o1.w = fmaxf(o1.w, 0.f);
        }
        *(float4*)&C[(size_t)m * N + n0 + tx * 8]     = o0;
        *(float4*)&C[(size_t)m * N + n0 + tx * 8 + 4] = o1;
    }
}

// ---------------------------------------------------------------------------
// Attention scores: S[b,h,qi,kj] = (q.k)/8 + rel_table[qi-kj+1023, h]  (+mask)
// q,k in [B,S,D] layout (head h slice = cols h*64..h*64+63).
// grid: (S/64 ktile, S/64 qtile, B*H), 256 threads, 4x4 per thread.
// ---------------------------------------------------------------------------
__global__ __launch_bounds__(256)
void scores_kernel(const float* __restrict__ q,
                   const float* __restrict__ k,
                   const float* __restrict__ rel,
                   const int*   __restrict__ mask,
                   float* __restrict__ sc)
{
    __shared__ float Qs[64][68];
    __shared__ float Ks[64][68];

    const int kt = blockIdx.x, qt = blockIdx.y, bh = blockIdx.z;
    const int b = bh >> 4, h = bh & 15;
    const int tid = threadIdx.x;
    const int tx = tid & 15, ty = tid >> 4;

    const size_t qbase = ((size_t)b * S_ + qt * 64) * D_ + h * 64;
    const size_t kbase = ((size_t)b * S_ + kt * 64) * D_ + h * 64;

#pragma unroll
    for (int l = 0; l < 16; l++) {
        int i = tid + l * 256;           // 0..4095
        int row = i >> 6, d = i & 63;
        Qs[row][d] = q[qbase + (size_t)row * D_ + d];
        Ks[row][d] = k[kbase + (size_t)row * D_ + d];
    }
    __syncthreads();

    float acc[4][4];
#pragma unroll
    for (int i = 0; i < 4; i++)
#pragma unroll
        for (int j = 0; j < 4; j++) acc[i][j] = 0.f;

#pragma unroll
    for (int d4 = 0; d4 < 16; d4++) {
        float4 qa[4], kb[4];
#pragma unroll
        for (int i = 0; i < 4; i++) qa[i] = *(const float4*)&Qs[ty * 4 + i][d4 * 4];
#pragma unroll
        for (int j = 0; j < 4; j++) kb[j] = *(const float4*)&Ks[tx * 4 + j][d4 * 4];
#pragma unroll
        for (int i = 0; i < 4; i++)
#pragma unroll
            for (int j = 0; j < 4; j++)
                acc[i][j] += qa[i].x * kb[j].x + qa[i].y * kb[j].y +
                             qa[i].z * kb[j].z + qa[i].w * kb[j].w;
    }

    int mj[4];
#pragma unroll
    for (int j = 0; j < 4; j++) mj[j] = mask[b * S_ + kt * 64 + tx * 4 + j];

#pragma unroll
    for (int i = 0; i < 4; i++) {
        int qi = qt * 64 + ty * 4 + i;
#pragma unroll
        for (int j = 0; j < 4; j++) {
            int kj = kt * 64 + tx * 4 + j;
            int coord = qi - kj + (S_ - 1);                 // always in [0,2046]
            float sv = acc[i][j] * 0.125f + rel[coord * H_ + h];
            if (mj[j] == 0) sv = -1e9f;
            sc[((size_t)bh * S_ + qi) * S_ + kj] = sv;
        }
    }
}

// ---------------------------------------------------------------------------
// Row softmax over last dim (length S). One block per row.
// ---------------------------------------------------------------------------
__global__ __launch_bounds__(256)
void softmax_kernel(float* __restrict__ sc)
{
    __shared__ float red[256];
    const size_t base = (size_t)blockIdx.x * S_;
    const int tid = threadIdx.x;

    float v[4];
    float mx = -INFINITY;
#pragma unroll
    for (int l = 0; l < 4; l++) {
        v[l] = sc[base + tid + l * 256];
        mx = fmaxf(mx, v[l]);
    }
    red[tid] = mx; __syncthreads();
    for (int st = 128; st > 0; st >>= 1) {
        if (tid < st) red[tid] = fmaxf(red[tid], red[tid + st]);
        __syncthreads();
    }
    mx = red[0]; __syncthreads();

    float s = 0.f;
#pragma unroll
    for (int l = 0; l < 4; l++) { v[l] = __expf(v[l] - mx); s += v[l]; }
    red[tid] = s; __syncthreads();
    for (int st = 128; st > 0; st >>= 1) {
        if (tid < st) red[tid] += red[tid + st];
        __syncthreads();
    }
    float inv = 1.f / red[0];
#pragma unroll
    for (int l = 0; l < 4; l++) sc[base + tid + l * 256] = v[l] * inv;
}

// ---------------------------------------------------------------------------
// ctx[b, qi, h*64+d] = sum_k attn[bh,qi,k] * v[b,k,h*64+d]
// grid: (S/64 mtile, B*H), 256 threads, 4x4 per thread, 64-wide N (=DK).
// ---------------------------------------------------------------------------
__global__ __launch_bounds__(256)
void av_kernel(const float* __restrict__ attn,
               const float* __restrict__ v,
               float* __restrict__ ctx)
{
    __shared__ float At[64][20];    // [m][kk]
    __shared__ float Vs[16][68];    // [kk][d]

    const int mt = blockIdx.x, bh = blockIdx.y;
    const int b = bh >> 4, h = bh & 15;
    const int tid = threadIdx.x;
    const int tx = tid & 15, ty = tid >> 4;

    const size_t abase = ((size_t)bh * S_ + mt * 64) * S_;
    const size_t vbase = (size_t)b * S_ * D_ + h * 64;

    float acc[4][4];
#pragma unroll
    for (int i = 0; i < 4; i++)
#pragma unroll
        for (int j = 0; j < 4; j++) acc[i][j] = 0.f;

    for (int k0 = 0; k0 < S_; k0 += 16) {
#pragma unroll
        for (int l = 0; l < 4; l++) {
            int i = tid + l * 256;           // 0..1023
            int m = i >> 4, kk = i & 15;
            At[m][kk] = attn[abase + (size_t)m * S_ + k0 + kk];
            int kk2 = i >> 6, d = i & 63;
            Vs[kk2][d] = v[vbase + (size_t)(k0 + kk2) * D_ + d];
        }
        __syncthreads();

#pragma unroll
        for (int kc = 0; kc < 4; kc++) {
            float at[4][4];
#pragma unroll
            for (int i = 0; i < 4; i++) {
                float4 t = *(const float4*)&At[ty * 4 + i][kc * 4];
                at[i][0] = t.x; at[i][1] = t.y; at[i][2] = t.z; at[i][3] = t.w;
            }
#pragma unroll
            for (int u = 0; u < 4; u++) {
                float4 bv = *(const float4*)&Vs[kc * 4 + u][tx * 4];
#pragma unroll
                for (int i = 0; i < 4; i++) {
                    float a = at[i][u];
                    acc[i][0] += a * bv.x; acc[i][1] += a * bv.y;
                    acc[i][2] += a * bv.z; acc[i][3] += a * bv.w;
                }
            }
        }
        __syncthreads();
    }

#pragma unroll
    for (int i = 0; i < 4; i++) {
        int m = mt * 64 + ty * 4 + i;
        float4 o;
        o.x = acc[i][0]; o.y = acc[i][1]; o.z = acc[i][2]; o.w = acc[i][3];
        *(float4*)&ctx[((size_t)b * S_ + m) * D_ + h * 64 + tx * 4] = o;
    }
}

// ---------------------------------------------------------------------------
// out[row] = LayerNorm(x[row] + y[row]) * g + b     (row length D=1024)
// One block (256 threads) per row.
// ---------------------------------------------------------------------------
__global__ __launch_bounds__(256)
void add_ln_kernel(const float* __restrict__ x,
                   const float* __restrict__ y,
                   const float* __restrict__ g,
                   const float* __restrict__ b,
                   float* __restrict__ out)
{
    __shared__ float red[256];
    const size_t base = (size_t)blockIdx.x * D_;
    const int tid = threadIdx.x;

    float v[4];
    float s = 0.f;
#pragma unroll
    for (int l = 0; l < 4; l++) {
        int i = tid + l * 256;
        v[l] = x[base + i] + y[base + i];
        s += v[l];
    }
    red[tid] = s; __syncthreads();
    for (int st = 128; st > 0; st >>= 1) {
        if (tid < st) red[tid] += red[tid + st];
        __syncthreads();
    }
    float mean = red[0] * (1.0f / D_); __syncthreads();

    float sq = 0.f;
#pragma unroll
    for (int l = 0; l < 4; l++) { float d = v[l] - mean; sq += d * d; }
    red[tid] = sq; __syncthreads();
    for (int st = 128; st > 0; st >>= 1) {
        if (tid < st) red[tid] += red[tid + st];
        __syncthreads();
    }
    float var = red[0] * (1.0f / D_);
    float rstd = rsqrtf(var + 1e-5f);

#pragma unroll
    for (int l = 0; l < 4; l++) {
        int i = tid + l * 256;
        out[base + i] = (v[l] - mean) * rstd * g[i] + b[i];
    }
}

// ---------------------------------------------------------------------------
// Launch
// ---------------------------------------------------------------------------
extern "C" void kernel_launch(void* const* d_in, const int* in_sizes, int n_in,
                              void* d_out, int out_size)
{
    const float* x     = (const float*)d_in[0];
    const float* wq    = (const float*)d_in[1];
    const float* bq    = (const float*)d_in[2];
    const float* wk    = (const float*)d_in[3];
    const float* bk    = (const float*)d_in[4];
    const float* wv    = (const float*)d_in[5];
    const float* bv    = (const float*)d_in[6];
    const float* wo    = (const float*)d_in[7];
    const float* bo    = (const float*)d_in[8];
    const float* rel   = (const float*)d_in[9];
    const float* ln1g  = (const float*)d_in[10];
    const float* ln1b  = (const float*)d_in[11];
    const float* w1    = (const float*)d_in[12];
    const float* b1    = (const float*)d_in[13];
    const float* w2    = (const float*)d_in[14];
    const float* b2    = (const float*)d_in[15];
    const float* ln2g  = (const float*)d_in[16];
    const float* ln2b  = (const float*)d_in[17];
    const int*   mask  = (const int*)  d_in[18];
    float* out = (float*)d_out;

    float *pq, *pk, *pv, *psc, *pctx, *pt1, *px1, *pffh;
    cudaGetSymbolAddress((void**)&pq,   g_q);
    cudaGetSymbolAddress((void**)&pk,   g_k);
    cudaGetSymbolAddress((void**)&pv,   g_v);
    cudaGetSymbolAddress((void**)&psc,  g_sc);
    cudaGetSymbolAddress((void**)&pctx, g_ctx);
    cudaGetSymbolAddress((void**)&pt1,  g_t1);
    cudaGetSymbolAddress((void**)&px1,  g_x1);
    cudaGetSymbolAddress((void**)&pffh, g_ffh);

    dim3 blk(256);

    // QKV projections: [4096,1024] @ [1024,1024]
    dim3 gProj(D_ / 128, NR_ / 128);
    gemm_bias_kernel<<<gProj, blk>>>(x, wq, bq, pq, NR_, D_, D_, 0);
    gemm_bias_kernel<<<gProj, blk>>>(x, wk, bk, pk, NR_, D_, D_, 0);
    gemm_bias_kernel<<<gProj, blk>>>(x, wv, bv, pv, NR_, D_, D_, 0);

    // Attention scores + bias + mask
    dim3 gSc(S_ / 64, S_ / 64, BH_);
    scores_kernel<<<gSc, blk>>>(pq, pk, rel, mask, psc);

    // Softmax (one block per row)
    softmax_kernel<<<BH_ * S_, blk>>>(psc);

    // ctx = attn @ v
    dim3 gAv(S_ / 64, BH_);
    av_kernel<<<gAv, blk>>>(psc, pv, pctx);

    // Output projection
    gemm_bias_kernel<<<gProj, blk>>>(pctx, wo, bo, pt1, NR_, D_, D_, 0);

    // x1 = LN(x + attn_out)
    add_ln_kernel<<<NR_, blk>>>(x, pt1, ln1g, ln1b, px1);

    // FFN
    dim3 gF1(DFF_ / 128, NR_ / 128);
    gemm_bias_kernel<<<gF1, blk>>>(px1, w1, b1, pffh, NR_, DFF_, D_, 1);
    dim3 gF2(D_ / 128, NR_ / 128);
    gemm_bias_kernel<<<gF2, blk>>>(pffh, w2, b2, pt1, NR_, D_, DFF_, 0);

    // out = LN(x1 + ff)
    add_ln_kernel<<<NR_, blk>>>(px1, pt1, ln2g, ln2b, out);
}

// round 4
// speedup vs baseline: 2.0790x; 2.0790x over previous
#include <cuda_runtime.h>
#include <cuda_bf16.h>
#include <math.h>
#include <stdint.h>

// Problem constants
#define B_   4
#define S_   1024
#define D_   1024
#define H_   16
#define DK_  64
#define DFF_ 4096
#define NR_  4096          // B*S rows
#define BH_  64            // B*H

typedef __nv_bfloat16 bf16;

// ---------------------------------------------------------------------------
// Scratch (device globals; .bss — no allocations)
// ---------------------------------------------------------------------------
__device__ float g_q  [(size_t)NR_ * D_];
__device__ float g_k  [(size_t)NR_ * D_];
__device__ float g_v  [(size_t)NR_ * D_];
__device__ float g_kt [(size_t)BH_ * DK_ * S_];      // K transposed per head: [bh][d][s]
__device__ float g_sc [(size_t)BH_ * S_ * S_];       // scores / probs (256 MB)
__device__ float g_t1 [(size_t)NR_ * D_];
__device__ float g_x1 [(size_t)NR_ * D_];

// bf16 hi/lo split buffers
__device__ bf16 g_xh  [(size_t)NR_ * D_];
__device__ bf16 g_xl  [(size_t)NR_ * D_];
__device__ bf16 g_ctxh[(size_t)NR_ * D_];
__device__ bf16 g_ctxl[(size_t)NR_ * D_];
__device__ bf16 g_x1h [(size_t)NR_ * D_];
__device__ bf16 g_x1l [(size_t)NR_ * D_];
__device__ bf16 g_ffh [(size_t)NR_ * DFF_];
__device__ bf16 g_ffl [(size_t)NR_ * DFF_];
// transposed+split weights: [N,K] bf16
__device__ bf16 g_wqTh[(size_t)D_ * D_];
__device__ bf16 g_wqTl[(size_t)D_ * D_];
__device__ bf16 g_wkTh[(size_t)D_ * D_];
__device__ bf16 g_wkTl[(size_t)D_ * D_];
__device__ bf16 g_wvTh[(size_t)D_ * D_];
__device__ bf16 g_wvTl[(size_t)D_ * D_];
__device__ bf16 g_woTh[(size_t)D_ * D_];
__device__ bf16 g_woTl[(size_t)D_ * D_];
__device__ bf16 g_w1Th[(size_t)DFF_ * D_];
__device__ bf16 g_w1Tl[(size_t)DFF_ * D_];
__device__ bf16 g_w2Th[(size_t)D_ * DFF_];
__device__ bf16 g_w2Tl[(size_t)D_ * DFF_];

// ---------------------------------------------------------------------------
// Warp-MMA primitives (ldmatrix + mma.sync, portable to plain compute_103)
// ---------------------------------------------------------------------------
__device__ __forceinline__ uint32_t smem_to_u32(const void* p) {
    uint32_t a;
    asm("{ .reg .u64 t; cvta.to.shared.u64 t, %1; cvt.u32.u64 %0, t; }"
        : "=r"(a) : "l"(p));
    return a;
}

__device__ __forceinline__ void ldmx4(uint32_t* r, uint32_t addr) {
    asm volatile("ldmatrix.sync.aligned.m8n8.x4.shared.b16 {%0,%1,%2,%3}, [%4];"
                 : "=r"(r[0]), "=r"(r[1]), "=r"(r[2]), "=r"(r[3]) : "r"(addr));
}

__device__ __forceinline__ void mma_bf16(float* c, const uint32_t* a,
                                         const uint32_t* b) {
    asm volatile(
        "mma.sync.aligned.m16n8k16.row.col.f32.bf16.bf16.f32 "
        "{%0,%1,%2,%3}, {%4,%5,%6,%7}, {%8,%9}, {%0,%1,%2,%3};"
        : "+f"(c[0]), "+f"(c[1]), "+f"(c[2]), "+f"(c[3])
        : "r"(a[0]), "r"(a[1]), "r"(a[2]), "r"(a[3]), "r"(b[0]), "r"(b[1]));
}

// ---------------------------------------------------------------------------
// Tensor-core GEMM (mma.sync): C[M,N] = A[M,K] @ B^T + bias, 3-term bf16 split
// A: [M,K] (hi,lo). B: [N,K] (hi,lo). 128x128 CTA tile, 8 warps 2x4 (64x32
// warp tile). Kchunk=64; all 4 tiles resident -> 3 products per chunk.
// Outputs: Cf (fp32) and/or Chi/Clo (bf16 split), optional relu.
// ---------------------------------------------------------------------------
#define GT_ROWB   144                       // padded row bytes (64 bf16 + 8 pad)
#define GT_TILE   (128 * GT_ROWB)           // 18432 B per tile
#define GEMM_SMEM (4 * GT_TILE)             // 73728 B

__global__ __launch_bounds__(256)
void gemm_tc_kernel(const bf16* __restrict__ Ahi, const bf16* __restrict__ Alo,
                    const bf16* __restrict__ Bhi, const bf16* __restrict__ Blo,
                    const float* __restrict__ bias,
                    float* __restrict__ Cf,
                    bf16* __restrict__ Chi, bf16* __restrict__ Clo,
                    int M, int N, int K, int relu)
{
    extern __shared__ char smem[];
    const uint32_t sbase = smem_to_u32(smem);

    const int tid  = threadIdx.x;
    const int wid  = tid >> 5;
    const int lane = tid & 31;
    const int warpM = wid >> 2;       // 0..1 -> m offset 64
    const int warpN = wid & 3;        // 0..3 -> n offset 32
    const int m0 = blockIdx.y * 128;
    const int n0 = blockIdx.x * 128;

    // smem tile order: 0=Ahi 1=Alo 2=Bhi 3=Blo
    const bf16* srcs[4] = { Ahi + (size_t)m0 * K, Alo + (size_t)m0 * K,
                            Bhi + (size_t)n0 * K, Blo + (size_t)n0 * K };

    float acc[4][4][4];
#pragma unroll
    for (int i = 0; i < 4; i++)
#pragma unroll
        for (int j = 0; j < 4; j++)
#pragma unroll
            for (int r = 0; r < 4; r++) acc[i][j][r] = 0.f;

    // per-thread ldmatrix address components (bytes)
    const uint32_t aoff = (uint32_t)(lane & 15) * GT_ROWB + (uint32_t)(lane >> 4) * 16;
    const uint32_t boff = (uint32_t)(((lane >> 4) * 8) + (lane & 7)) * GT_ROWB
                        + (uint32_t)((lane >> 3) & 1) * 16;
    const uint32_t aBaseHi = sbase + 0 * GT_TILE + (uint32_t)warpM * 64 * GT_ROWB + aoff;
    const uint32_t aBaseLo = sbase + 1 * GT_TILE + (uint32_t)warpM * 64 * GT_ROWB + aoff;
    const uint32_t bBaseHi = sbase + 2 * GT_TILE + (uint32_t)warpN * 32 * GT_ROWB + boff;
    const uint32_t bBaseLo = sbase + 3 * GT_TILE + (uint32_t)warpN * 32 * GT_ROWB + boff;

    for (int k0 = 0; k0 < K; k0 += 64) {
        __syncthreads();
        // load 4 tiles: 4096 float4 chunks, 16 per thread
#pragma unroll
        for (int l = 0; l < 16; l++) {
            int i = tid + l * 256;
            int t = i >> 10, j = i & 1023;
            int row = j >> 3, kc = j & 7;
            *(float4*)(smem + t * GT_TILE + row * GT_ROWB + kc * 16) =
                *(const float4*)(srcs[t] + (size_t)row * K + k0 + kc * 8);
        }
        __syncthreads();

#pragma unroll
        for (int ks = 0; ks < 4; ks++) {
            uint32_t af[4][4], bh_[4][2], bl_[4][2];
            // A-hi fragments (4 x 16 rows)
#pragma unroll
            for (int fm = 0; fm < 4; fm++)
                ldmx4(af[fm], aBaseHi + (uint32_t)fm * 16 * GT_ROWB + ks * 32);
            // B-hi fragments (2 x ldmatrix.x4 -> 4 n-frags)
#pragma unroll
            for (int g = 0; g < 2; g++) {
                uint32_t r[4];
                ldmx4(r, bBaseHi + (uint32_t)g * 16 * GT_ROWB + ks * 32);
                bh_[g * 2][0] = r[0]; bh_[g * 2][1] = r[1];
                bh_[g * 2 + 1][0] = r[2]; bh_[g * 2 + 1][1] = r[3];
            }
#pragma unroll
            for (int fm = 0; fm < 4; fm++)
#pragma unroll
                for (int fn = 0; fn < 4; fn++)
                    mma_bf16(acc[fm][fn], af[fm], bh_[fn]);
            // B-lo
#pragma unroll
            for (int g = 0; g < 2; g++) {
                uint32_t r[4];
                ldmx4(r, bBaseLo + (uint32_t)g * 16 * GT_ROWB + ks * 32);
                bl_[g * 2][0] = r[0]; bl_[g * 2][1] = r[1];
                bl_[g * 2 + 1][0] = r[2]; bl_[g * 2 + 1][1] = r[3];
            }
#pragma unroll
            for (int fm = 0; fm < 4; fm++)
#pragma unroll
                for (int fn = 0; fn < 4; fn++)
                    mma_bf16(acc[fm][fn], af[fm], bl_[fn]);
            // A-lo (overwrite af)
#pragma unroll
            for (int fm = 0; fm < 4; fm++)
                ldmx4(af[fm], aBaseLo + (uint32_t)fm * 16 * GT_ROWB + ks * 32);
#pragma unroll
            for (int fm = 0; fm < 4; fm++)
#pragma unroll
                for (int fn = 0; fn < 4; fn++)
                    mma_bf16(acc[fm][fn], af[fm], bh_[fn]);
        }
    }

    // Epilogue
    const int qr = lane >> 2;          // quad row 0..7
    const int qc = (lane & 3) * 2;     // quad col 0,2,4,6
#pragma unroll
    for (int fm = 0; fm < 4; fm++) {
#pragma unroll
        for (int fn = 0; fn < 4; fn++) {
            float* a = acc[fm][fn];
            int row = m0 + warpM * 64 + fm * 16 + qr;
            int col = n0 + warpN * 32 + fn * 8 + qc;
            float b0 = bias[col], b1 = bias[col + 1];
            float v00 = a[0] + b0, v01 = a[1] + b1;
            float v10 = a[2] + b0, v11 = a[3] + b1;
            if (relu) {
                v00 = fmaxf(v00, 0.f); v01 = fmaxf(v01, 0.f);
                v10 = fmaxf(v10, 0.f); v11 = fmaxf(v11, 0.f);
            }
            size_t i0 = (size_t)row * N + col;
            size_t i1 = (size_t)(row + 8) * N + col;
            if (Cf) {
                *(float2*)&Cf[i0] = make_float2(v00, v01);
                *(float2*)&Cf[i1] = make_float2(v10, v11);
            }
            if (Chi) {
                bf16 h00 = __float2bfloat16(v00), h01 = __float2bfloat16(v01);
                bf16 h10 = __float2bfloat16(v10), h11 = __float2bfloat16(v11);
                *(__nv_bfloat162*)&Chi[i0] = __nv_bfloat162(h00, h01);
                *(__nv_bfloat162*)&Chi[i1] = __nv_bfloat162(h10, h11);
                *(__nv_bfloat162*)&Clo[i0] = __nv_bfloat162(
                    __float2bfloat16(v00 - __bfloat162float(h00)),
                    __float2bfloat16(v01 - __bfloat162float(h01)));
                *(__nv_bfloat162*)&Clo[i1] = __nv_bfloat162(
                    __float2bfloat16(v10 - __bfloat162float(h10)),
                    __float2bfloat16(v11 - __bfloat162float(h11)));
            }
        }
    }
}

// ---------------------------------------------------------------------------
// fp32 -> bf16 hi/lo split (elementwise, vectorized)
// ---------------------------------------------------------------------------
__global__ __launch_bounds__(256)
void split_kernel(const float* __restrict__ X, bf16* __restrict__ Xh,
                  bf16* __restrict__ Xl, size_t n4)
{
    size_t i = (size_t)blockIdx.x * 256 + threadIdx.x;
    if (i >= n4) return;
    float4 v = ((const float4*)X)[i];
    bf16 h0 = __float2bfloat16(v.x), h1 = __float2bfloat16(v.y);
    bf16 h2 = __float2bfloat16(v.z), h3 = __float2bfloat16(v.w);
    size_t o = i * 4;
    Xh[o] = h0; Xh[o+1] = h1; Xh[o+2] = h2; Xh[o+3] = h3;
    Xl[o]   = __float2bfloat16(v.x - __bfloat162float(h0));
    Xl[o+1] = __float2bfloat16(v.y - __bfloat162float(h1));
    Xl[o+2] = __float2bfloat16(v.z - __bfloat162float(h2));
    Xl[o+3] = __float2bfloat16(v.w - __bfloat162float(h3));
}

// ---------------------------------------------------------------------------
// W[K,N] fp32 -> transposed hi/lo bf16 [N,K]
// ---------------------------------------------------------------------------
__global__ __launch_bounds__(256)
void tsplit_kernel(const float* __restrict__ W, bf16* __restrict__ Th,
                   bf16* __restrict__ Tl, int K, int N)
{
    __shared__ float t[32][33];
    const int k0 = blockIdx.y * 32, n0 = blockIdx.x * 32;
    const int tx = threadIdx.x & 31, ty = threadIdx.x >> 5;
    for (int r = ty; r < 32; r += 8)
        t[r][tx] = W[(size_t)(k0 + r) * N + n0 + tx];
    __syncthreads();
    for (int r = ty; r < 32; r += 8) {
        float v = t[tx][r];     // = W[k0+tx][n0+r]
        bf16 h = __float2bfloat16(v);
        size_t oi = (size_t)(n0 + r) * K + k0 + tx;
        Th[oi] = h;
        Tl[oi] = __float2bfloat16(v - __bfloat162float(h));
    }
}

// ---------------------------------------------------------------------------
// K [B,S,D] -> kT [bh][d][s]
// ---------------------------------------------------------------------------
__global__ __launch_bounds__(256)
void ktrans_kernel(const float* __restrict__ k, float* __restrict__ kt)
{
    __shared__ float t[32][33];
    const int s0 = blockIdx.x * 32, d0 = blockIdx.y * 32, b = blockIdx.z;
    const int tx = threadIdx.x & 31, ty = threadIdx.x >> 5;
    for (int r = ty; r < 32; r += 8)
        t[r][tx] = k[((size_t)b * S_ + s0 + r) * D_ + d0 + tx];
    __syncthreads();
    const int h = d0 >> 6, dl = d0 & 63;
    for (int r = ty; r < 32; r += 8)
        kt[((size_t)(b * H_ + h) * DK_ + dl + r) * S_ + s0 + tx] = t[tx][r];
}

// ---------------------------------------------------------------------------
// Scores: 128x128 tile, 8x8 register blocking (conflict-free LDS)
// sc[bh,qi,kj] = (q.k)/8 + rel[qi-kj+1023, h]  (+mask)
// ---------------------------------------------------------------------------
__global__ __launch_bounds__(256)
void scores2_kernel(const float* __restrict__ q, const float* __restrict__ kt,
                    const float* __restrict__ rel, const int* __restrict__ mask,
                    float* __restrict__ sc)
{
    __shared__ float At[128][20];   // [q-row][kk]
    __shared__ float Bs[16][132];   // [kk][k-token]

    const int kt0 = blockIdx.x * 128, qt0 = blockIdx.y * 128, bh = blockIdx.z;
    const int b = bh >> 4, h = bh & 15;
    const int tid = threadIdx.x;
    const int tx = tid & 15, ty = tid >> 4;

    const size_t qbase  = ((size_t)b * S_ + qt0) * D_ + h * 64;
    const size_t ktbase = (size_t)bh * DK_ * S_ + kt0;

    float acc[8][8];
#pragma unroll
    for (int r = 0; r < 8; r++)
#pragma unroll
        for (int c = 0; c < 8; c++) acc[r][c] = 0.f;

    for (int d0 = 0; d0 < 64; d0 += 16) {
#pragma unroll
        for (int l = 0; l < 8; l++) {
            int i = tid + l * 256;                 // 0..2047
            int m = i >> 4, kk = i & 15;
            At[m][kk] = q[qbase + (size_t)m * D_ + d0 + kk];
            int kk2 = i >> 7, n = i & 127;
            Bs[kk2][n] = kt[ktbase + (size_t)(d0 + kk2) * S_ + n];
        }
        __syncthreads();
#pragma unroll
        for (int kc = 0; kc < 4; kc++) {
            float at[8][4];
#pragma unroll
            for (int r = 0; r < 8; r++) {
                float4 t = *(const float4*)&At[ty * 8 + r][kc * 4];
                at[r][0] = t.x; at[r][1] = t.y; at[r][2] = t.z; at[r][3] = t.w;
            }
#pragma unroll
            for (int u = 0; u < 4; u++) {
                float4 blo = *(const float4*)&Bs[kc * 4 + u][tx * 8];
                float4 bhi = *(const float4*)&Bs[kc * 4 + u][tx * 8 + 4];
#pragma unroll
                for (int r = 0; r < 8; r++) {
                    float a = at[r][u];
                    acc[r][0] += a * blo.x;  acc[r][1] += a * blo.y;
                    acc[r][2] += a * blo.z;  acc[r][3] += a * blo.w;
                    acc[r][4] += a * bhi.x;  acc[r][5] += a * bhi.y;
                    acc[r][6] += a * bhi.z;  acc[r][7] += a * bhi.w;
                }
            }
        }
        __syncthreads();
    }

    int mj[8];
#pragma unroll
    for (int c = 0; c < 8; c++) mj[c] = mask[b * S_ + kt0 + tx * 8 + c];

#pragma unroll
    for (int r = 0; r < 8; r++) {
        int qi = qt0 + ty * 8 + r;
        float o[8];
#pragma unroll
        for (int c = 0; c < 8; c++) {
            int kj = kt0 + tx * 8 + c;
            int coord = qi - kj + (S_ - 1);
            float v = acc[r][c] * 0.125f + rel[coord * H_ + h];
            o[c] = (mj[c] == 0) ? -1e9f : v;
        }
        float* dst = &sc[((size_t)bh * S_ + qi) * S_ + kt0 + tx * 8];
        *(float4*)dst       = make_float4(o[0], o[1], o[2], o[3]);
        *(float4*)(dst + 4) = make_float4(o[4], o[5], o[6], o[7]);
    }
}

// ---------------------------------------------------------------------------
// Row softmax over last dim (length S). One block per row.
// ---------------------------------------------------------------------------
__global__ __launch_bounds__(256)
void softmax_kernel(float* __restrict__ sc)
{
    __shared__ float red[256];
    const size_t base = (size_t)blockIdx.x * S_;
    const int tid = threadIdx.x;

    float v[4];
    float mx = -INFINITY;
#pragma unroll
    for (int l = 0; l < 4; l++) {
        v[l] = sc[base + tid + l * 256];
        mx = fmaxf(mx, v[l]);
    }
    red[tid] = mx; __syncthreads();
    for (int st = 128; st > 0; st >>= 1) {
        if (tid < st) red[tid] = fmaxf(red[tid], red[tid + st]);
        __syncthreads();
    }
    mx = red[0]; __syncthreads();

    float s = 0.f;
#pragma unroll
    for (int l = 0; l < 4; l++) { v[l] = __expf(v[l] - mx); s += v[l]; }
    red[tid] = s; __syncthreads();
    for (int st = 128; st > 0; st >>= 1) {
        if (tid < st) red[tid] += red[tid + st];
        __syncthreads();
    }
    float inv = 1.f / red[0];
#pragma unroll
    for (int l = 0; l < 4; l++) sc[base + tid + l * 256] = v[l] * inv;
}

// ---------------------------------------------------------------------------
// AV: ctx = attn @ v, 128x64 tile, 8x4 blocking; emits bf16 hi/lo split.
// ---------------------------------------------------------------------------
__global__ __launch_bounds__(256)
void av2_kernel(const float* __restrict__ attn, const float* __restrict__ v,
                bf16* __restrict__ ctxh, bf16* __restrict__ ctxl)
{
    __shared__ float At[128][20];   // [q-row][kk]
    __shared__ float Bs[16][68];    // [kk][d]

    const int mt = blockIdx.x, bh = blockIdx.y;
    const int b = bh >> 4, h = bh & 15;
    const int tid = threadIdx.x;
    const int tx = tid & 15, ty = tid >> 4;

    const size_t abase = ((size_t)bh * S_ + mt * 128) * S_;
    const size_t vbase = (size_t)b * S_ * D_ + h * 64;

    float acc[8][4];
#pragma unroll
    for (int r = 0; r < 8; r++)
#pragma unroll
        for (int c = 0; c < 4; c++) acc[r][c] = 0.f;

    for (int k0 = 0; k0 < S_; k0 += 16) {
#pragma unroll
        for (int l = 0; l < 8; l++) {
            int i = tid + l * 256;                 // 0..2047
            int m = i >> 4, kk = i & 15;
            At[m][kk] = attn[abase + (size_t)m * S_ + k0 + kk];
        }
#pragma unroll
        for (int l = 0; l < 4; l++) {
            int i = tid + l * 256;                 // 0..1023
            int kk = i >> 6, n = i & 63;
            Bs[kk][n] = v[vbase + (size_t)(k0 + kk) * D_ + n];
        }
        __syncthreads();
#pragma unroll
        for (int kc = 0; kc < 4; kc++) {
            float at[8][4];
#pragma unroll
            for (int r = 0; r < 8; r++) {
                float4 t = *(const float4*)&At[ty * 8 + r][kc * 4];
                at[r][0] = t.x; at[r][1] = t.y; at[r][2] = t.z; at[r][3] = t.w;
            }
#pragma unroll
            for (int u = 0; u < 4; u++) {
                float4 bv = *(const float4*)&Bs[kc * 4 + u][tx * 4];
#pragma unroll
                for (int r = 0; r < 8; r++) {
                    float a = at[r][u];
                    acc[r][0] += a * bv.x; acc[r][1] += a * bv.y;
                    acc[r][2] += a * bv.z; acc[r][3] += a * bv.w;
                }
            }
        }
        __syncthreads();
    }

#pragma unroll
    for (int r = 0; r < 8; r++) {
        int m = mt * 128 + ty * 8 + r;
        size_t oi = ((size_t)b * S_ + m) * D_ + h * 64 + tx * 4;
#pragma unroll
        for (int c = 0; c < 4; c++) {
            float vv = acc[r][c];
            bf16 hh = __float2bfloat16(vv);
            ctxh[oi + c] = hh;
            ctxl[oi + c] = __float2bfloat16(vv - __bfloat162float(hh));
        }
    }
}

// ---------------------------------------------------------------------------
// out = LayerNorm(x + y) * g + b; optionally also emit bf16 hi/lo split
// ---------------------------------------------------------------------------
__global__ __launch_bounds__(256)
void add_ln_kernel(const float* __restrict__ x, const float* __restrict__ y,
                   const float* __restrict__ g, const float* __restrict__ b,
                   float* __restrict__ out, bf16* __restrict__ oh,
                   bf16* __restrict__ ol)
{
    __shared__ float red[256];
    const size_t base = (size_t)blockIdx.x * D_;
    const int tid = threadIdx.x;

    float v[4];
    float s = 0.f;
#pragma unroll
    for (int l = 0; l < 4; l++) {
        int i = tid + l * 256;
        v[l] = x[base + i] + y[base + i];
        s += v[l];
    }
    red[tid] = s; __syncthreads();
    for (int st = 128; st > 0; st >>= 1) {
        if (tid < st) red[tid] += red[tid + st];
        __syncthreads();
    }
    float mean = red[0] * (1.0f / D_); __syncthreads();

    float sq = 0.f;
#pragma unroll
    for (int l = 0; l < 4; l++) { float d = v[l] - mean; sq += d * d; }
    red[tid] = sq; __syncthreads();
    for (int st = 128; st > 0; st >>= 1) {
        if (tid < st) red[tid] += red[tid + st];
        __syncthreads();
    }
    float rstd = rsqrtf(red[0] * (1.0f / D_) + 1e-5f);

#pragma unroll
    for (int l = 0; l < 4; l++) {
        int i = tid + l * 256;
        float o = (v[l] - mean) * rstd * g[i] + b[i];
        out[base + i] = o;
        if (oh) {
            bf16 hh = __float2bfloat16(o);
            oh[base + i] = hh;
            ol[base + i] = __float2bfloat16(o - __bfloat162float(hh));
        }
    }
}

// ---------------------------------------------------------------------------
// Launch
// ---------------------------------------------------------------------------
extern "C" void kernel_launch(void* const* d_in, const int* in_sizes, int n_in,
                              void* d_out, int out_size)
{
    const float* x    = (const float*)d_in[0];
    const float* wq   = (const float*)d_in[1];
    const float* bq   = (const float*)d_in[2];
    const float* wk   = (const float*)d_in[3];
    const float* bk   = (const float*)d_in[4];
    const float* wv   = (const float*)d_in[5];
    const float* bv   = (const float*)d_in[6];
    const float* wo   = (const float*)d_in[7];
    const float* bo   = (const float*)d_in[8];
    const float* rel  = (const float*)d_in[9];
    const float* ln1g = (const float*)d_in[10];
    const float* ln1b = (const float*)d_in[11];
    const float* w1   = (const float*)d_in[12];
    const float* b1   = (const float*)d_in[13];
    const float* w2   = (const float*)d_in[14];
    const float* b2   = (const float*)d_in[15];
    const float* ln2g = (const float*)d_in[16];
    const float* ln2b = (const float*)d_in[17];
    const int*   mask = (const int*)  d_in[18];
    float* out = (float*)d_out;

    float *pq, *pk, *pv, *pkt, *psc, *pt1, *px1;
    bf16 *pxh, *pxl, *pctxh, *pctxl, *px1h, *px1l, *pffh, *pffl;
    bf16 *wqTh, *wqTl, *wkTh, *wkTl, *wvTh, *wvTl, *woTh, *woTl;
    bf16 *w1Th, *w1Tl, *w2Th, *w2Tl;
    cudaGetSymbolAddress((void**)&pq,   g_q);
    cudaGetSymbolAddress((void**)&pk,   g_k);
    cudaGetSymbolAddress((void**)&pv,   g_v);
    cudaGetSymbolAddress((void**)&pkt,  g_kt);
    cudaGetSymbolAddress((void**)&psc,  g_sc);
    cudaGetSymbolAddress((void**)&pt1,  g_t1);
    cudaGetSymbolAddress((void**)&px1,  g_x1);
    cudaGetSymbolAddress((void**)&pxh,  g_xh);
    cudaGetSymbolAddress((void**)&pxl,  g_xl);
    cudaGetSymbolAddress((void**)&pctxh, g_ctxh);
    cudaGetSymbolAddress((void**)&pctxl, g_ctxl);
    cudaGetSymbolAddress((void**)&px1h, g_x1h);
    cudaGetSymbolAddress((void**)&px1l, g_x1l);
    cudaGetSymbolAddress((void**)&pffh, g_ffh);
    cudaGetSymbolAddress((void**)&pffl, g_ffl);
    cudaGetSymbolAddress((void**)&wqTh, g_wqTh);
    cudaGetSymbolAddress((void**)&wqTl, g_wqTl);
    cudaGetSymbolAddress((void**)&wkTh, g_wkTh);
    cudaGetSymbolAddress((void**)&wkTl, g_wkTl);
    cudaGetSymbolAddress((void**)&wvTh, g_wvTh);
    cudaGetSymbolAddress((void**)&wvTl, g_wvTl);
    cudaGetSymbolAddress((void**)&woTh, g_woTh);
    cudaGetSymbolAddress((void**)&woTl, g_woTl);
    cudaGetSymbolAddress((void**)&w1Th, g_w1Th);
    cudaGetSymbolAddress((void**)&w1Tl, g_w1Tl);
    cudaGetSymbolAddress((void**)&w2Th, g_w2Th);
    cudaGetSymbolAddress((void**)&w2Tl, g_w2Tl);

    static int attr_done = 0;
    if (!attr_done) {
        cudaFuncSetAttribute(gemm_tc_kernel,
                             cudaFuncAttributeMaxDynamicSharedMemorySize, GEMM_SMEM);
        attr_done = 1;
    }

    dim3 blk(256);

    // input split + weight transpose/split
    split_kernel<<<(NR_ * D_ / 4 + 255) / 256, blk>>>(x, pxh, pxl, (size_t)NR_ * D_ / 4);
    tsplit_kernel<<<dim3(D_ / 32, D_ / 32), blk>>>(wq, wqTh, wqTl, D_, D_);
    tsplit_kernel<<<dim3(D_ / 32, D_ / 32), blk>>>(wk, wkTh, wkTl, D_, D_);
    tsplit_kernel<<<dim3(D_ / 32, D_ / 32), blk>>>(wv, wvTh, wvTl, D_, D_);
    tsplit_kernel<<<dim3(D_ / 32, D_ / 32), blk>>>(wo, woTh, woTl, D_, D_);
    tsplit_kernel<<<dim3(DFF_ / 32, D_ / 32), blk>>>(w1, w1Th, w1Tl, D_, DFF_);
    tsplit_kernel<<<dim3(D_ / 32, DFF_ / 32), blk>>>(w2, w2Th, w2Tl, DFF_, D_);

    // QKV projections (tensor cores, mma.sync)
    dim3 gProj(D_ / 128, NR_ / 128);
    gemm_tc_kernel<<<gProj, blk, GEMM_SMEM>>>(pxh, pxl, wqTh, wqTl, bq, pq,
                                              nullptr, nullptr, NR_, D_, D_, 0);
    gemm_tc_kernel<<<gProj, blk, GEMM_SMEM>>>(pxh, pxl, wkTh, wkTl, bk, pk,
                                              nullptr, nullptr, NR_, D_, D_, 0);
    gemm_tc_kernel<<<gProj, blk, GEMM_SMEM>>>(pxh, pxl, wvTh, wvTl, bv, pv,
                                              nullptr, nullptr, NR_, D_, D_, 0);

    // K transpose per head, scores, softmax, AV
    ktrans_kernel<<<dim3(S_ / 32, D_ / 32, B_), blk>>>(pk, pkt);
    scores2_kernel<<<dim3(S_ / 128, S_ / 128, BH_), blk>>>(pq, pkt, rel, mask, psc);
    softmax_kernel<<<BH_ * S_, blk>>>(psc);
    av2_kernel<<<dim3(S_ / 128, BH_), blk>>>(psc, pv, pctxh, pctxl);

    // O projection
    gemm_tc_kernel<<<gProj, blk, GEMM_SMEM>>>(pctxh, pctxl, woTh, woTl, bo, pt1,
                                              nullptr, nullptr, NR_, D_, D_, 0);

    // x1 = LN(x + attn_out), with split
    add_ln_kernel<<<NR_, blk>>>(x, pt1, ln1g, ln1b, px1, px1h, px1l);

    // FFN
    dim3 gF1(DFF_ / 128, NR_ / 128);
    gemm_tc_kernel<<<gF1, blk, GEMM_SMEM>>>(px1h, px1l, w1Th, w1Tl, b1, nullptr,
                                            pffh, pffl, NR_, DFF_, D_, 1);
    dim3 gF2(D_ / 128, NR_ / 128);
    gemm_tc_kernel<<<gF2, blk, GEMM_SMEM>>>(pffh, pffl, w2Th, w2Tl, b2, pt1,
                                            nullptr, nullptr, NR_, D_, DFF_, 0);

    // out = LN(x1 + ff)
    add_ln_kernel<<<NR_, blk>>>(px1, pt1, ln2g, ln2b, out, nullptr, nullptr);
}

// round 5
// speedup vs baseline: 2.7407x; 1.3183x over previous
#include <cuda_runtime.h>
#include <cuda_bf16.h>
#include <math.h>
#include <stdint.h>

// Problem constants
#define B_   4
#define S_   1024
#define D_   1024
#define H_   16
#define DK_  64
#define DFF_ 4096
#define NR_  4096          // B*S rows
#define BH_  64            // B*H

typedef __nv_bfloat16 bf16;

// ---------------------------------------------------------------------------
// Scratch (device globals; .bss — no allocations)
// ---------------------------------------------------------------------------
__device__ float g_t1 [(size_t)NR_ * D_];
__device__ float g_x1 [(size_t)NR_ * D_];

// bf16 hi/lo split buffers
__device__ bf16 g_xh  [(size_t)NR_ * D_];
__device__ bf16 g_xl  [(size_t)NR_ * D_];
__device__ bf16 g_qh  [(size_t)NR_ * D_];
__device__ bf16 g_ql  [(size_t)NR_ * D_];
__device__ bf16 g_kh  [(size_t)NR_ * D_];
__device__ bf16 g_kl  [(size_t)NR_ * D_];
__device__ bf16 g_vh  [(size_t)NR_ * D_];
__device__ bf16 g_vl  [(size_t)NR_ * D_];
__device__ bf16 g_ctxh[(size_t)NR_ * D_];
__device__ bf16 g_ctxl[(size_t)NR_ * D_];
__device__ bf16 g_x1h [(size_t)NR_ * D_];
__device__ bf16 g_x1l [(size_t)NR_ * D_];
__device__ bf16 g_ffh [(size_t)NR_ * DFF_];
__device__ bf16 g_ffl [(size_t)NR_ * DFF_];
// transposed+split weights: [N,K] bf16
__device__ bf16 g_wqTh[(size_t)D_ * D_];
__device__ bf16 g_wqTl[(size_t)D_ * D_];
__device__ bf16 g_wkTh[(size_t)D_ * D_];
__device__ bf16 g_wkTl[(size_t)D_ * D_];
__device__ bf16 g_wvTh[(size_t)D_ * D_];
__device__ bf16 g_wvTl[(size_t)D_ * D_];
__device__ bf16 g_woTh[(size_t)D_ * D_];
__device__ bf16 g_woTl[(size_t)D_ * D_];
__device__ bf16 g_w1Th[(size_t)DFF_ * D_];
__device__ bf16 g_w1Tl[(size_t)DFF_ * D_];
__device__ bf16 g_w2Th[(size_t)D_ * DFF_];
__device__ bf16 g_w2Tl[(size_t)D_ * DFF_];

// ---------------------------------------------------------------------------
// Warp-MMA primitives (ldmatrix + mma.sync, portable to plain compute_103)
// ---------------------------------------------------------------------------
__device__ __forceinline__ uint32_t smem_to_u32(const void* p) {
    uint32_t a;
    asm("{ .reg .u64 t; cvta.to.shared.u64 t, %1; cvt.u32.u64 %0, t; }"
        : "=r"(a) : "l"(p));
    return a;
}

__device__ __forceinline__ void ldmx4(uint32_t* r, uint32_t addr) {
    asm volatile("ldmatrix.sync.aligned.m8n8.x4.shared.b16 {%0,%1,%2,%3}, [%4];"
                 : "=r"(r[0]), "=r"(r[1]), "=r"(r[2]), "=r"(r[3]) : "r"(addr));
}

__device__ __forceinline__ void ldmx4t(uint32_t* r, uint32_t addr) {
    asm volatile("ldmatrix.sync.aligned.m8n8.x4.trans.shared.b16 {%0,%1,%2,%3}, [%4];"
                 : "=r"(r[0]), "=r"(r[1]), "=r"(r[2]), "=r"(r[3]) : "r"(addr));
}

__device__ __forceinline__ void mma_bf16(float* c, const uint32_t* a,
                                         const uint32_t* b) {
    asm volatile(
        "mma.sync.aligned.m16n8k16.row.col.f32.bf16.bf16.f32 "
        "{%0,%1,%2,%3}, {%4,%5,%6,%7}, {%8,%9}, {%0,%1,%2,%3};"
        : "+f"(c[0]), "+f"(c[1]), "+f"(c[2]), "+f"(c[3])
        : "r"(a[0]), "r"(a[1]), "r"(a[2]), "r"(a[3]), "r"(b[0]), "r"(b[1]));
}

__device__ __forceinline__ uint32_t packbf(float lo, float hi) {
    uint32_t r;
    asm("cvt.rn.bf16x2.f32 %0, %1, %2;" : "=r"(r) : "f"(hi), "f"(lo));
    return r;
}
__device__ __forceinline__ float bfres(float x) {
    return x - __bfloat162float(__float2bfloat16(x));
}

// ---------------------------------------------------------------------------
// Tensor-core GEMM (mma.sync): C[M,N] = A[M,K] @ B^T + bias, 3-term bf16 split
// ---------------------------------------------------------------------------
#define GT_ROWB   144
#define GT_TILE   (128 * GT_ROWB)
#define GEMM_SMEM (4 * GT_TILE)

__global__ __launch_bounds__(256)
void gemm_tc_kernel(const bf16* __restrict__ Ahi, const bf16* __restrict__ Alo,
                    const bf16* __restrict__ Bhi, const bf16* __restrict__ Blo,
                    const float* __restrict__ bias,
                    float* __restrict__ Cf,
                    bf16* __restrict__ Chi, bf16* __restrict__ Clo,
                    int M, int N, int K, int relu)
{
    extern __shared__ char smem[];
    const uint32_t sbase = smem_to_u32(smem);

    const int tid  = threadIdx.x;
    const int wid  = tid >> 5;
    const int lane = tid & 31;
    const int warpM = wid >> 2;
    const int warpN = wid & 3;
    const int m0 = blockIdx.y * 128;
    const int n0 = blockIdx.x * 128;

    const bf16* srcs[4] = { Ahi + (size_t)m0 * K, Alo + (size_t)m0 * K,
                            Bhi + (size_t)n0 * K, Blo + (size_t)n0 * K };

    float acc[4][4][4];
#pragma unroll
    for (int i = 0; i < 4; i++)
#pragma unroll
        for (int j = 0; j < 4; j++)
#pragma unroll
            for (int r = 0; r < 4; r++) acc[i][j][r] = 0.f;

    const uint32_t aoff = (uint32_t)(lane & 15) * GT_ROWB + (uint32_t)(lane >> 4) * 16;
    const uint32_t boff = (uint32_t)(((lane >> 4) * 8) + (lane & 7)) * GT_ROWB
                        + (uint32_t)((lane >> 3) & 1) * 16;
    const uint32_t aBaseHi = sbase + 0 * GT_TILE + (uint32_t)warpM * 64 * GT_ROWB + aoff;
    const uint32_t aBaseLo = sbase + 1 * GT_TILE + (uint32_t)warpM * 64 * GT_ROWB + aoff;
    const uint32_t bBaseHi = sbase + 2 * GT_TILE + (uint32_t)warpN * 32 * GT_ROWB + boff;
    const uint32_t bBaseLo = sbase + 3 * GT_TILE + (uint32_t)warpN * 32 * GT_ROWB + boff;

    for (int k0 = 0; k0 < K; k0 += 64) {
        __syncthreads();
#pragma unroll
        for (int l = 0; l < 16; l++) {
            int i = tid + l * 256;
            int t = i >> 10, j = i & 1023;
            int row = j >> 3, kc = j & 7;
            *(float4*)(smem + t * GT_TILE + row * GT_ROWB + kc * 16) =
                *(const float4*)(srcs[t] + (size_t)row * K + k0 + kc * 8);
        }
        __syncthreads();

#pragma unroll
        for (int ks = 0; ks < 4; ks++) {
            uint32_t af[4][4], bh_[4][2], bl_[4][2];
#pragma unroll
            for (int fm = 0; fm < 4; fm++)
                ldmx4(af[fm], aBaseHi + (uint32_t)fm * 16 * GT_ROWB + ks * 32);
#pragma unroll
            for (int g = 0; g < 2; g++) {
                uint32_t r[4];
                ldmx4(r, bBaseHi + (uint32_t)g * 16 * GT_ROWB + ks * 32);
                bh_[g * 2][0] = r[0]; bh_[g * 2][1] = r[1];
                bh_[g * 2 + 1][0] = r[2]; bh_[g * 2 + 1][1] = r[3];
            }
#pragma unroll
            for (int fm = 0; fm < 4; fm++)
#pragma unroll
                for (int fn = 0; fn < 4; fn++)
                    mma_bf16(acc[fm][fn], af[fm], bh_[fn]);
#pragma unroll
            for (int g = 0; g < 2; g++) {
                uint32_t r[4];
                ldmx4(r, bBaseLo + (uint32_t)g * 16 * GT_ROWB + ks * 32);
                bl_[g * 2][0] = r[0]; bl_[g * 2][1] = r[1];
                bl_[g * 2 + 1][0] = r[2]; bl_[g * 2 + 1][1] = r[3];
            }
#pragma unroll
            for (int fm = 0; fm < 4; fm++)
#pragma unroll
                for (int fn = 0; fn < 4; fn++)
                    mma_bf16(acc[fm][fn], af[fm], bl_[fn]);
#pragma unroll
            for (int fm = 0; fm < 4; fm++)
                ldmx4(af[fm], aBaseLo + (uint32_t)fm * 16 * GT_ROWB + ks * 32);
#pragma unroll
            for (int fm = 0; fm < 4; fm++)
#pragma unroll
                for (int fn = 0; fn < 4; fn++)
                    mma_bf16(acc[fm][fn], af[fm], bh_[fn]);
        }
    }

    const int qr = lane >> 2;
    const int qc = (lane & 3) * 2;
#pragma unroll
    for (int fm = 0; fm < 4; fm++) {
#pragma unroll
        for (int fn = 0; fn < 4; fn++) {
            float* a = acc[fm][fn];
            int row = m0 + warpM * 64 + fm * 16 + qr;
            int col = n0 + warpN * 32 + fn * 8 + qc;
            float b0 = bias[col], b1 = bias[col + 1];
            float v00 = a[0] + b0, v01 = a[1] + b1;
            float v10 = a[2] + b0, v11 = a[3] + b1;
            if (relu) {
                v00 = fmaxf(v00, 0.f); v01 = fmaxf(v01, 0.f);
                v10 = fmaxf(v10, 0.f); v11 = fmaxf(v11, 0.f);
            }
            size_t i0 = (size_t)row * N + col;
            size_t i1 = (size_t)(row + 8) * N + col;
            if (Cf) {
                *(float2*)&Cf[i0] = make_float2(v00, v01);
                *(float2*)&Cf[i1] = make_float2(v10, v11);
            }
            if (Chi) {
                bf16 h00 = __float2bfloat16(v00), h01 = __float2bfloat16(v01);
                bf16 h10 = __float2bfloat16(v10), h11 = __float2bfloat16(v11);
                *(__nv_bfloat162*)&Chi[i0] = __nv_bfloat162(h00, h01);
                *(__nv_bfloat162*)&Chi[i1] = __nv_bfloat162(h10, h11);
                *(__nv_bfloat162*)&Clo[i0] = __nv_bfloat162(
                    __float2bfloat16(v00 - __bfloat162float(h00)),
                    __float2bfloat16(v01 - __bfloat162float(h01)));
                *(__nv_bfloat162*)&Clo[i1] = __nv_bfloat162(
                    __float2bfloat16(v10 - __bfloat162float(h10)),
                    __float2bfloat16(v11 - __bfloat162float(h11)));
            }
        }
    }
}

// ---------------------------------------------------------------------------
// Fused flash attention: per CTA = (128-row q-tile, one head)
//   S = Q.K^T/8 + rel-bias (+mask), online softmax, O = P.V   (all in-kernel)
// 8 warps; warp w owns rows w*16..w*16+15. bf16 3-term splits on both MMAs.
// ---------------------------------------------------------------------------
#define FROWB 144
#define FTILE (128 * FROWB)                    // 18432 B
#define FLASH_SMEM (6 * FTILE + 8192 + 512)    // 119296 B

__global__ __launch_bounds__(256)
void flash_attn_kernel(const bf16* __restrict__ qh, const bf16* __restrict__ ql,
                       const bf16* __restrict__ kh, const bf16* __restrict__ kl,
                       const bf16* __restrict__ vh, const bf16* __restrict__ vl,
                       const float* __restrict__ rel, const int* __restrict__ mask,
                       bf16* __restrict__ ctxh, bf16* __restrict__ ctxl)
{
    extern __shared__ char smem[];
    const int qt = blockIdx.x;
    const int bhid = blockIdx.y;
    const int b = bhid >> 4, h = bhid & 15;
    const int tid = threadIdx.x, wid = tid >> 5, lane = tid & 31;
    const int qr = lane >> 2, qc = (lane & 3) * 2;

    const uint32_t ub = smem_to_u32(smem);
    float* s_rel = (float*)(smem + 6 * FTILE);
    int*   s_msk = (int*)(smem + 6 * FTILE + 8192);

    // Q tiles (hi/lo), loaded once
    const size_t qg = ((size_t)b * S_ + qt * 128) * D_ + h * 64;
#pragma unroll
    for (int l = 0; l < 8; l++) {
        int i = tid + l * 256;
        int t = i >> 10, j = i & 1023;
        int row = j >> 3, kc = j & 7;
        const bf16* src = t ? ql : qh;
        *(float4*)(smem + t * FTILE + row * FROWB + kc * 16) =
            *(const float4*)(src + qg + (size_t)row * D_ + kc * 8);
    }
    // rel-bias column for this head
    for (int i = tid; i < 2047; i += 256) s_rel[i] = rel[i * H_ + h];

    float acc_o[8][4];
#pragma unroll
    for (int a = 0; a < 8; a++) {
        acc_o[a][0] = acc_o[a][1] = acc_o[a][2] = acc_o[a][3] = 0.f;
    }
    float mrow[2] = {-1e30f, -1e30f}, lrow[2] = {0.f, 0.f};

    const uint32_t aoff = (uint32_t)(lane & 15) * FROWB + (uint32_t)(lane >> 4) * 16;
    const uint32_t boff = (uint32_t)(((lane >> 4) * 8) + (lane & 7)) * FROWB
                        + (uint32_t)((lane >> 3) & 1) * 16;
    const uint32_t uQh = ub + 0 * FTILE + (uint32_t)wid * 16 * FROWB + aoff;
    const uint32_t uQl = ub + 1 * FTILE + (uint32_t)wid * 16 * FROWB + aoff;
    const uint32_t uKh = ub + 2 * FTILE + boff;
    const uint32_t uKl = ub + 3 * FTILE + boff;
    const uint32_t vto = (uint32_t)(lane & 15) * FROWB + (uint32_t)(lane >> 4) * 16;
    const uint32_t uVh = ub + 4 * FTILE + vto;
    const uint32_t uVl = ub + 5 * FTILE + vto;

    for (int kt = 0; kt < 8; kt++) {
        __syncthreads();
        const size_t kg = ((size_t)b * S_ + kt * 128) * D_ + h * 64;
#pragma unroll
        for (int l = 0; l < 16; l++) {
            int i = tid + l * 256;
            int t = i >> 10, j = i & 1023;
            int row = j >> 3, kc = j & 7;
            const bf16* src = (t == 0) ? kh : (t == 1) ? kl : (t == 2) ? vh : vl;
            *(float4*)(smem + (2 + t) * FTILE + row * FROWB + kc * 16) =
                *(const float4*)(src + kg + (size_t)row * D_ + kc * 8);
        }
        if (tid < 128) s_msk[tid] = mask[b * S_ + kt * 128 + tid];
        __syncthreads();

        // ---- S = Q.K^T (3-term bf16) ----
        float accs[16][4];
#pragma unroll
        for (int f = 0; f < 16; f++) {
            accs[f][0] = accs[f][1] = accs[f][2] = accs[f][3] = 0.f;
        }
#pragma unroll
        for (int ks = 0; ks < 4; ks++) {
            uint32_t aqh[4], aql4[4];
            ldmx4(aqh,  uQh + ks * 32);
            ldmx4(aql4, uQl + ks * 32);
#pragma unroll
            for (int g = 0; g < 8; g++) {
                uint32_t rkh[4], rkl[4];
                ldmx4(rkh, uKh + (uint32_t)g * 16 * FROWB + ks * 32);
                ldmx4(rkl, uKl + (uint32_t)g * 16 * FROWB + ks * 32);
                mma_bf16(accs[2 * g],     aqh,  rkh);
                mma_bf16(accs[2 * g + 1], aqh,  rkh + 2);
                mma_bf16(accs[2 * g],     aqh,  rkl);
                mma_bf16(accs[2 * g + 1], aqh,  rkl + 2);
                mma_bf16(accs[2 * g],     aql4, rkh);
                mma_bf16(accs[2 * g + 1], aql4, rkh + 2);
            }
        }

        // ---- bias + mask + online softmax ----
        const int rb0 = qt * 128 + wid * 16 + qr - kt * 128 + 1023;
        float rmax[2] = {-1e30f, -1e30f};
#pragma unroll
        for (int f = 0; f < 16; f++) {
            int c0 = f * 8 + qc;
            float s0 = accs[f][0] * 0.125f + s_rel[rb0 - c0];
            float s1 = accs[f][1] * 0.125f + s_rel[rb0 - c0 - 1];
            float s2 = accs[f][2] * 0.125f + s_rel[rb0 + 8 - c0];
            float s3 = accs[f][3] * 0.125f + s_rel[rb0 + 8 - c0 - 1];
            if (s_msk[c0] == 0)     { s0 = -1e9f; s2 = -1e9f; }
            if (s_msk[c0 + 1] == 0) { s1 = -1e9f; s3 = -1e9f; }
            accs[f][0] = s0; accs[f][1] = s1; accs[f][2] = s2; accs[f][3] = s3;
            rmax[0] = fmaxf(rmax[0], fmaxf(s0, s1));
            rmax[1] = fmaxf(rmax[1], fmaxf(s2, s3));
        }
#pragma unroll
        for (int r = 0; r < 2; r++) {
            rmax[r] = fmaxf(rmax[r], __shfl_xor_sync(0xffffffff, rmax[r], 1));
            rmax[r] = fmaxf(rmax[r], __shfl_xor_sync(0xffffffff, rmax[r], 2));
        }
        float alpha[2];
#pragma unroll
        for (int r = 0; r < 2; r++) {
            float mn = fmaxf(mrow[r], rmax[r]);
            alpha[r] = __expf(mrow[r] - mn);
            mrow[r] = mn;
        }
        float rsum[2] = {0.f, 0.f};
#pragma unroll
        for (int f = 0; f < 16; f++) {
            float p0 = __expf(accs[f][0] - mrow[0]);
            float p1 = __expf(accs[f][1] - mrow[0]);
            float p2 = __expf(accs[f][2] - mrow[1]);
            float p3 = __expf(accs[f][3] - mrow[1]);
            accs[f][0] = p0; accs[f][1] = p1; accs[f][2] = p2; accs[f][3] = p3;
            rsum[0] += p0 + p1;
            rsum[1] += p2 + p3;
        }
#pragma unroll
        for (int r = 0; r < 2; r++) {
            rsum[r] += __shfl_xor_sync(0xffffffff, rsum[r], 1);
            rsum[r] += __shfl_xor_sync(0xffffffff, rsum[r], 2);
            lrow[r] = lrow[r] * alpha[r] + rsum[r];
        }
#pragma unroll
        for (int a = 0; a < 8; a++) {
            acc_o[a][0] *= alpha[0]; acc_o[a][1] *= alpha[0];
            acc_o[a][2] *= alpha[1]; acc_o[a][3] *= alpha[1];
        }

        // ---- O += P.V (3-term: Ph*Vh + Ph*Vl + Pl*Vh) ----
#pragma unroll
        for (int kc = 0; kc < 8; kc++) {
            const int f0 = 2 * kc, f1 = 2 * kc + 1;
            uint32_t aPh[4], aPl[4];
            aPh[0] = packbf(accs[f0][0], accs[f0][1]);
            aPh[1] = packbf(accs[f0][2], accs[f0][3]);
            aPh[2] = packbf(accs[f1][0], accs[f1][1]);
            aPh[3] = packbf(accs[f1][2], accs[f1][3]);
            aPl[0] = packbf(bfres(accs[f0][0]), bfres(accs[f0][1]));
            aPl[1] = packbf(bfres(accs[f0][2]), bfres(accs[f0][3]));
            aPl[2] = packbf(bfres(accs[f1][0]), bfres(accs[f1][1]));
            aPl[3] = packbf(bfres(accs[f1][2]), bfres(accs[f1][3]));
#pragma unroll
            for (int jg = 0; jg < 4; jg++) {
                uint32_t v4h[4], v4l[4];
                uint32_t off = (uint32_t)(kc * 16) * FROWB + jg * 32;
                ldmx4t(v4h, uVh + off);
                ldmx4t(v4l, uVl + off);
                mma_bf16(acc_o[2 * jg],     aPh, v4h);
                mma_bf16(acc_o[2 * jg + 1], aPh, v4h + 2);
                mma_bf16(acc_o[2 * jg],     aPh, v4l);
                mma_bf16(acc_o[2 * jg + 1], aPh, v4l + 2);
                mma_bf16(acc_o[2 * jg],     aPl, v4h);
                mma_bf16(acc_o[2 * jg + 1], aPl, v4h + 2);
            }
        }
    }

    // ---- epilogue: normalize, split to bf16 hi/lo, write ctx ----
    const float inv0 = 1.f / lrow[0], inv1 = 1.f / lrow[1];
    const int row0 = qt * 128 + wid * 16 + qr;
#pragma unroll
    for (int a = 0; a < 8; a++) {
        int col = a * 8 + qc;
        size_t i0 = ((size_t)b * S_ + row0) * D_ + h * 64 + col;
        size_t i1 = ((size_t)b * S_ + row0 + 8) * D_ + h * 64 + col;
        float v00 = acc_o[a][0] * inv0, v01 = acc_o[a][1] * inv0;
        float v10 = acc_o[a][2] * inv1, v11 = acc_o[a][3] * inv1;
        bf16 h00 = __float2bfloat16(v00), h01 = __float2bfloat16(v01);
        bf16 h10 = __float2bfloat16(v10), h11 = __float2bfloat16(v11);
        *(__nv_bfloat162*)&ctxh[i0] = __nv_bfloat162(h00, h01);
        *(__nv_bfloat162*)&ctxh[i1] = __nv_bfloat162(h10, h11);
        *(__nv_bfloat162*)&ctxl[i0] = __nv_bfloat162(
            __float2bfloat16(v00 - __bfloat162float(h00)),
            __float2bfloat16(v01 - __bfloat162float(h01)));
        *(__nv_bfloat162*)&ctxl[i1] = __nv_bfloat162(
            __float2bfloat16(v10 - __bfloat162float(h10)),
            __float2bfloat16(v11 - __bfloat162float(h11)));
    }
}

// ---------------------------------------------------------------------------
// fp32 -> bf16 hi/lo split (elementwise, vectorized)
// ---------------------------------------------------------------------------
__global__ __launch_bounds__(256)
void split_kernel(const float* __restrict__ X, bf16* __restrict__ Xh,
                  bf16* __restrict__ Xl, size_t n4)
{
    size_t i = (size_t)blockIdx.x * 256 + threadIdx.x;
    if (i >= n4) return;
    float4 v = ((const float4*)X)[i];
    bf16 h0 = __float2bfloat16(v.x), h1 = __float2bfloat16(v.y);
    bf16 h2 = __float2bfloat16(v.z), h3 = __float2bfloat16(v.w);
    size_t o = i * 4;
    Xh[o] = h0; Xh[o+1] = h1; Xh[o+2] = h2; Xh[o+3] = h3;
    Xl[o]   = __float2bfloat16(v.x - __bfloat162float(h0));
    Xl[o+1] = __float2bfloat16(v.y - __bfloat162float(h1));
    Xl[o+2] = __float2bfloat16(v.z - __bfloat162float(h2));
    Xl[o+3] = __float2bfloat16(v.w - __bfloat162float(h3));
}

// ---------------------------------------------------------------------------
// W[K,N] fp32 -> transposed hi/lo bf16 [N,K]
// ---------------------------------------------------------------------------
__global__ __launch_bounds__(256)
void tsplit_kernel(const float* __restrict__ W, bf16* __restrict__ Th,
                   bf16* __restrict__ Tl, int K, int N)
{
    __shared__ float t[32][33];
    const int k0 = blockIdx.y * 32, n0 = blockIdx.x * 32;
    const int tx = threadIdx.x & 31, ty = threadIdx.x >> 5;
    for (int r = ty; r < 32; r += 8)
        t[r][tx] = W[(size_t)(k0 + r) * N + n0 + tx];
    __syncthreads();
    for (int r = ty; r < 32; r += 8) {
        float v = t[tx][r];
        bf16 h = __float2bfloat16(v);
        size_t oi = (size_t)(n0 + r) * K + k0 + tx;
        Th[oi] = h;
        Tl[oi] = __float2bfloat16(v - __bfloat162float(h));
    }
}

// ---------------------------------------------------------------------------
// out = LayerNorm(x + y) * g + b; optionally also emit bf16 hi/lo split
// ---------------------------------------------------------------------------
__global__ __launch_bounds__(256)
void add_ln_kernel(const float* __restrict__ x, const float* __restrict__ y,
                   const float* __restrict__ g, const float* __restrict__ b,
                   float* __restrict__ out, bf16* __restrict__ oh,
                   bf16* __restrict__ ol)
{
    __shared__ float red[256];
    const size_t base = (size_t)blockIdx.x * D_;
    const int tid = threadIdx.x;

    float v[4];
    float s = 0.f;
#pragma unroll
    for (int l = 0; l < 4; l++) {
        int i = tid + l * 256;
        v[l] = x[base + i] + y[base + i];
        s += v[l];
    }
    red[tid] = s; __syncthreads();
    for (int st = 128; st > 0; st >>= 1) {
        if (tid < st) red[tid] += red[tid + st];
        __syncthreads();
    }
    float mean = red[0] * (1.0f / D_); __syncthreads();

    float sq = 0.f;
#pragma unroll
    for (int l = 0; l < 4; l++) { float d = v[l] - mean; sq += d * d; }
    red[tid] = sq; __syncthreads();
    for (int st = 128; st > 0; st >>= 1) {
        if (tid < st) red[tid] += red[tid + st];
        __syncthreads();
    }
    float rstd = rsqrtf(red[0] * (1.0f / D_) + 1e-5f);

#pragma unroll
    for (int l = 0; l < 4; l++) {
        int i = tid + l * 256;
        float o = (v[l] - mean) * rstd * g[i] + b[i];
        out[base + i] = o;
        if (oh) {
            bf16 hh = __float2bfloat16(o);
            oh[base + i] = hh;
            ol[base + i] = __float2bfloat16(o - __bfloat162float(hh));
        }
    }
}

// ---------------------------------------------------------------------------
// Launch
// ---------------------------------------------------------------------------
extern "C" void kernel_launch(void* const* d_in, const int* in_sizes, int n_in,
                              void* d_out, int out_size)
{
    const float* x    = (const float*)d_in[0];
    const float* wq   = (const float*)d_in[1];
    const float* bq   = (const float*)d_in[2];
    const float* wk   = (const float*)d_in[3];
    const float* bk   = (const float*)d_in[4];
    const float* wv   = (const float*)d_in[5];
    const float* bv   = (const float*)d_in[6];
    const float* wo   = (const float*)d_in[7];
    const float* bo   = (const float*)d_in[8];
    const float* rel  = (const float*)d_in[9];
    const float* ln1g = (const float*)d_in[10];
    const float* ln1b = (const float*)d_in[11];
    const float* w1   = (const float*)d_in[12];
    const float* b1   = (const float*)d_in[13];
    const float* w2   = (const float*)d_in[14];
    const float* b2   = (const float*)d_in[15];
    const float* ln2g = (const float*)d_in[16];
    const float* ln2b = (const float*)d_in[17];
    const int*   mask = (const int*)  d_in[18];
    float* out = (float*)d_out;

    float *pt1, *px1;
    bf16 *pxh, *pxl, *pqh, *pql, *pkh, *pkl, *pvh, *pvl;
    bf16 *pctxh, *pctxl, *px1h, *px1l, *pffh, *pffl;
    bf16 *wqTh, *wqTl, *wkTh, *wkTl, *wvTh, *wvTl, *woTh, *woTl;
    bf16 *w1Th, *w1Tl, *w2Th, *w2Tl;
    cudaGetSymbolAddress((void**)&pt1,  g_t1);
    cudaGetSymbolAddress((void**)&px1,  g_x1);
    cudaGetSymbolAddress((void**)&pxh,  g_xh);
    cudaGetSymbolAddress((void**)&pxl,  g_xl);
    cudaGetSymbolAddress((void**)&pqh,  g_qh);
    cudaGetSymbolAddress((void**)&pql,  g_ql);
    cudaGetSymbolAddress((void**)&pkh,  g_kh);
    cudaGetSymbolAddress((void**)&pkl,  g_kl);
    cudaGetSymbolAddress((void**)&pvh,  g_vh);
    cudaGetSymbolAddress((void**)&pvl,  g_vl);
    cudaGetSymbolAddress((void**)&pctxh, g_ctxh);
    cudaGetSymbolAddress((void**)&pctxl, g_ctxl);
    cudaGetSymbolAddress((void**)&px1h, g_x1h);
    cudaGetSymbolAddress((void**)&px1l, g_x1l);
    cudaGetSymbolAddress((void**)&pffh, g_ffh);
    cudaGetSymbolAddress((void**)&pffl, g_ffl);
    cudaGetSymbolAddress((void**)&wqTh, g_wqTh);
    cudaGetSymbolAddress((void**)&wqTl, g_wqTl);
    cudaGetSymbolAddress((void**)&wkTh, g_wkTh);
    cudaGetSymbolAddress((void**)&wkTl, g_wkTl);
    cudaGetSymbolAddress((void**)&wvTh, g_wvTh);
    cudaGetSymbolAddress((void**)&wvTl, g_wvTl);
    cudaGetSymbolAddress((void**)&woTh, g_woTh);
    cudaGetSymbolAddress((void**)&woTl, g_woTl);
    cudaGetSymbolAddress((void**)&w1Th, g_w1Th);
    cudaGetSymbolAddress((void**)&w1Tl, g_w1Tl);
    cudaGetSymbolAddress((void**)&w2Th, g_w2Th);
    cudaGetSymbolAddress((void**)&w2Tl, g_w2Tl);

    static int attr_done = 0;
    if (!attr_done) {
        cudaFuncSetAttribute(gemm_tc_kernel,
                             cudaFuncAttributeMaxDynamicSharedMemorySize, GEMM_SMEM);
        cudaFuncSetAttribute(flash_attn_kernel,
                             cudaFuncAttributeMaxDynamicSharedMemorySize, FLASH_SMEM);
        attr_done = 1;
    }

    dim3 blk(256);

    // input split + weight transpose/split
    split_kernel<<<(NR_ * D_ / 4 + 255) / 256, blk>>>(x, pxh, pxl, (size_t)NR_ * D_ / 4);
    tsplit_kernel<<<dim3(D_ / 32, D_ / 32), blk>>>(wq, wqTh, wqTl, D_, D_);
    tsplit_kernel<<<dim3(D_ / 32, D_ / 32), blk>>>(wk, wkTh, wkTl, D_, D_);
    tsplit_kernel<<<dim3(D_ / 32, D_ / 32), blk>>>(wv, wvTh, wvTl, D_, D_);
    tsplit_kernel<<<dim3(D_ / 32, D_ / 32), blk>>>(wo, woTh, woTl, D_, D_);
    tsplit_kernel<<<dim3(DFF_ / 32, D_ / 32), blk>>>(w1, w1Th, w1Tl, D_, DFF_);
    tsplit_kernel<<<dim3(D_ / 32, DFF_ / 32), blk>>>(w2, w2Th, w2Tl, DFF_, D_);

    // QKV projections -> bf16 hi/lo outputs
    dim3 gProj(D_ / 128, NR_ / 128);
    gemm_tc_kernel<<<gProj, blk, GEMM_SMEM>>>(pxh, pxl, wqTh, wqTl, bq, nullptr,
                                              pqh, pql, NR_, D_, D_, 0);
    gemm_tc_kernel<<<gProj, blk, GEMM_SMEM>>>(pxh, pxl, wkTh, wkTl, bk, nullptr,
                                              pkh, pkl, NR_, D_, D_, 0);
    gemm_tc_kernel<<<gProj, blk, GEMM_SMEM>>>(pxh, pxl, wvTh, wvTl, bv, nullptr,
                                              pvh, pvl, NR_, D_, D_, 0);

    // fused flash attention
    flash_attn_kernel<<<dim3(S_ / 128, BH_), blk, FLASH_SMEM>>>(
        pqh, pql, pkh, pkl, pvh, pvl, rel, mask, pctxh, pctxl);

    // O projection
    gemm_tc_kernel<<<gProj, blk, GEMM_SMEM>>>(pctxh, pctxl, woTh, woTl, bo, pt1,
                                              nullptr, nullptr, NR_, D_, D_, 0);

    // x1 = LN(x + attn_out), with split
    add_ln_kernel<<<NR_, blk>>>(x, pt1, ln1g, ln1b, px1, px1h, px1l);

    // FFN
    dim3 gF1(DFF_ / 128, NR_ / 128);
    gemm_tc_kernel<<<gF1, blk, GEMM_SMEM>>>(px1h, px1l, w1Th, w1Tl, b1, nullptr,
                                            pffh, pffl, NR_, DFF_, D_, 1);
    dim3 gF2(D_ / 128, NR_ / 128);
    gemm_tc_kernel<<<gF2, blk, GEMM_SMEM>>>(pffh, pffl, w2Th, w2Tl, b2, pt1,
                                            nullptr, nullptr, NR_, D_, DFF_, 0);

    // out = LN(x1 + ff)
    add_ln_kernel<<<NR_, blk>>>(px1, pt1, ln2g, ln2b, out, nullptr, nullptr);
}

// round 6
// speedup vs baseline: 3.6284x; 1.3239x over previous
#include <cuda_runtime.h>
#include <cuda_bf16.h>
#include <math.h>
#include <stdint.h>

// Problem constants
#define B_   4
#define S_   1024
#define D_   1024
#define H_   16
#define DK_  64
#define DFF_ 4096
#define NR_  4096          // B*S rows
#define BH_  64            // B*H

typedef __nv_bfloat16 bf16;

// ---------------------------------------------------------------------------
// Scratch (device globals; .bss — no allocations)
// ---------------------------------------------------------------------------
__device__ float g_t1 [(size_t)NR_ * D_];
__device__ float g_x1 [(size_t)NR_ * D_];

// bf16 hi/lo split buffers
__device__ bf16 g_xh  [(size_t)NR_ * D_];
__device__ bf16 g_xl  [(size_t)NR_ * D_];
__device__ bf16 g_qh  [(size_t)NR_ * D_];
__device__ bf16 g_ql  [(size_t)NR_ * D_];
__device__ bf16 g_kh  [(size_t)NR_ * D_];
__device__ bf16 g_kl  [(size_t)NR_ * D_];
__device__ bf16 g_vh  [(size_t)NR_ * D_];
__device__ bf16 g_vl  [(size_t)NR_ * D_];
__device__ bf16 g_ctxh[(size_t)NR_ * D_];
__device__ bf16 g_ctxl[(size_t)NR_ * D_];
__device__ bf16 g_x1h [(size_t)NR_ * D_];
__device__ bf16 g_x1l [(size_t)NR_ * D_];
__device__ bf16 g_ffh [(size_t)NR_ * DFF_];
__device__ bf16 g_ffl [(size_t)NR_ * DFF_];
// transposed+split weights: [N,K] bf16
__device__ bf16 g_wqTh[(size_t)D_ * D_];
__device__ bf16 g_wqTl[(size_t)D_ * D_];
__device__ bf16 g_wkTh[(size_t)D_ * D_];
__device__ bf16 g_wkTl[(size_t)D_ * D_];
__device__ bf16 g_wvTh[(size_t)D_ * D_];
__device__ bf16 g_wvTl[(size_t)D_ * D_];
__device__ bf16 g_woTh[(size_t)D_ * D_];
__device__ bf16 g_woTl[(size_t)D_ * D_];
__device__ bf16 g_w1Th[(size_t)DFF_ * D_];
__device__ bf16 g_w1Tl[(size_t)DFF_ * D_];
__device__ bf16 g_w2Th[(size_t)D_ * DFF_];
__device__ bf16 g_w2Tl[(size_t)D_ * DFF_];

// ---------------------------------------------------------------------------
// Warp-MMA / cp.async primitives (portable to plain compute_103)
// ---------------------------------------------------------------------------
__device__ __forceinline__ uint32_t smem_to_u32(const void* p) {
    uint32_t a;
    asm("{ .reg .u64 t; cvta.to.shared.u64 t, %1; cvt.u32.u64 %0, t; }"
        : "=r"(a) : "l"(p));
    return a;
}

__device__ __forceinline__ void ldmx4(uint32_t* r, uint32_t addr) {
    asm volatile("ldmatrix.sync.aligned.m8n8.x4.shared.b16 {%0,%1,%2,%3}, [%4];"
                 : "=r"(r[0]), "=r"(r[1]), "=r"(r[2]), "=r"(r[3]) : "r"(addr));
}

__device__ __forceinline__ void ldmx4t(uint32_t* r, uint32_t addr) {
    asm volatile("ldmatrix.sync.aligned.m8n8.x4.trans.shared.b16 {%0,%1,%2,%3}, [%4];"
                 : "=r"(r[0]), "=r"(r[1]), "=r"(r[2]), "=r"(r[3]) : "r"(addr));
}

__device__ __forceinline__ void mma_bf16(float* c, const uint32_t* a,
                                         const uint32_t* b) {
    asm volatile(
        "mma.sync.aligned.m16n8k16.row.col.f32.bf16.bf16.f32 "
        "{%0,%1,%2,%3}, {%4,%5,%6,%7}, {%8,%9}, {%0,%1,%2,%3};"
        : "+f"(c[0]), "+f"(c[1]), "+f"(c[2]), "+f"(c[3])
        : "r"(a[0]), "r"(a[1]), "r"(a[2]), "r"(a[3]), "r"(b[0]), "r"(b[1]));
}

__device__ __forceinline__ uint32_t packbf(float lo, float hi) {
    uint32_t r;
    asm("cvt.rn.bf16x2.f32 %0, %1, %2;" : "=r"(r) : "f"(hi), "f"(lo));
    return r;
}
__device__ __forceinline__ float bfres(float x) {
    return x - __bfloat162float(__float2bfloat16(x));
}

#define CP_ASYNC16(dst, src) \
    asm volatile("cp.async.cg.shared.global [%0], [%1], 16;" \
                 :: "r"(dst), "l"(src) : "memory")
#define CP_COMMIT() asm volatile("cp.async.commit_group;" ::: "memory")
#define CP_WAIT(n)  asm volatile("cp.async.wait_group %0;" :: "n"(n) : "memory")

// ---------------------------------------------------------------------------
// Tensor-core GEMM (mma.sync): C[M,N] = A[M,K] @ B^T + bias, 3-term bf16 split
// 2-stage cp.async pipeline, 128x128 CTA tile, 8 warps 2x4.
// ---------------------------------------------------------------------------
#define GT_ROWB   144
#define GT_TILE   (128 * GT_ROWB)       // 18432
#define GT_STAGE  (4 * GT_TILE)         // 73728
#define GEMM_SMEM (2 * GT_STAGE)        // 147456

__global__ __launch_bounds__(256)
void gemm_tc_kernel(const bf16* __restrict__ Ahi, const bf16* __restrict__ Alo,
                    const bf16* __restrict__ Bhi, const bf16* __restrict__ Blo,
                    const float* __restrict__ bias,
                    float* __restrict__ Cf,
                    bf16* __restrict__ Chi, bf16* __restrict__ Clo,
                    int M, int N, int K, int relu)
{
    extern __shared__ char smem[];
    const uint32_t sbase = smem_to_u32(smem);

    const int tid  = threadIdx.x;
    const int wid  = tid >> 5;
    const int lane = tid & 31;
    const int warpM = wid >> 2;
    const int warpN = wid & 3;
    const int m0 = blockIdx.y * 128;
    const int n0 = blockIdx.x * 128;

    const bf16* srcs[4] = { Ahi + (size_t)m0 * K, Alo + (size_t)m0 * K,
                            Bhi + (size_t)n0 * K, Blo + (size_t)n0 * K };

    // per-thread load geometry: 16 chunks of 16B
    const int lt   = tid >> 6;              // which of 4 tiles this thread group... no:
    // use flat decomposition as before: i = tid + l*256; t=i>>10; j=i&1023
    float acc[4][4][4];
#pragma unroll
    for (int i = 0; i < 4; i++)
#pragma unroll
        for (int j = 0; j < 4; j++)
#pragma unroll
            for (int r = 0; r < 4; r++) acc[i][j][r] = 0.f;
    (void)lt;

    const uint32_t aoff = (uint32_t)(lane & 15) * GT_ROWB + (uint32_t)(lane >> 4) * 16;
    const uint32_t boff = (uint32_t)(((lane >> 4) * 8) + (lane & 7)) * GT_ROWB
                        + (uint32_t)((lane >> 3) & 1) * 16;

    const int nchunk = K >> 6;

    // prologue: issue chunk 0 into stage 0
#pragma unroll
    for (int l = 0; l < 16; l++) {
        int i = tid + l * 256;
        int t = i >> 10, j = i & 1023;
        int row = j >> 3, kc = j & 7;
        uint32_t dst = sbase + t * GT_TILE + row * GT_ROWB + kc * 16;
        CP_ASYNC16(dst, srcs[t] + (size_t)row * K + kc * 8);
    }
    CP_COMMIT();

    for (int s = 0; s < nchunk; s++) {
        if (s + 1 < nchunk) {
            const uint32_t stg = (uint32_t)((s + 1) & 1) * GT_STAGE;
            const int k1 = (s + 1) << 6;
#pragma unroll
            for (int l = 0; l < 16; l++) {
                int i = tid + l * 256;
                int t = i >> 10, j = i & 1023;
                int row = j >> 3, kc = j & 7;
                uint32_t dst = sbase + stg + t * GT_TILE + row * GT_ROWB + kc * 16;
                CP_ASYNC16(dst, srcs[t] + (size_t)row * K + k1 + kc * 8);
            }
            CP_COMMIT();
            CP_WAIT(1);
        } else {
            CP_WAIT(0);
        }
        __syncthreads();

        const uint32_t stg = (uint32_t)(s & 1) * GT_STAGE;
        const uint32_t aBaseHi = sbase + stg + 0 * GT_TILE + (uint32_t)warpM * 64 * GT_ROWB + aoff;
        const uint32_t aBaseLo = sbase + stg + 1 * GT_TILE + (uint32_t)warpM * 64 * GT_ROWB + aoff;
        const uint32_t bBaseHi = sbase + stg + 2 * GT_TILE + (uint32_t)warpN * 32 * GT_ROWB + boff;
        const uint32_t bBaseLo = sbase + stg + 3 * GT_TILE + (uint32_t)warpN * 32 * GT_ROWB + boff;

#pragma unroll
        for (int ks = 0; ks < 4; ks++) {
            uint32_t af[4][4], bh_[4][2], bl_[4][2];
#pragma unroll
            for (int fm = 0; fm < 4; fm++)
                ldmx4(af[fm], aBaseHi + (uint32_t)fm * 16 * GT_ROWB + ks * 32);
#pragma unroll
            for (int g = 0; g < 2; g++) {
                uint32_t r[4];
                ldmx4(r, bBaseHi + (uint32_t)g * 16 * GT_ROWB + ks * 32);
                bh_[g * 2][0] = r[0]; bh_[g * 2][1] = r[1];
                bh_[g * 2 + 1][0] = r[2]; bh_[g * 2 + 1][1] = r[3];
            }
#pragma unroll
            for (int fm = 0; fm < 4; fm++)
#pragma unroll
                for (int fn = 0; fn < 4; fn++)
                    mma_bf16(acc[fm][fn], af[fm], bh_[fn]);
#pragma unroll
            for (int g = 0; g < 2; g++) {
                uint32_t r[4];
                ldmx4(r, bBaseLo + (uint32_t)g * 16 * GT_ROWB + ks * 32);
                bl_[g * 2][0] = r[0]; bl_[g * 2][1] = r[1];
                bl_[g * 2 + 1][0] = r[2]; bl_[g * 2 + 1][1] = r[3];
            }
#pragma unroll
            for (int fm = 0; fm < 4; fm++)
#pragma unroll
                for (int fn = 0; fn < 4; fn++)
                    mma_bf16(acc[fm][fn], af[fm], bl_[fn]);
#pragma unroll
            for (int fm = 0; fm < 4; fm++)
                ldmx4(af[fm], aBaseLo + (uint32_t)fm * 16 * GT_ROWB + ks * 32);
#pragma unroll
            for (int fm = 0; fm < 4; fm++)
#pragma unroll
                for (int fn = 0; fn < 4; fn++)
                    mma_bf16(acc[fm][fn], af[fm], bh_[fn]);
        }
        __syncthreads();
    }

    const int qr = lane >> 2;
    const int qc = (lane & 3) * 2;
#pragma unroll
    for (int fm = 0; fm < 4; fm++) {
#pragma unroll
        for (int fn = 0; fn < 4; fn++) {
            float* a = acc[fm][fn];
            int row = m0 + warpM * 64 + fm * 16 + qr;
            int col = n0 + warpN * 32 + fn * 8 + qc;
            float b0 = bias[col], b1 = bias[col + 1];
            float v00 = a[0] + b0, v01 = a[1] + b1;
            float v10 = a[2] + b0, v11 = a[3] + b1;
            if (relu) {
                v00 = fmaxf(v00, 0.f); v01 = fmaxf(v01, 0.f);
                v10 = fmaxf(v10, 0.f); v11 = fmaxf(v11, 0.f);
            }
            size_t i0 = (size_t)row * N + col;
            size_t i1 = (size_t)(row + 8) * N + col;
            if (Cf) {
                *(float2*)&Cf[i0] = make_float2(v00, v01);
                *(float2*)&Cf[i1] = make_float2(v10, v11);
            }
            if (Chi) {
                bf16 h00 = __float2bfloat16(v00), h01 = __float2bfloat16(v01);
                bf16 h10 = __float2bfloat16(v10), h11 = __float2bfloat16(v11);
                *(__nv_bfloat162*)&Chi[i0] = __nv_bfloat162(h00, h01);
                *(__nv_bfloat162*)&Chi[i1] = __nv_bfloat162(h10, h11);
                *(__nv_bfloat162*)&Clo[i0] = __nv_bfloat162(
                    __float2bfloat16(v00 - __bfloat162float(h00)),
                    __float2bfloat16(v01 - __bfloat162float(h01)));
                *(__nv_bfloat162*)&Clo[i1] = __nv_bfloat162(
                    __float2bfloat16(v10 - __bfloat162float(h10)),
                    __float2bfloat16(v11 - __bfloat162float(h11)));
            }
        }
    }
}

// ---------------------------------------------------------------------------
// Fused flash attention with 2-stage cp.async K/V pipeline.
// per CTA = (128-row q-tile, one head); 8 warps, warp w owns rows w*16..+15.
// ---------------------------------------------------------------------------
#define FROWB 144
#define FTILE (128 * FROWB)                      // 18432
#define FKV_STAGE (4 * FTILE)                    // 73728
#define FLASH_SMEM (10 * FTILE + 8192 + 4096)    // 196608

__global__ __launch_bounds__(256)
void flash_attn_kernel(const bf16* __restrict__ qh, const bf16* __restrict__ ql,
                       const bf16* __restrict__ kh, const bf16* __restrict__ kl,
                       const bf16* __restrict__ vh, const bf16* __restrict__ vl,
                       const float* __restrict__ rel, const int* __restrict__ mask,
                       bf16* __restrict__ ctxh, bf16* __restrict__ ctxl)
{
    extern __shared__ char smem[];
    const int qt = blockIdx.x;
    const int bhid = blockIdx.y;
    const int b = bhid >> 4, h = bhid & 15;
    const int tid = threadIdx.x, wid = tid >> 5, lane = tid & 31;
    const int qr = lane >> 2, qc = (lane & 3) * 2;

    const uint32_t ub = smem_to_u32(smem);
    float* s_rel = (float*)(smem + 10 * FTILE);
    int*   s_msk = (int*)(smem + 10 * FTILE + 8192);

    const bf16* kvsrc[4] = { kh, kl, vh, vl };

    // KV chunk 0 via cp.async into stage 0
    {
        const size_t kg = ((size_t)b * S_) * D_ + h * 64;
#pragma unroll
        for (int l = 0; l < 16; l++) {
            int i = tid + l * 256;
            int t = i >> 10, j = i & 1023;
            int row = j >> 3, kc = j & 7;
            uint32_t dst = ub + 2 * FTILE + t * FTILE + row * FROWB + kc * 16;
            CP_ASYNC16(dst, kvsrc[t] + kg + (size_t)row * D_ + kc * 8);
        }
        CP_COMMIT();
    }

    // Q tiles (hi/lo) + rel column + full mask row (regular loads)
    const size_t qg = ((size_t)b * S_ + qt * 128) * D_ + h * 64;
#pragma unroll
    for (int l = 0; l < 8; l++) {
        int i = tid + l * 256;
        int t = i >> 10, j = i & 1023;
        int row = j >> 3, kc = j & 7;
        const bf16* src = t ? ql : qh;
        *(float4*)(smem + t * FTILE + row * FROWB + kc * 16) =
            *(const float4*)(src + qg + (size_t)row * D_ + kc * 8);
    }
    for (int i = tid; i < 2047; i += 256) s_rel[i] = rel[i * H_ + h];
    for (int i = tid; i < 1024; i += 256) s_msk[i] = mask[b * S_ + i];

    float acc_o[8][4];
#pragma unroll
    for (int a = 0; a < 8; a++) {
        acc_o[a][0] = acc_o[a][1] = acc_o[a][2] = acc_o[a][3] = 0.f;
    }
    float mrow[2] = {-1e30f, -1e30f}, lrow[2] = {0.f, 0.f};

    const uint32_t aoff = (uint32_t)(lane & 15) * FROWB + (uint32_t)(lane >> 4) * 16;
    const uint32_t boff = (uint32_t)(((lane >> 4) * 8) + (lane & 7)) * FROWB
                        + (uint32_t)((lane >> 3) & 1) * 16;
    const uint32_t uQh = ub + 0 * FTILE + (uint32_t)wid * 16 * FROWB + aoff;
    const uint32_t uQl = ub + 1 * FTILE + (uint32_t)wid * 16 * FROWB + aoff;
    const uint32_t vto = (uint32_t)(lane & 15) * FROWB + (uint32_t)(lane >> 4) * 16;

    for (int kt = 0; kt < 8; kt++) {
        if (kt + 1 < 8) {
            const uint32_t stg = (uint32_t)((kt + 1) & 1) * FKV_STAGE;
            const size_t kg = ((size_t)b * S_ + (kt + 1) * 128) * D_ + h * 64;
#pragma unroll
            for (int l = 0; l < 16; l++) {
                int i = tid + l * 256;
                int t = i >> 10, j = i & 1023;
                int row = j >> 3, kc = j & 7;
                uint32_t dst = ub + 2 * FTILE + stg + t * FTILE + row * FROWB + kc * 16;
                CP_ASYNC16(dst, kvsrc[t] + kg + (size_t)row * D_ + kc * 8);
            }
            CP_COMMIT();
            CP_WAIT(1);
        } else {
            CP_WAIT(0);
        }
        __syncthreads();

        const uint32_t stg = (uint32_t)(kt & 1) * FKV_STAGE;
        const uint32_t uKh = ub + 2 * FTILE + stg + 0 * FTILE + boff;
        const uint32_t uKl = ub + 2 * FTILE + stg + 1 * FTILE + boff;
        const uint32_t uVh = ub + 2 * FTILE + stg + 2 * FTILE + vto;
        const uint32_t uVl = ub + 2 * FTILE + stg + 3 * FTILE + vto;

        // ---- S = Q.K^T (3-term bf16) ----
        float accs[16][4];
#pragma unroll
        for (int f = 0; f < 16; f++) {
            accs[f][0] = accs[f][1] = accs[f][2] = accs[f][3] = 0.f;
        }
#pragma unroll
        for (int ks = 0; ks < 4; ks++) {
            uint32_t aqh[4], aql4[4];
            ldmx4(aqh,  uQh + ks * 32);
            ldmx4(aql4, uQl + ks * 32);
#pragma unroll
            for (int g = 0; g < 8; g++) {
                uint32_t rkh[4], rkl[4];
                ldmx4(rkh, uKh + (uint32_t)g * 16 * FROWB + ks * 32);
                ldmx4(rkl, uKl + (uint32_t)g * 16 * FROWB + ks * 32);
                mma_bf16(accs[2 * g],     aqh,  rkh);
                mma_bf16(accs[2 * g + 1], aqh,  rkh + 2);
                mma_bf16(accs[2 * g],     aqh,  rkl);
                mma_bf16(accs[2 * g + 1], aqh,  rkl + 2);
                mma_bf16(accs[2 * g],     aql4, rkh);
                mma_bf16(accs[2 * g + 1], aql4, rkh + 2);
            }
        }

        // ---- bias + mask + online softmax ----
        const int rb0 = qt * 128 + wid * 16 + qr - kt * 128 + 1023;
        const int mb0 = kt * 128;
        float rmax[2] = {-1e30f, -1e30f};
#pragma unroll
        for (int f = 0; f < 16; f++) {
            int c0 = f * 8 + qc;
            float s0 = accs[f][0] * 0.125f + s_rel[rb0 - c0];
            float s1 = accs[f][1] * 0.125f + s_rel[rb0 - c0 - 1];
            float s2 = accs[f][2] * 0.125f + s_rel[rb0 + 8 - c0];
            float s3 = accs[f][3] * 0.125f + s_rel[rb0 + 8 - c0 - 1];
            if (s_msk[mb0 + c0] == 0)     { s0 = -1e9f; s2 = -1e9f; }
            if (s_msk[mb0 + c0 + 1] == 0) { s1 = -1e9f; s3 = -1e9f; }
            accs[f][0] = s0; accs[f][1] = s1; accs[f][2] = s2; accs[f][3] = s3;
            rmax[0] = fmaxf(rmax[0], fmaxf(s0, s1));
            rmax[1] = fmaxf(rmax[1], fmaxf(s2, s3));
        }
#pragma unroll
        for (int r = 0; r < 2; r++) {
            rmax[r] = fmaxf(rmax[r], __shfl_xor_sync(0xffffffff, rmax[r], 1));
            rmax[r] = fmaxf(rmax[r], __shfl_xor_sync(0xffffffff, rmax[r], 2));
        }
        float alpha[2];
#pragma unroll
        for (int r = 0; r < 2; r++) {
            float mn = fmaxf(mrow[r], rmax[r]);
            alpha[r] = __expf(mrow[r] - mn);
            mrow[r] = mn;
        }
        float rsum[2] = {0.f, 0.f};
#pragma unroll
        for (int f = 0; f < 16; f++) {
            float p0 = __expf(accs[f][0] - mrow[0]);
            float p1 = __expf(accs[f][1] - mrow[0]);
            float p2 = __expf(accs[f][2] - mrow[1]);
            float p3 = __expf(accs[f][3] - mrow[1]);
            accs[f][0] = p0; accs[f][1] = p1; accs[f][2] = p2; accs[f][3] = p3;
            rsum[0] += p0 + p1;
            rsum[1] += p2 + p3;
        }
#pragma unroll
        for (int r = 0; r < 2; r++) {
            rsum[r] += __shfl_xor_sync(0xffffffff, rsum[r], 1);
            rsum[r] += __shfl_xor_sync(0xffffffff, rsum[r], 2);
            lrow[r] = lrow[r] * alpha[r] + rsum[r];
        }
#pragma unroll
        for (int a = 0; a < 8; a++) {
            acc_o[a][0] *= alpha[0]; acc_o[a][1] *= alpha[0];
            acc_o[a][2] *= alpha[1]; acc_o[a][3] *= alpha[1];
        }

        // ---- O += P.V (3-term: Ph*Vh + Ph*Vl + Pl*Vh) ----
#pragma unroll
        for (int kc = 0; kc < 8; kc++) {
            const int f0 = 2 * kc, f1 = 2 * kc + 1;
            uint32_t aPh[4], aPl[4];
            aPh[0] = packbf(accs[f0][0], accs[f0][1]);
            aPh[1] = packbf(accs[f0][2], accs[f0][3]);
            aPh[2] = packbf(accs[f1][0], accs[f1][1]);
            aPh[3] = packbf(accs[f1][2], accs[f1][3]);
            aPl[0] = packbf(bfres(accs[f0][0]), bfres(accs[f0][1]));
            aPl[1] = packbf(bfres(accs[f0][2]), bfres(accs[f0][3]));
            aPl[2] = packbf(bfres(accs[f1][0]), bfres(accs[f1][1]));
            aPl[3] = packbf(bfres(accs[f1][2]), bfres(accs[f1][3]));
#pragma unroll
            for (int jg = 0; jg < 4; jg++) {
                uint32_t v4h[4], v4l[4];
                uint32_t off = (uint32_t)(kc * 16) * FROWB + jg * 32;
                ldmx4t(v4h, uVh + off);
                ldmx4t(v4l, uVl + off);
                mma_bf16(acc_o[2 * jg],     aPh, v4h);
                mma_bf16(acc_o[2 * jg + 1], aPh, v4h + 2);
                mma_bf16(acc_o[2 * jg],     aPh, v4l);
                mma_bf16(acc_o[2 * jg + 1], aPh, v4l + 2);
                mma_bf16(acc_o[2 * jg],     aPl, v4h);
                mma_bf16(acc_o[2 * jg + 1], aPl, v4h + 2);
            }
        }
        __syncthreads();
    }

    // ---- epilogue: normalize, split to bf16 hi/lo, write ctx ----
    const float inv0 = 1.f / lrow[0], inv1 = 1.f / lrow[1];
    const int row0 = qt * 128 + wid * 16 + qr;
#pragma unroll
    for (int a = 0; a < 8; a++) {
        int col = a * 8 + qc;
        size_t i0 = ((size_t)b * S_ + row0) * D_ + h * 64 + col;
        size_t i1 = ((size_t)b * S_ + row0 + 8) * D_ + h * 64 + col;
        float v00 = acc_o[a][0] * inv0, v01 = acc_o[a][1] * inv0;
        float v10 = acc_o[a][2] * inv1, v11 = acc_o[a][3] * inv1;
        bf16 h00 = __float2bfloat16(v00), h01 = __float2bfloat16(v01);
        bf16 h10 = __float2bfloat16(v10), h11 = __float2bfloat16(v11);
        *(__nv_bfloat162*)&ctxh[i0] = __nv_bfloat162(h00, h01);
        *(__nv_bfloat162*)&ctxh[i1] = __nv_bfloat162(h10, h11);
        *(__nv_bfloat162*)&ctxl[i0] = __nv_bfloat162(
            __float2bfloat16(v00 - __bfloat162float(h00)),
            __float2bfloat16(v01 - __bfloat162float(h01)));
        *(__nv_bfloat162*)&ctxl[i1] = __nv_bfloat162(
            __float2bfloat16(v10 - __bfloat162float(h10)),
            __float2bfloat16(v11 - __bfloat162float(h11)));
    }
}

// ---------------------------------------------------------------------------
// fp32 -> bf16 hi/lo split (elementwise, vectorized)
// ---------------------------------------------------------------------------
__global__ __launch_bounds__(256)
void split_kernel(const float* __restrict__ X, bf16* __restrict__ Xh,
                  bf16* __restrict__ Xl, size_t n4)
{
    size_t i = (size_t)blockIdx.x * 256 + threadIdx.x;
    if (i >= n4) return;
    float4 v = ((const float4*)X)[i];
    bf16 h0 = __float2bfloat16(v.x), h1 = __float2bfloat16(v.y);
    bf16 h2 = __float2bfloat16(v.z), h3 = __float2bfloat16(v.w);
    size_t o = i * 4;
    Xh[o] = h0; Xh[o+1] = h1; Xh[o+2] = h2; Xh[o+3] = h3;
    Xl[o]   = __float2bfloat16(v.x - __bfloat162float(h0));
    Xl[o+1] = __float2bfloat16(v.y - __bfloat162float(h1));
    Xl[o+2] = __float2bfloat16(v.z - __bfloat162float(h2));
    Xl[o+3] = __float2bfloat16(v.w - __bfloat162float(h3));
}

// ---------------------------------------------------------------------------
// W[K,N] fp32 -> transposed hi/lo bf16 [N,K]
// ---------------------------------------------------------------------------
__global__ __launch_bounds__(256)
void tsplit_kernel(const float* __restrict__ W, bf16* __restrict__ Th,
                   bf16* __restrict__ Tl, int K, int N)
{
    __shared__ float t[32][33];
    const int k0 = blockIdx.y * 32, n0 = blockIdx.x * 32;
    const int tx = threadIdx.x & 31, ty = threadIdx.x >> 5;
    for (int r = ty; r < 32; r += 8)
        t[r][tx] = W[(size_t)(k0 + r) * N + n0 + tx];
    __syncthreads();
    for (int r = ty; r < 32; r += 8) {
        float v = t[tx][r];
        bf16 h = __float2bfloat16(v);
        size_t oi = (size_t)(n0 + r) * K + k0 + tx;
        Th[oi] = h;
        Tl[oi] = __float2bfloat16(v - __bfloat162float(h));
    }
}

// ---------------------------------------------------------------------------
// out = LayerNorm(x + y) * g + b; optionally also emit bf16 hi/lo split
// ---------------------------------------------------------------------------
__global__ __launch_bounds__(256)
void add_ln_kernel(const float* __restrict__ x, const float* __restrict__ y,
                   const float* __restrict__ g, const float* __restrict__ b,
                   float* __restrict__ out, bf16* __restrict__ oh,
                   bf16* __restrict__ ol)
{
    __shared__ float red[256];
    const size_t base = (size_t)blockIdx.x * D_;
    const int tid = threadIdx.x;

    float v[4];
    float s = 0.f;
#pragma unroll
    for (int l = 0; l < 4; l++) {
        int i = tid + l * 256;
        v[l] = x[base + i] + y[base + i];
        s += v[l];
    }
    red[tid] = s; __syncthreads();
    for (int st = 128; st > 0; st >>= 1) {
        if (tid < st) red[tid] += red[tid + st];
        __syncthreads();
    }
    float mean = red[0] * (1.0f / D_); __syncthreads();

    float sq = 0.f;
#pragma unroll
    for (int l = 0; l < 4; l++) { float d = v[l] - mean; sq += d * d; }
    red[tid] = sq; __syncthreads();
    for (int st = 128; st > 0; st >>= 1) {
        if (tid < st) red[tid] += red[tid + st];
        __syncthreads();
    }
    float rstd = rsqrtf(red[0] * (1.0f / D_) + 1e-5f);

#pragma unroll
    for (int l = 0; l < 4; l++) {
        int i = tid + l * 256;
        float o = (v[l] - mean) * rstd * g[i] + b[i];
        out[base + i] = o;
        if (oh) {
            bf16 hh = __float2bfloat16(o);
            oh[base + i] = hh;
            ol[base + i] = __float2bfloat16(o - __bfloat162float(hh));
        }
    }
}

// ---------------------------------------------------------------------------
// Launch
// ---------------------------------------------------------------------------
extern "C" void kernel_launch(void* const* d_in, const int* in_sizes, int n_in,
                              void* d_out, int out_size)
{
    const float* x    = (const float*)d_in[0];
    const float* wq   = (const float*)d_in[1];
    const float* bq   = (const float*)d_in[2];
    const float* wk   = (const float*)d_in[3];
    const float* bk   = (const float*)d_in[4];
    const float* wv   = (const float*)d_in[5];
    const float* bv   = (const float*)d_in[6];
    const float* wo   = (const float*)d_in[7];
    const float* bo   = (const float*)d_in[8];
    const float* rel  = (const float*)d_in[9];
    const float* ln1g = (const float*)d_in[10];
    const float* ln1b = (const float*)d_in[11];
    const float* w1   = (const float*)d_in[12];
    const float* b1   = (const float*)d_in[13];
    const float* w2   = (const float*)d_in[14];
    const float* b2   = (const float*)d_in[15];
    const float* ln2g = (const float*)d_in[16];
    const float* ln2b = (const float*)d_in[17];
    const int*   mask = (const int*)  d_in[18];
    float* out = (float*)d_out;

    float *pt1, *px1;
    bf16 *pxh, *pxl, *pqh, *pql, *pkh, *pkl, *pvh, *pvl;
    bf16 *pctxh, *pctxl, *px1h, *px1l, *pffh, *pffl;
    bf16 *wqTh, *wqTl, *wkTh, *wkTl, *wvTh, *wvTl, *woTh, *woTl;
    bf16 *w1Th, *w1Tl, *w2Th, *w2Tl;
    cudaGetSymbolAddress((void**)&pt1,  g_t1);
    cudaGetSymbolAddress((void**)&px1,  g_x1);
    cudaGetSymbolAddress((void**)&pxh,  g_xh);
    cudaGetSymbolAddress((void**)&pxl,  g_xl);
    cudaGetSymbolAddress((void**)&pqh,  g_qh);
    cudaGetSymbolAddress((void**)&pql,  g_ql);
    cudaGetSymbolAddress((void**)&pkh,  g_kh);
    cudaGetSymbolAddress((void**)&pkl,  g_kl);
    cudaGetSymbolAddress((void**)&pvh,  g_vh);
    cudaGetSymbolAddress((void**)&pvl,  g_vl);
    cudaGetSymbolAddress((void**)&pctxh, g_ctxh);
    cudaGetSymbolAddress((void**)&pctxl, g_ctxl);
    cudaGetSymbolAddress((void**)&px1h, g_x1h);
    cudaGetSymbolAddress((void**)&px1l, g_x1l);
    cudaGetSymbolAddress((void**)&pffh, g_ffh);
    cudaGetSymbolAddress((void**)&pffl, g_ffl);
    cudaGetSymbolAddress((void**)&wqTh, g_wqTh);
    cudaGetSymbolAddress((void**)&wqTl, g_wqTl);
    cudaGetSymbolAddress((void**)&wkTh, g_wkTh);
    cudaGetSymbolAddress((void**)&wkTl, g_wkTl);
    cudaGetSymbolAddress((void**)&wvTh, g_wvTh);
    cudaGetSymbolAddress((void**)&wvTl, g_wvTl);
    cudaGetSymbolAddress((void**)&woTh, g_woTh);
    cudaGetSymbolAddress((void**)&woTl, g_woTl);
    cudaGetSymbolAddress((void**)&w1Th, g_w1Th);
    cudaGetSymbolAddress((void**)&w1Tl, g_w1Tl);
    cudaGetSymbolAddress((void**)&w2Th, g_w2Th);
    cudaGetSymbolAddress((void**)&w2Tl, g_w2Tl);

    cudaFuncSetAttribute(gemm_tc_kernel,
                         cudaFuncAttributeMaxDynamicSharedMemorySize, GEMM_SMEM);
    cudaFuncSetAttribute(flash_attn_kernel,
                         cudaFuncAttributeMaxDynamicSharedMemorySize, FLASH_SMEM);

    dim3 blk(256);

    // input split + weight transpose/split
    split_kernel<<<(NR_ * D_ / 4 + 255) / 256, blk>>>(x, pxh, pxl, (size_t)NR_ * D_ / 4);
    tsplit_kernel<<<dim3(D_ / 32, D_ / 32), blk>>>(wq, wqTh, wqTl, D_, D_);
    tsplit_kernel<<<dim3(D_ / 32, D_ / 32), blk>>>(wk, wkTh, wkTl, D_, D_);
    tsplit_kernel<<<dim3(D_ / 32, D_ / 32), blk>>>(wv, wvTh, wvTl, D_, D_);
    tsplit_kernel<<<dim3(D_ / 32, D_ / 32), blk>>>(wo, woTh, woTl, D_, D_);
    tsplit_kernel<<<dim3(DFF_ / 32, D_ / 32), blk>>>(w1, w1Th, w1Tl, D_, DFF_);
    tsplit_kernel<<<dim3(D_ / 32, DFF_ / 32), blk>>>(w2, w2Th, w2Tl, DFF_, D_);

    // QKV projections -> bf16 hi/lo outputs
    dim3 gProj(D_ / 128, NR_ / 128);
    gemm_tc_kernel<<<gProj, blk, GEMM_SMEM>>>(pxh, pxl, wqTh, wqTl, bq, nullptr,
                                              pqh, pql, NR_, D_, D_, 0);
    gemm_tc_kernel<<<gProj, blk, GEMM_SMEM>>>(pxh, pxl, wkTh, wkTl, bk, nullptr,
                                              pkh, pkl, NR_, D_, D_, 0);
    gemm_tc_kernel<<<gProj, blk, GEMM_SMEM>>>(pxh, pxl, wvTh, wvTl, bv, nullptr,
                                              pvh, pvl, NR_, D_, D_, 0);

    // fused flash attention
    flash_attn_kernel<<<dim3(S_ / 128, BH_), blk, FLASH_SMEM>>>(
        pqh, pql, pkh, pkl, pvh, pvl, rel, mask, pctxh, pctxl);

    // O projection
    gemm_tc_kernel<<<gProj, blk, GEMM_SMEM>>>(pctxh, pctxl, woTh, woTl, bo, pt1,
                                              nullptr, nullptr, NR_, D_, D_, 0);

    // x1 = LN(x + attn_out), with split
    add_ln_kernel<<<NR_, blk>>>(x, pt1, ln1g, ln1b, px1, px1h, px1l);

    // FFN
    dim3 gF1(DFF_ / 128, NR_ / 128);
    gemm_tc_kernel<<<gF1, blk, GEMM_SMEM>>>(px1h, px1l, w1Th, w1Tl, b1, nullptr,
                                            pffh, pffl, NR_, DFF_, D_, 1);
    dim3 gF2(D_ / 128, NR_ / 128);
    gemm_tc_kernel<<<gF2, blk, GEMM_SMEM>>>(pffh, pffl, w2Th, w2Tl, b2, pt1,
                                            nullptr, nullptr, NR_, D_, DFF_, 0);

    // out = LN(x1 + ff)
    add_ln_kernel<<<NR_, blk>>>(px1, pt1, ln2g, ln2b, out, nullptr, nullptr);
}

// round 7
// speedup vs baseline: 3.6432x; 1.0041x over previous
#include <cuda_runtime.h>
#include <cuda_bf16.h>
#include <math.h>
#include <stdint.h>

// Problem constants
#define B_   4
#define S_   1024
#define D_   1024
#define H_   16
#define DK_  64
#define DFF_ 4096
#define NR_  4096          // B*S rows
#define BH_  64            // B*H

typedef __nv_bfloat16 bf16;

// ---------------------------------------------------------------------------
// Scratch (device globals; .bss — no allocations)
// ---------------------------------------------------------------------------
__device__ float g_t1 [(size_t)NR_ * D_];
__device__ float g_x1 [(size_t)NR_ * D_];

__device__ bf16 g_xh  [(size_t)NR_ * D_];
__device__ bf16 g_xl  [(size_t)NR_ * D_];
__device__ bf16 g_qh  [(size_t)NR_ * D_];
__device__ bf16 g_ql  [(size_t)NR_ * D_];
__device__ bf16 g_kh  [(size_t)NR_ * D_];
__device__ bf16 g_kl  [(size_t)NR_ * D_];
__device__ bf16 g_vh  [(size_t)NR_ * D_];
__device__ bf16 g_vl  [(size_t)NR_ * D_];
__device__ bf16 g_ctxh[(size_t)NR_ * D_];
__device__ bf16 g_ctxl[(size_t)NR_ * D_];
__device__ bf16 g_x1h [(size_t)NR_ * D_];
__device__ bf16 g_x1l [(size_t)NR_ * D_];
__device__ bf16 g_ffh [(size_t)NR_ * DFF_];
__device__ bf16 g_ffl [(size_t)NR_ * DFF_];
// transposed+split weights: [N,K] bf16
__device__ bf16 g_wqTh[(size_t)D_ * D_];
__device__ bf16 g_wqTl[(size_t)D_ * D_];
__device__ bf16 g_wkTh[(size_t)D_ * D_];
__device__ bf16 g_wkTl[(size_t)D_ * D_];
__device__ bf16 g_wvTh[(size_t)D_ * D_];
__device__ bf16 g_wvTl[(size_t)D_ * D_];
__device__ bf16 g_woTh[(size_t)D_ * D_];
__device__ bf16 g_woTl[(size_t)D_ * D_];
__device__ bf16 g_w1Th[(size_t)DFF_ * D_];
__device__ bf16 g_w1Tl[(size_t)DFF_ * D_];
__device__ bf16 g_w2Th[(size_t)D_ * DFF_];
__device__ bf16 g_w2Tl[(size_t)D_ * DFF_];

// ---------------------------------------------------------------------------
// Warp-MMA / cp.async primitives (portable to plain compute_103)
// ---------------------------------------------------------------------------
__device__ __forceinline__ uint32_t smem_to_u32(const void* p) {
    uint32_t a;
    asm("{ .reg .u64 t; cvta.to.shared.u64 t, %1; cvt.u32.u64 %0, t; }"
        : "=r"(a) : "l"(p));
    return a;
}

__device__ __forceinline__ void ldmx4(uint32_t* r, uint32_t addr) {
    asm volatile("ldmatrix.sync.aligned.m8n8.x4.shared.b16 {%0,%1,%2,%3}, [%4];"
                 : "=r"(r[0]), "=r"(r[1]), "=r"(r[2]), "=r"(r[3]) : "r"(addr));
}

__device__ __forceinline__ void ldmx4t(uint32_t* r, uint32_t addr) {
    asm volatile("ldmatrix.sync.aligned.m8n8.x4.trans.shared.b16 {%0,%1,%2,%3}, [%4];"
                 : "=r"(r[0]), "=r"(r[1]), "=r"(r[2]), "=r"(r[3]) : "r"(addr));
}

__device__ __forceinline__ void mma_bf16(float* c, const uint32_t* a,
                                         const uint32_t* b) {
    asm volatile(
        "mma.sync.aligned.m16n8k16.row.col.f32.bf16.bf16.f32 "
        "{%0,%1,%2,%3}, {%4,%5,%6,%7}, {%8,%9}, {%0,%1,%2,%3};"
        : "+f"(c[0]), "+f"(c[1]), "+f"(c[2]), "+f"(c[3])
        : "r"(a[0]), "r"(a[1]), "r"(a[2]), "r"(a[3]), "r"(b[0]), "r"(b[1]));
}

__device__ __forceinline__ uint32_t packbf(float lo, float hi) {
    uint32_t r;
    asm("cvt.rn.bf16x2.f32 %0, %1, %2;" : "=r"(r) : "f"(hi), "f"(lo));
    return r;
}
__device__ __forceinline__ float bfres(float x) {
    return x - __bfloat162float(__float2bfloat16(x));
}

#define CP_ASYNC16(dst, src) \
    asm volatile("cp.async.cg.shared.global [%0], [%1], 16;" \
                 :: "r"(dst), "l"(src) : "memory")
#define CP_COMMIT() asm volatile("cp.async.commit_group;" ::: "memory")
#define CP_WAIT(n)  asm volatile("cp.async.wait_group %0;" :: "n"(n) : "memory")

// ---------------------------------------------------------------------------
// Tensor-core GEMM (mma.sync): C[M,N] = A[M,K] @ B^T + bias, 3-term bf16 split
// 2-stage cp.async pipeline, ONE barrier per K-chunk:
//   wait(0) -> sync -> issue next chunk -> compute
// (sync proves all warps finished compute s-1 on stage (s+1)&1 before we
//  overwrite it, and that chunk s's data is visible to all warps.)
// ---------------------------------------------------------------------------
#define GT_ROWB   144
#define GT_TILE   (128 * GT_ROWB)       // 18432
#define GT_STAGE  (4 * GT_TILE)         // 73728
#define GEMM_SMEM (2 * GT_STAGE)        // 147456

__global__ __launch_bounds__(256)
void gemm_tc_kernel(const bf16* __restrict__ Ahi, const bf16* __restrict__ Alo,
                    const bf16* __restrict__ Bhi, const bf16* __restrict__ Blo,
                    const float* __restrict__ bias,
                    float* __restrict__ Cf,
                    bf16* __restrict__ Chi, bf16* __restrict__ Clo,
                    int M, int N, int K, int relu)
{
    extern __shared__ char smem[];
    const uint32_t sbase = smem_to_u32(smem);

    const int tid  = threadIdx.x;
    const int wid  = tid >> 5;
    const int lane = tid & 31;
    const int warpM = wid >> 2;
    const int warpN = wid & 3;
    const int m0 = blockIdx.y * 128;
    const int n0 = blockIdx.x * 128;

    const bf16* srcs[4] = { Ahi + (size_t)m0 * K, Alo + (size_t)m0 * K,
                            Bhi + (size_t)n0 * K, Blo + (size_t)n0 * K };

    float acc[4][4][4];
#pragma unroll
    for (int i = 0; i < 4; i++)
#pragma unroll
        for (int j = 0; j < 4; j++)
#pragma unroll
            for (int r = 0; r < 4; r++) acc[i][j][r] = 0.f;

    const uint32_t aoff = (uint32_t)(lane & 15) * GT_ROWB + (uint32_t)(lane >> 4) * 16;
    const uint32_t boff = (uint32_t)(((lane >> 4) * 8) + (lane & 7)) * GT_ROWB
                        + (uint32_t)((lane >> 3) & 1) * 16;

    const int nchunk = K >> 6;

    // prologue: issue chunk 0 into stage 0
#pragma unroll
    for (int l = 0; l < 16; l++) {
        int i = tid + l * 256;
        int t = i >> 10, j = i & 1023;
        int row = j >> 3, kc = j & 7;
        uint32_t dst = sbase + t * GT_TILE + row * GT_ROWB + kc * 16;
        CP_ASYNC16(dst, srcs[t] + (size_t)row * K + kc * 8);
    }
    CP_COMMIT();

    for (int s = 0; s < nchunk; s++) {
        CP_WAIT(0);
        __syncthreads();
        if (s + 1 < nchunk) {
            const uint32_t stg = (uint32_t)((s + 1) & 1) * GT_STAGE;
            const int k1 = (s + 1) << 6;
#pragma unroll
            for (int l = 0; l < 16; l++) {
                int i = tid + l * 256;
                int t = i >> 10, j = i & 1023;
                int row = j >> 3, kc = j & 7;
                uint32_t dst = sbase + stg + t * GT_TILE + row * GT_ROWB + kc * 16;
                CP_ASYNC16(dst, srcs[t] + (size_t)row * K + k1 + kc * 8);
            }
            CP_COMMIT();
        }

        const uint32_t stg = (uint32_t)(s & 1) * GT_STAGE;
        const uint32_t aBaseHi = sbase + stg + 0 * GT_TILE + (uint32_t)warpM * 64 * GT_ROWB + aoff;
        const uint32_t aBaseLo = sbase + stg + 1 * GT_TILE + (uint32_t)warpM * 64 * GT_ROWB + aoff;
        const uint32_t bBaseHi = sbase + stg + 2 * GT_TILE + (uint32_t)warpN * 32 * GT_ROWB + boff;
        const uint32_t bBaseLo = sbase + stg + 3 * GT_TILE + (uint32_t)warpN * 32 * GT_ROWB + boff;

#pragma unroll
        for (int ks = 0; ks < 4; ks++) {
            uint32_t af[4][4], bh_[4][2], bl_[4][2];
#pragma unroll
            for (int fm = 0; fm < 4; fm++)
                ldmx4(af[fm], aBaseHi + (uint32_t)fm * 16 * GT_ROWB + ks * 32);
#pragma unroll
            for (int g = 0; g < 2; g++) {
                uint32_t r[4];
                ldmx4(r, bBaseHi + (uint32_t)g * 16 * GT_ROWB + ks * 32);
                bh_[g * 2][0] = r[0]; bh_[g * 2][1] = r[1];
                bh_[g * 2 + 1][0] = r[2]; bh_[g * 2 + 1][1] = r[3];
            }
#pragma unroll
            for (int fm = 0; fm < 4; fm++)
#pragma unroll
                for (int fn = 0; fn < 4; fn++)
                    mma_bf16(acc[fm][fn], af[fm], bh_[fn]);
#pragma unroll
            for (int g = 0; g < 2; g++) {
                uint32_t r[4];
                ldmx4(r, bBaseLo + (uint32_t)g * 16 * GT_ROWB + ks * 32);
                bl_[g * 2][0] = r[0]; bl_[g * 2][1] = r[1];
                bl_[g * 2 + 1][0] = r[2]; bl_[g * 2 + 1][1] = r[3];
            }
#pragma unroll
            for (int fm = 0; fm < 4; fm++)
#pragma unroll
                for (int fn = 0; fn < 4; fn++)
                    mma_bf16(acc[fm][fn], af[fm], bl_[fn]);
#pragma unroll
            for (int fm = 0; fm < 4; fm++)
                ldmx4(af[fm], aBaseLo + (uint32_t)fm * 16 * GT_ROWB + ks * 32);
#pragma unroll
            for (int fm = 0; fm < 4; fm++)
#pragma unroll
                for (int fn = 0; fn < 4; fn++)
                    mma_bf16(acc[fm][fn], af[fm], bh_[fn]);
        }
    }

    const int qr = lane >> 2;
    const int qc = (lane & 3) * 2;
#pragma unroll
    for (int fm = 0; fm < 4; fm++) {
#pragma unroll
        for (int fn = 0; fn < 4; fn++) {
            float* a = acc[fm][fn];
            int row = m0 + warpM * 64 + fm * 16 + qr;
            int col = n0 + warpN * 32 + fn * 8 + qc;
            float b0 = bias[col], b1 = bias[col + 1];
            float v00 = a[0] + b0, v01 = a[1] + b1;
            float v10 = a[2] + b0, v11 = a[3] + b1;
            if (relu) {
                v00 = fmaxf(v00, 0.f); v01 = fmaxf(v01, 0.f);
                v10 = fmaxf(v10, 0.f); v11 = fmaxf(v11, 0.f);
            }
            size_t i0 = (size_t)row * N + col;
            size_t i1 = (size_t)(row + 8) * N + col;
            if (Cf) {
                *(float2*)&Cf[i0] = make_float2(v00, v01);
                *(float2*)&Cf[i1] = make_float2(v10, v11);
            }
            if (Chi) {
                bf16 h00 = __float2bfloat16(v00), h01 = __float2bfloat16(v01);
                bf16 h10 = __float2bfloat16(v10), h11 = __float2bfloat16(v11);
                *(__nv_bfloat162*)&Chi[i0] = __nv_bfloat162(h00, h01);
                *(__nv_bfloat162*)&Chi[i1] = __nv_bfloat162(h10, h11);
                *(__nv_bfloat162*)&Clo[i0] = __nv_bfloat162(
                    __float2bfloat16(v00 - __bfloat162float(h00)),
                    __float2bfloat16(v01 - __bfloat162float(h01)));
                *(__nv_bfloat162*)&Clo[i1] = __nv_bfloat162(
                    __float2bfloat16(v10 - __bfloat162float(h10)),
                    __float2bfloat16(v11 - __bfloat162float(h11)));
            }
        }
    }
}

// ---------------------------------------------------------------------------
// Fused flash attention, 2-stage cp.async K/V pipeline, ONE barrier per tile.
// ---------------------------------------------------------------------------
#define FROWB 144
#define FTILE (128 * FROWB)                      // 18432
#define FKV_STAGE (4 * FTILE)                    // 73728
#define FLASH_SMEM (10 * FTILE + 8192 + 4096)    // 196608

__global__ __launch_bounds__(256)
void flash_attn_kernel(const bf16* __restrict__ qh, const bf16* __restrict__ ql,
                       const bf16* __restrict__ kh, const bf16* __restrict__ kl,
                       const bf16* __restrict__ vh, const bf16* __restrict__ vl,
                       const float* __restrict__ rel, const int* __restrict__ mask,
                       bf16* __restrict__ ctxh, bf16* __restrict__ ctxl)
{
    extern __shared__ char smem[];
    const int qt = blockIdx.x;
    const int bhid = blockIdx.y;
    const int b = bhid >> 4, h = bhid & 15;
    const int tid = threadIdx.x, wid = tid >> 5, lane = tid & 31;
    const int qr = lane >> 2, qc = (lane & 3) * 2;

    const uint32_t ub = smem_to_u32(smem);
    float* s_rel = (float*)(smem + 10 * FTILE);
    int*   s_msk = (int*)(smem + 10 * FTILE + 8192);

    const bf16* kvsrc[4] = { kh, kl, vh, vl };

    // KV chunk 0 via cp.async into stage 0
    {
        const size_t kg = ((size_t)b * S_) * D_ + h * 64;
#pragma unroll
        for (int l = 0; l < 16; l++) {
            int i = tid + l * 256;
            int t = i >> 10, j = i & 1023;
            int row = j >> 3, kc = j & 7;
            uint32_t dst = ub + 2 * FTILE + t * FTILE + row * FROWB + kc * 16;
            CP_ASYNC16(dst, kvsrc[t] + kg + (size_t)row * D_ + kc * 8);
        }
        CP_COMMIT();
    }

    // Q tiles (hi/lo) + rel column + full mask row (regular loads)
    const size_t qg = ((size_t)b * S_ + qt * 128) * D_ + h * 64;
#pragma unroll
    for (int l = 0; l < 8; l++) {
        int i = tid + l * 256;
        int t = i >> 10, j = i & 1023;
        int row = j >> 3, kc = j & 7;
        const bf16* src = t ? ql : qh;
        *(float4*)(smem + t * FTILE + row * FROWB + kc * 16) =
            *(const float4*)(src + qg + (size_t)row * D_ + kc * 8);
    }
    for (int i = tid; i < 2047; i += 256) s_rel[i] = rel[i * H_ + h];
    for (int i = tid; i < 1024; i += 256) s_msk[i] = mask[b * S_ + i];

    float acc_o[8][4];
#pragma unroll
    for (int a = 0; a < 8; a++) {
        acc_o[a][0] = acc_o[a][1] = acc_o[a][2] = acc_o[a][3] = 0.f;
    }
    float mrow[2] = {-1e30f, -1e30f}, lrow[2] = {0.f, 0.f};

    const uint32_t aoff = (uint32_t)(lane & 15) * FROWB + (uint32_t)(lane >> 4) * 16;
    const uint32_t boff = (uint32_t)(((lane >> 4) * 8) + (lane & 7)) * FROWB
                        + (uint32_t)((lane >> 3) & 1) * 16;
    const uint32_t uQh = ub + 0 * FTILE + (uint32_t)wid * 16 * FROWB + aoff;
    const uint32_t uQl = ub + 1 * FTILE + (uint32_t)wid * 16 * FROWB + aoff;
    const uint32_t vto = (uint32_t)(lane & 15) * FROWB + (uint32_t)(lane >> 4) * 16;

    for (int kt = 0; kt < 8; kt++) {
        CP_WAIT(0);
        __syncthreads();
        if (kt + 1 < 8) {
            const uint32_t stg = (uint32_t)((kt + 1) & 1) * FKV_STAGE;
            const size_t kg = ((size_t)b * S_ + (kt + 1) * 128) * D_ + h * 64;
#pragma unroll
            for (int l = 0; l < 16; l++) {
                int i = tid + l * 256;
                int t = i >> 10, j = i & 1023;
                int row = j >> 3, kc = j & 7;
                uint32_t dst = ub + 2 * FTILE + stg + t * FTILE + row * FROWB + kc * 16;
                CP_ASYNC16(dst, kvsrc[t] + kg + (size_t)row * D_ + kc * 8);
            }
            CP_COMMIT();
        }

        const uint32_t stg = (uint32_t)(kt & 1) * FKV_STAGE;
        const uint32_t uKh = ub + 2 * FTILE + stg + 0 * FTILE + boff;
        const uint32_t uKl = ub + 2 * FTILE + stg + 1 * FTILE + boff;
        const uint32_t uVh = ub + 2 * FTILE + stg + 2 * FTILE + vto;
        const uint32_t uVl = ub + 2 * FTILE + stg + 3 * FTILE + vto;

        // ---- S = Q.K^T (3-term bf16) ----
        float accs[16][4];
#pragma unroll
        for (int f = 0; f < 16; f++) {
            accs[f][0] = accs[f][1] = accs[f][2] = accs[f][3] = 0.f;
        }
#pragma unroll
        for (int ks = 0; ks < 4; ks++) {
            uint32_t aqh[4], aql4[4];
            ldmx4(aqh,  uQh + ks * 32);
            ldmx4(aql4, uQl + ks * 32);
#pragma unroll
            for (int g = 0; g < 8; g++) {
                uint32_t rkh[4], rkl[4];
                ldmx4(rkh, uKh + (uint32_t)g * 16 * FROWB + ks * 32);
                ldmx4(rkl, uKl + (uint32_t)g * 16 * FROWB + ks * 32);
                mma_bf16(accs[2 * g],     aqh,  rkh);
                mma_bf16(accs[2 * g + 1], aqh,  rkh + 2);
                mma_bf16(accs[2 * g],     aqh,  rkl);
                mma_bf16(accs[2 * g + 1], aqh,  rkl + 2);
                mma_bf16(accs[2 * g],     aql4, rkh);
                mma_bf16(accs[2 * g + 1], aql4, rkh + 2);
            }
        }

        // ---- bias + mask + online softmax ----
        const int rb0 = qt * 128 + wid * 16 + qr - kt * 128 + 1023;
        const int mb0 = kt * 128;
        float rmax[2] = {-1e30f, -1e30f};
#pragma unroll
        for (int f = 0; f < 16; f++) {
            int c0 = f * 8 + qc;
            float s0 = accs[f][0] * 0.125f + s_rel[rb0 - c0];
            float s1 = accs[f][1] * 0.125f + s_rel[rb0 - c0 - 1];
            float s2 = accs[f][2] * 0.125f + s_rel[rb0 + 8 - c0];
            float s3 = accs[f][3] * 0.125f + s_rel[rb0 + 8 - c0 - 1];
            if (s_msk[mb0 + c0] == 0)     { s0 = -1e9f; s2 = -1e9f; }
            if (s_msk[mb0 + c0 + 1] == 0) { s1 = -1e9f; s3 = -1e9f; }
            accs[f][0] = s0; accs[f][1] = s1; accs[f][2] = s2; accs[f][3] = s3;
            rmax[0] = fmaxf(rmax[0], fmaxf(s0, s1));
            rmax[1] = fmaxf(rmax[1], fmaxf(s2, s3));
        }
#pragma unroll
        for (int r = 0; r < 2; r++) {
            rmax[r] = fmaxf(rmax[r], __shfl_xor_sync(0xffffffff, rmax[r], 1));
            rmax[r] = fmaxf(rmax[r], __shfl_xor_sync(0xffffffff, rmax[r], 2));
        }
        float alpha[2];
#pragma unroll
        for (int r = 0; r < 2; r++) {
            float mn = fmaxf(mrow[r], rmax[r]);
            alpha[r] = __expf(mrow[r] - mn);
            mrow[r] = mn;
        }
        float rsum[2] = {0.f, 0.f};
#pragma unroll
        for (int f = 0; f < 16; f++) {
            float p0 = __expf(accs[f][0] - mrow[0]);
            float p1 = __expf(accs[f][1] - mrow[0]);
            float p2 = __expf(accs[f][2] - mrow[1]);
            float p3 = __expf(accs[f][3] - mrow[1]);
            accs[f][0] = p0; accs[f][1] = p1; accs[f][2] = p2; accs[f][3] = p3;
            rsum[0] += p0 + p1;
            rsum[1] += p2 + p3;
        }
#pragma unroll
        for (int r = 0; r < 2; r++) {
            rsum[r] += __shfl_xor_sync(0xffffffff, rsum[r], 1);
            rsum[r] += __shfl_xor_sync(0xffffffff, rsum[r], 2);
            lrow[r] = lrow[r] * alpha[r] + rsum[r];
        }
#pragma unroll
        for (int a = 0; a < 8; a++) {
            acc_o[a][0] *= alpha[0]; acc_o[a][1] *= alpha[0];
            acc_o[a][2] *= alpha[1]; acc_o[a][3] *= alpha[1];
        }

        // ---- O += P.V (3-term: Ph*Vh + Ph*Vl + Pl*Vh) ----
#pragma unroll
        for (int kc = 0; kc < 8; kc++) {
            const int f0 = 2 * kc, f1 = 2 * kc + 1;
            uint32_t aPh[4], aPl[4];
            aPh[0] = packbf(accs[f0][0], accs[f0][1]);
            aPh[1] = packbf(accs[f0][2], accs[f0][3]);
            aPh[2] = packbf(accs[f1][0], accs[f1][1]);
            aPh[3] = packbf(accs[f1][2], accs[f1][3]);
            aPl[0] = packbf(bfres(accs[f0][0]), bfres(accs[f0][1]));
            aPl[1] = packbf(bfres(accs[f0][2]), bfres(accs[f0][3]));
            aPl[2] = packbf(bfres(accs[f1][0]), bfres(accs[f1][1]));
            aPl[3] = packbf(bfres(accs[f1][2]), bfres(accs[f1][3]));
#pragma unroll
            for (int jg = 0; jg < 4; jg++) {
                uint32_t v4h[4], v4l[4];
                uint32_t off = (uint32_t)(kc * 16) * FROWB + jg * 32;
                ldmx4t(v4h, uVh + off);
                ldmx4t(v4l, uVl + off);
                mma_bf16(acc_o[2 * jg],     aPh, v4h);
                mma_bf16(acc_o[2 * jg + 1], aPh, v4h + 2);
                mma_bf16(acc_o[2 * jg],     aPh, v4l);
                mma_bf16(acc_o[2 * jg + 1], aPh, v4l + 2);
                mma_bf16(acc_o[2 * jg],     aPl, v4h);
                mma_bf16(acc_o[2 * jg + 1], aPl, v4h + 2);
            }
        }
    }

    // ---- epilogue ----
    const float inv0 = 1.f / lrow[0], inv1 = 1.f / lrow[1];
    const int row0 = qt * 128 + wid * 16 + qr;
#pragma unroll
    for (int a = 0; a < 8; a++) {
        int col = a * 8 + qc;
        size_t i0 = ((size_t)b * S_ + row0) * D_ + h * 64 + col;
        size_t i1 = ((size_t)b * S_ + row0 + 8) * D_ + h * 64 + col;
        float v00 = acc_o[a][0] * inv0, v01 = acc_o[a][1] * inv0;
        float v10 = acc_o[a][2] * inv1, v11 = acc_o[a][3] * inv1;
        bf16 h00 = __float2bfloat16(v00), h01 = __float2bfloat16(v01);
        bf16 h10 = __float2bfloat16(v10), h11 = __float2bfloat16(v11);
        *(__nv_bfloat162*)&ctxh[i0] = __nv_bfloat162(h00, h01);
        *(__nv_bfloat162*)&ctxh[i1] = __nv_bfloat162(h10, h11);
        *(__nv_bfloat162*)&ctxl[i0] = __nv_bfloat162(
            __float2bfloat16(v00 - __bfloat162float(h00)),
            __float2bfloat16(v01 - __bfloat162float(h01)));
        *(__nv_bfloat162*)&ctxl[i1] = __nv_bfloat162(
            __float2bfloat16(v10 - __bfloat162float(h10)),
            __float2bfloat16(v11 - __bfloat162float(h11)));
    }
}

// ---------------------------------------------------------------------------
// fp32 -> bf16 hi/lo split (elementwise, vectorized)
// ---------------------------------------------------------------------------
__global__ __launch_bounds__(256)
void split_kernel(const float* __restrict__ X, bf16* __restrict__ Xh,
                  bf16* __restrict__ Xl, size_t n4)
{
    size_t i = (size_t)blockIdx.x * 256 + threadIdx.x;
    if (i >= n4) return;
    float4 v = ((const float4*)X)[i];
    bf16 h0 = __float2bfloat16(v.x), h1 = __float2bfloat16(v.y);
    bf16 h2 = __float2bfloat16(v.z), h3 = __float2bfloat16(v.w);
    size_t o = i * 4;
    Xh[o] = h0; Xh[o+1] = h1; Xh[o+2] = h2; Xh[o+3] = h3;
    Xl[o]   = __float2bfloat16(v.x - __bfloat162float(h0));
    Xl[o+1] = __float2bfloat16(v.y - __bfloat162float(h1));
    Xl[o+2] = __float2bfloat16(v.z - __bfloat162float(h2));
    Xl[o+3] = __float2bfloat16(v.w - __bfloat162float(h3));
}

// ---------------------------------------------------------------------------
// All 6 weight transposes+splits in ONE launch. Flat grid decode:
//   [0,4096):   wq/wk/wv/wo (1024 blocks each, 32x32 grid over [K=1024,N=1024])
//   [4096,8192): w1 (grid 128x32 over [K=1024,N=4096])
//   [8192,12288): w2 (grid 32x128 over [K=4096,N=1024])
// ---------------------------------------------------------------------------
__global__ __launch_bounds__(256)
void tsplit_all_kernel(const float* __restrict__ wq, const float* __restrict__ wk,
                       const float* __restrict__ wv, const float* __restrict__ wo,
                       const float* __restrict__ w1, const float* __restrict__ w2,
                       bf16* __restrict__ qTh, bf16* __restrict__ qTl,
                       bf16* __restrict__ kTh, bf16* __restrict__ kTl,
                       bf16* __restrict__ vTh, bf16* __restrict__ vTl,
                       bf16* __restrict__ oTh, bf16* __restrict__ oTl,
                       bf16* __restrict__ w1Th, bf16* __restrict__ w1Tl,
                       bf16* __restrict__ w2Th, bf16* __restrict__ w2Tl)
{
    const int idx = blockIdx.x;
    const float* W; bf16 *Th, *Tl;
    int K, N, bx, by;
    if (idx < 4096) {
        const int seg = idx >> 10, r = idx & 1023;
        bx = r & 31; by = r >> 5; K = D_; N = D_;
        W  = (seg == 0) ? wq  : (seg == 1) ? wk  : (seg == 2) ? wv  : wo;
        Th = (seg == 0) ? qTh : (seg == 1) ? kTh : (seg == 2) ? vTh : oTh;
        Tl = (seg == 0) ? qTl : (seg == 1) ? kTl : (seg == 2) ? vTl : oTl;
    } else if (idx < 8192) {
        const int r = idx - 4096;
        bx = r & 127; by = r >> 7; K = D_; N = DFF_;
        W = w1; Th = w1Th; Tl = w1Tl;
    } else {
        const int r = idx - 8192;
        bx = r & 31; by = r >> 5; K = DFF_; N = D_;
        W = w2; Th = w2Th; Tl = w2Tl;
    }

    __shared__ float t[32][33];
    const int k0 = by * 32, n0 = bx * 32;
    const int tx = threadIdx.x & 31, ty = threadIdx.x >> 5;
    for (int r = ty; r < 32; r += 8)
        t[r][tx] = W[(size_t)(k0 + r) * N + n0 + tx];
    __syncthreads();
    for (int r = ty; r < 32; r += 8) {
        float v = t[tx][r];
        bf16 h = __float2bfloat16(v);
        size_t oi = (size_t)(n0 + r) * K + k0 + tx;
        Th[oi] = h;
        Tl[oi] = __float2bfloat16(v - __bfloat162float(h));
    }
}

// ---------------------------------------------------------------------------
// out = LayerNorm(x + y) * g + b; optionally also emit bf16 hi/lo split
// ---------------------------------------------------------------------------
__global__ __launch_bounds__(256)
void add_ln_kernel(const float* __restrict__ x, const float* __restrict__ y,
                   const float* __restrict__ g, const float* __restrict__ b,
                   float* __restrict__ out, bf16* __restrict__ oh,
                   bf16* __restrict__ ol)
{
    __shared__ float red[256];
    const size_t base = (size_t)blockIdx.x * D_;
    const int tid = threadIdx.x;

    float v[4];
    float s = 0.f;
#pragma unroll
    for (int l = 0; l < 4; l++) {
        int i = tid + l * 256;
        v[l] = x[base + i] + y[base + i];
        s += v[l];
    }
    red[tid] = s; __syncthreads();
    for (int st = 128; st > 0; st >>= 1) {
        if (tid < st) red[tid] += red[tid + st];
        __syncthreads();
    }
    float mean = red[0] * (1.0f / D_); __syncthreads();

    float sq = 0.f;
#pragma unroll
    for (int l = 0; l < 4; l++) { float d = v[l] - mean; sq += d * d; }
    red[tid] = sq; __syncthreads();
    for (int st = 128; st > 0; st >>= 1) {
        if (tid < st) red[tid] += red[tid + st];
        __syncthreads();
    }
    float rstd = rsqrtf(red[0] * (1.0f / D_) + 1e-5f);

#pragma unroll
    for (int l = 0; l < 4; l++) {
        int i = tid + l * 256;
        float o = (v[l] - mean) * rstd * g[i] + b[i];
        out[base + i] = o;
        if (oh) {
            bf16 hh = __float2bfloat16(o);
            oh[base + i] = hh;
            ol[base + i] = __float2bfloat16(o - __bfloat162float(hh));
        }
    }
}

// ---------------------------------------------------------------------------
// Launch
// ---------------------------------------------------------------------------
extern "C" void kernel_launch(void* const* d_in, const int* in_sizes, int n_in,
                              void* d_out, int out_size)
{
    const float* x    = (const float*)d_in[0];
    const float* wq   = (const float*)d_in[1];
    const float* bq   = (const float*)d_in[2];
    const float* wk   = (const float*)d_in[3];
    const float* bk   = (const float*)d_in[4];
    const float* wv   = (const float*)d_in[5];
    const float* bv   = (const float*)d_in[6];
    const float* wo   = (const float*)d_in[7];
    const float* bo   = (const float*)d_in[8];
    const float* rel  = (const float*)d_in[9];
    const float* ln1g = (const float*)d_in[10];
    const float* ln1b = (const float*)d_in[11];
    const float* w1   = (const float*)d_in[12];
    const float* b1   = (const float*)d_in[13];
    const float* w2   = (const float*)d_in[14];
    const float* b2   = (const float*)d_in[15];
    const float* ln2g = (const float*)d_in[16];
    const float* ln2b = (const float*)d_in[17];
    const int*   mask = (const int*)  d_in[18];
    float* out = (float*)d_out;

    float *pt1, *px1;
    bf16 *pxh, *pxl, *pqh, *pql, *pkh, *pkl, *pvh, *pvl;
    bf16 *pctxh, *pctxl, *px1h, *px1l, *pffh, *pffl;
    bf16 *wqTh, *wqTl, *wkTh, *wkTl, *wvTh, *wvTl, *woTh, *woTl;
    bf16 *w1Th, *w1Tl, *w2Th, *w2Tl;
    cudaGetSymbolAddress((void**)&pt1,  g_t1);
    cudaGetSymbolAddress((void**)&px1,  g_x1);
    cudaGetSymbolAddress((void**)&pxh,  g_xh);
    cudaGetSymbolAddress((void**)&pxl,  g_xl);
    cudaGetSymbolAddress((void**)&pqh,  g_qh);
    cudaGetSymbolAddress((void**)&pql,  g_ql);
    cudaGetSymbolAddress((void**)&pkh,  g_kh);
    cudaGetSymbolAddress((void**)&pkl,  g_kl);
    cudaGetSymbolAddress((void**)&pvh,  g_vh);
    cudaGetSymbolAddress((void**)&pvl,  g_vl);
    cudaGetSymbolAddress((void**)&pctxh, g_ctxh);
    cudaGetSymbolAddress((void**)&pctxl, g_ctxl);
    cudaGetSymbolAddress((void**)&px1h, g_x1h);
    cudaGetSymbolAddress((void**)&px1l, g_x1l);
    cudaGetSymbolAddress((void**)&pffh, g_ffh);
    cudaGetSymbolAddress((void**)&pffl, g_ffl);
    cudaGetSymbolAddress((void**)&wqTh, g_wqTh);
    cudaGetSymbolAddress((void**)&wqTl, g_wqTl);
    cudaGetSymbolAddress((void**)&wkTh, g_wkTh);
    cudaGetSymbolAddress((void**)&wkTl, g_wkTl);
    cudaGetSymbolAddress((void**)&wvTh, g_wvTh);
    cudaGetSymbolAddress((void**)&wvTl, g_wvTl);
    cudaGetSymbolAddress((void**)&woTh, g_woTh);
    cudaGetSymbolAddress((void**)&woTl, g_woTl);
    cudaGetSymbolAddress((void**)&w1Th, g_w1Th);
    cudaGetSymbolAddress((void**)&w1Tl, g_w1Tl);
    cudaGetSymbolAddress((void**)&w2Th, g_w2Th);
    cudaGetSymbolAddress((void**)&w2Tl, g_w2Tl);

    cudaFuncSetAttribute(gemm_tc_kernel,
                         cudaFuncAttributeMaxDynamicSharedMemorySize, GEMM_SMEM);
    cudaFuncSetAttribute(flash_attn_kernel,
                         cudaFuncAttributeMaxDynamicSharedMemorySize, FLASH_SMEM);

    dim3 blk(256);

    // 1: input split
    split_kernel<<<(NR_ * D_ / 4 + 255) / 256, blk>>>(x, pxh, pxl, (size_t)NR_ * D_ / 4);
    // 2: all weight transposes+splits
    tsplit_all_kernel<<<12288, blk>>>(wq, wk, wv, wo, w1, w2,
                                      wqTh, wqTl, wkTh, wkTl, wvTh, wvTl,
                                      woTh, woTl, w1Th, w1Tl, w2Th, w2Tl);

    // 3-5: QKV projections -> bf16 hi/lo outputs
    dim3 gProj(D_ / 128, NR_ / 128);
    gemm_tc_kernel<<<gProj, blk, GEMM_SMEM>>>(pxh, pxl, wqTh, wqTl, bq, nullptr,
                                              pqh, pql, NR_, D_, D_, 0);
    gemm_tc_kernel<<<gProj, blk, GEMM_SMEM>>>(pxh, pxl, wkTh, wkTl, bk, nullptr,
                                              pkh, pkl, NR_, D_, D_, 0);
    gemm_tc_kernel<<<gProj, blk, GEMM_SMEM>>>(pxh, pxl, wvTh, wvTl, bv, nullptr,
                                              pvh, pvl, NR_, D_, D_, 0);

    // 6: fused flash attention  (ncu -s 5 -c 1 captures this launch)
    flash_attn_kernel<<<dim3(S_ / 128, BH_), blk, FLASH_SMEM>>>(
        pqh, pql, pkh, pkl, pvh, pvl, rel, mask, pctxh, pctxl);

    // 7: O projection
    gemm_tc_kernel<<<gProj, blk, GEMM_SMEM>>>(pctxh, pctxl, woTh, woTl, bo, pt1,
                                              nullptr, nullptr, NR_, D_, D_, 0);

    // 8: x1 = LN(x + attn_out), with split
    add_ln_kernel<<<NR_, blk>>>(x, pt1, ln1g, ln1b, px1, px1h, px1l);

    // 9-10: FFN
    dim3 gF1(DFF_ / 128, NR_ / 128);
    gemm_tc_kernel<<<gF1, blk, GEMM_SMEM>>>(px1h, px1l, w1Th, w1Tl, b1, nullptr,
                                            pffh, pffl, NR_, DFF_, D_, 1);
    dim3 gF2(D_ / 128, NR_ / 128);
    gemm_tc_kernel<<<gF2, blk, GEMM_SMEM>>>(pffh, pffl, w2Th, w2Tl, b2, pt1,
                                            nullptr, nullptr, NR_, D_, DFF_, 0);

    // 11: out = LN(x1 + ff)
    add_ln_kernel<<<NR_, blk>>>(px1, pt1, ln2g, ln2b, out, nullptr, nullptr);
}

// round 9
// speedup vs baseline: 3.7516x; 1.0298x over previous
#include <cuda_runtime.h>
#include <cuda_bf16.h>
#include <math.h>
#include <stdint.h>

// Problem constants
#define B_   4
#define S_   1024
#define D_   1024
#define H_   16
#define DK_  64
#define DFF_ 4096
#define NR_  4096          // B*S rows
#define BH_  64            // B*H

typedef __nv_bfloat16 bf16;

// ---------------------------------------------------------------------------
// Scratch (device globals; .bss — no allocations)
// ---------------------------------------------------------------------------
__device__ float g_t1 [(size_t)NR_ * D_];
__device__ float g_x1 [(size_t)NR_ * D_];

__device__ bf16 g_xh  [(size_t)NR_ * D_];
__device__ bf16 g_xl  [(size_t)NR_ * D_];
__device__ bf16 g_qh  [(size_t)NR_ * D_];
__device__ bf16 g_ql  [(size_t)NR_ * D_];
__device__ bf16 g_kh  [(size_t)NR_ * D_];
__device__ bf16 g_kl  [(size_t)NR_ * D_];
__device__ bf16 g_vh  [(size_t)NR_ * D_];
__device__ bf16 g_vl  [(size_t)NR_ * D_];
__device__ bf16 g_ctxh[(size_t)NR_ * D_];
__device__ bf16 g_ctxl[(size_t)NR_ * D_];
__device__ bf16 g_x1h [(size_t)NR_ * D_];
__device__ bf16 g_x1l [(size_t)NR_ * D_];
__device__ bf16 g_ffh [(size_t)NR_ * DFF_];
__device__ bf16 g_ffl [(size_t)NR_ * DFF_];
// transposed+split weights: [N,K] bf16
__device__ bf16 g_wqTh[(size_t)D_ * D_];
__device__ bf16 g_wqTl[(size_t)D_ * D_];
__device__ bf16 g_wkTh[(size_t)D_ * D_];
__device__ bf16 g_wkTl[(size_t)D_ * D_];
__device__ bf16 g_wvTh[(size_t)D_ * D_];
__device__ bf16 g_wvTl[(size_t)D_ * D_];
__device__ bf16 g_woTh[(size_t)D_ * D_];
__device__ bf16 g_woTl[(size_t)D_ * D_];
__device__ bf16 g_w1Th[(size_t)DFF_ * D_];
__device__ bf16 g_w1Tl[(size_t)DFF_ * D_];
__device__ bf16 g_w2Th[(size_t)D_ * DFF_];
__device__ bf16 g_w2Tl[(size_t)D_ * DFF_];

// ---------------------------------------------------------------------------
// Warp-MMA / cp.async primitives (portable to plain compute_103)
// ---------------------------------------------------------------------------
__device__ __forceinline__ uint32_t smem_to_u32(const void* p) {
    uint32_t a;
    asm("{ .reg .u64 t; cvta.to.shared.u64 t, %1; cvt.u32.u64 %0, t; }"
        : "=r"(a) : "l"(p));
    return a;
}

__device__ __forceinline__ void ldmx4(uint32_t* r, uint32_t addr) {
    asm volatile("ldmatrix.sync.aligned.m8n8.x4.shared.b16 {%0,%1,%2,%3}, [%4];"
                 : "=r"(r[0]), "=r"(r[1]), "=r"(r[2]), "=r"(r[3]) : "r"(addr));
}

__device__ __forceinline__ void ldmx4t(uint32_t* r, uint32_t addr) {
    asm volatile("ldmatrix.sync.aligned.m8n8.x4.trans.shared.b16 {%0,%1,%2,%3}, [%4];"
                 : "=r"(r[0]), "=r"(r[1]), "=r"(r[2]), "=r"(r[3]) : "r"(addr));
}

__device__ __forceinline__ void mma_bf16(float* c, const uint32_t* a,
                                         const uint32_t* b) {
    asm volatile(
        "mma.sync.aligned.m16n8k16.row.col.f32.bf16.bf16.f32 "
        "{%0,%1,%2,%3}, {%4,%5,%6,%7}, {%8,%9}, {%0,%1,%2,%3};"
        : "+f"(c[0]), "+f"(c[1]), "+f"(c[2]), "+f"(c[3])
        : "r"(a[0]), "r"(a[1]), "r"(a[2]), "r"(a[3]), "r"(b[0]), "r"(b[1]));
}

__device__ __forceinline__ uint32_t packbf(float lo, float hi) {
    uint32_t r;
    asm("cvt.rn.bf16x2.f32 %0, %1, %2;" : "=r"(r) : "f"(hi), "f"(lo));
    return r;
}
__device__ __forceinline__ float bfres(float x) {
    return x - __bfloat162float(__float2bfloat16(x));
}

#define CP_ASYNC16(dst, src) \
    asm volatile("cp.async.cg.shared.global [%0], [%1], 16;" \
                 :: "r"(dst), "l"(src) : "memory")
#define CP_COMMIT() asm volatile("cp.async.commit_group;" ::: "memory")
#define CP_WAIT(n)  asm volatile("cp.async.wait_group %0;" :: "n"(n) : "memory")

// ---------------------------------------------------------------------------
// Tensor-core GEMM (mma.sync): C[M,N] = A[M,K] @ B^T + bias, 3-term bf16 split
// K-chunk 32, 2-stage cp.async pipeline, 80B rows -> 80KB smem/CTA so TWO
// CTAs co-reside per SM (latency hiding across CTAs). One barrier per chunk.
// ---------------------------------------------------------------------------
#define GT_ROWB   80                     // 32 bf16 = 64B data + 16B pad
#define GT_TILE   (128 * GT_ROWB)        // 10240
#define GT_STAGE  (4 * GT_TILE)          // 40960
#define GEMM_SMEM (2 * GT_STAGE)         // 81920

__global__ __launch_bounds__(256, 2)
void gemm_tc_kernel(const bf16* __restrict__ Ahi, const bf16* __restrict__ Alo,
                    const bf16* __restrict__ Bhi, const bf16* __restrict__ Blo,
                    const float* __restrict__ bias,
                    float* __restrict__ Cf,
                    bf16* __restrict__ Chi, bf16* __restrict__ Clo,
                    int M, int N, int K, int relu)
{
    extern __shared__ char smem[];
    const uint32_t sbase = smem_to_u32(smem);

    const int tid  = threadIdx.x;
    const int wid  = tid >> 5;
    const int lane = tid & 31;
    const int warpM = wid >> 2;
    const int warpN = wid & 3;
    const int m0 = blockIdx.y * 128;
    const int n0 = blockIdx.x * 128;

    const bf16* srcs[4] = { Ahi + (size_t)m0 * K, Alo + (size_t)m0 * K,
                            Bhi + (size_t)n0 * K, Blo + (size_t)n0 * K };

    float acc[4][4][4];
#pragma unroll
    for (int i = 0; i < 4; i++)
#pragma unroll
        for (int j = 0; j < 4; j++)
#pragma unroll
            for (int r = 0; r < 4; r++) acc[i][j][r] = 0.f;

    const uint32_t aoff = (uint32_t)(lane & 15) * GT_ROWB + (uint32_t)(lane >> 4) * 16;
    const uint32_t boff = (uint32_t)(((lane >> 4) * 8) + (lane & 7)) * GT_ROWB
                        + (uint32_t)((lane >> 3) & 1) * 16;

    const int nchunk = K >> 5;

    // prologue: chunk 0 -> stage 0   (8 x 16B per thread: 4 tiles x 512 chunks)
#pragma unroll
    for (int l = 0; l < 8; l++) {
        int i = tid + l * 256;
        int t = i >> 9, j = i & 511;
        int row = j >> 2, kc = j & 3;
        uint32_t dst = sbase + t * GT_TILE + row * GT_ROWB + kc * 16;
        CP_ASYNC16(dst, srcs[t] + (size_t)row * K + kc * 8);
    }
    CP_COMMIT();

    for (int s = 0; s < nchunk; s++) {
        CP_WAIT(0);
        __syncthreads();
        if (s + 1 < nchunk) {
            const uint32_t stg = (uint32_t)((s + 1) & 1) * GT_STAGE;
            const int k1 = (s + 1) << 5;
#pragma unroll
            for (int l = 0; l < 8; l++) {
                int i = tid + l * 256;
                int t = i >> 9, j = i & 511;
                int row = j >> 2, kc = j & 3;
                uint32_t dst = sbase + stg + t * GT_TILE + row * GT_ROWB + kc * 16;
                CP_ASYNC16(dst, srcs[t] + (size_t)row * K + k1 + kc * 8);
            }
            CP_COMMIT();
        }

        const uint32_t stg = (uint32_t)(s & 1) * GT_STAGE;
        const uint32_t aBaseHi = sbase + stg + 0 * GT_TILE + (uint32_t)warpM * 64 * GT_ROWB + aoff;
        const uint32_t aBaseLo = sbase + stg + 1 * GT_TILE + (uint32_t)warpM * 64 * GT_ROWB + aoff;
        const uint32_t bBaseHi = sbase + stg + 2 * GT_TILE + (uint32_t)warpN * 32 * GT_ROWB + boff;
        const uint32_t bBaseLo = sbase + stg + 3 * GT_TILE + (uint32_t)warpN * 32 * GT_ROWB + boff;

#pragma unroll
        for (int ks = 0; ks < 2; ks++) {
            uint32_t af[4][4], bh_[4][2], bl_[4][2];
#pragma unroll
            for (int fm = 0; fm < 4; fm++)
                ldmx4(af[fm], aBaseHi + (uint32_t)fm * 16 * GT_ROWB + ks * 32);
#pragma unroll
            for (int g = 0; g < 2; g++) {
                uint32_t r[4];
                ldmx4(r, bBaseHi + (uint32_t)g * 16 * GT_ROWB + ks * 32);
                bh_[g * 2][0] = r[0]; bh_[g * 2][1] = r[1];
                bh_[g * 2 + 1][0] = r[2]; bh_[g * 2 + 1][1] = r[3];
            }
#pragma unroll
            for (int fm = 0; fm < 4; fm++)
#pragma unroll
                for (int fn = 0; fn < 4; fn++)
                    mma_bf16(acc[fm][fn], af[fm], bh_[fn]);
#pragma unroll
            for (int g = 0; g < 2; g++) {
                uint32_t r[4];
                ldmx4(r, bBaseLo + (uint32_t)g * 16 * GT_ROWB + ks * 32);
                bl_[g * 2][0] = r[0]; bl_[g * 2][1] = r[1];
                bl_[g * 2 + 1][0] = r[2]; bl_[g * 2 + 1][1] = r[3];
            }
#pragma unroll
            for (int fm = 0; fm < 4; fm++)
#pragma unroll
                for (int fn = 0; fn < 4; fn++)
                    mma_bf16(acc[fm][fn], af[fm], bl_[fn]);
#pragma unroll
            for (int fm = 0; fm < 4; fm++)
                ldmx4(af[fm], aBaseLo + (uint32_t)fm * 16 * GT_ROWB + ks * 32);
#pragma unroll
            for (int fm = 0; fm < 4; fm++)
#pragma unroll
                for (int fn = 0; fn < 4; fn++)
                    mma_bf16(acc[fm][fn], af[fm], bh_[fn]);
        }
    }

    const int qr = lane >> 2;
    const int qc = (lane & 3) * 2;
#pragma unroll
    for (int fm = 0; fm < 4; fm++) {
#pragma unroll
        for (int fn = 0; fn < 4; fn++) {
            float* a = acc[fm][fn];
            int row = m0 + warpM * 64 + fm * 16 + qr;
            int col = n0 + warpN * 32 + fn * 8 + qc;
            float b0 = bias[col], b1 = bias[col + 1];
            float v00 = a[0] + b0, v01 = a[1] + b1;
            float v10 = a[2] + b0, v11 = a[3] + b1;
            if (relu) {
                v00 = fmaxf(v00, 0.f); v01 = fmaxf(v01, 0.f);
                v10 = fmaxf(v10, 0.f); v11 = fmaxf(v11, 0.f);
            }
            size_t i0 = (size_t)row * N + col;
            size_t i1 = (size_t)(row + 8) * N + col;
            if (Cf) {
                *(float2*)&Cf[i0] = make_float2(v00, v01);
                *(float2*)&Cf[i1] = make_float2(v10, v11);
            }
            if (Chi) {
                bf16 h00 = __float2bfloat16(v00), h01 = __float2bfloat16(v01);
                bf16 h10 = __float2bfloat16(v10), h11 = __float2bfloat16(v11);
                *(__nv_bfloat162*)&Chi[i0] = __nv_bfloat162(h00, h01);
                *(__nv_bfloat162*)&Chi[i1] = __nv_bfloat162(h10, h11);
                *(__nv_bfloat162*)&Clo[i0] = __nv_bfloat162(
                    __float2bfloat16(v00 - __bfloat162float(h00)),
                    __float2bfloat16(v01 - __bfloat162float(h01)));
                *(__nv_bfloat162*)&Clo[i1] = __nv_bfloat162(
                    __float2bfloat16(v10 - __bfloat162float(h10)),
                    __float2bfloat16(v11 - __bfloat162float(h11)));
            }
        }
    }
}

// ---------------------------------------------------------------------------
// Fused flash attention, 2-stage cp.async K/V pipeline, ONE barrier per tile.
// ---------------------------------------------------------------------------
#define FROWB 144
#define FTILE (128 * FROWB)                      // 18432
#define FKV_STAGE (4 * FTILE)                    // 73728
#define FLASH_SMEM (10 * FTILE + 8192 + 4096)    // 196608

__global__ __launch_bounds__(256)
void flash_attn_kernel(const bf16* __restrict__ qh, const bf16* __restrict__ ql,
                       const bf16* __restrict__ kh, const bf16* __restrict__ kl,
                       const bf16* __restrict__ vh, const bf16* __restrict__ vl,
                       const float* __restrict__ rel, const int* __restrict__ mask,
                       bf16* __restrict__ ctxh, bf16* __restrict__ ctxl)
{
    extern __shared__ char smem[];
    const int qt = blockIdx.x;
    const int bhid = blockIdx.y;
    const int b = bhid >> 4, h = bhid & 15;
    const int tid = threadIdx.x, wid = tid >> 5, lane = tid & 31;
    const int qr = lane >> 2, qc = (lane & 3) * 2;

    const uint32_t ub = smem_to_u32(smem);
    float* s_rel = (float*)(smem + 10 * FTILE);
    int*   s_msk = (int*)(smem + 10 * FTILE + 8192);

    const bf16* kvsrc[4] = { kh, kl, vh, vl };

    // KV chunk 0 via cp.async into stage 0
    {
        const size_t kg = ((size_t)b * S_) * D_ + h * 64;
#pragma unroll
        for (int l = 0; l < 16; l++) {
            int i = tid + l * 256;
            int t = i >> 10, j = i & 1023;
            int row = j >> 3, kc = j & 7;
            uint32_t dst = ub + 2 * FTILE + t * FTILE + row * FROWB + kc * 16;
            CP_ASYNC16(dst, kvsrc[t] + kg + (size_t)row * D_ + kc * 8);
        }
        CP_COMMIT();
    }

    // Q tiles (hi/lo) + rel column + full mask row (regular loads)
    const size_t qg = ((size_t)b * S_ + qt * 128) * D_ + h * 64;
#pragma unroll
    for (int l = 0; l < 8; l++) {
        int i = tid + l * 256;
        int t = i >> 10, j = i & 1023;
        int row = j >> 3, kc = j & 7;
        const bf16* src = t ? ql : qh;
        *(float4*)(smem + t * FTILE + row * FROWB + kc * 16) =
            *(const float4*)(src + qg + (size_t)row * D_ + kc * 8);
    }
    for (int i = tid; i < 2047; i += 256) s_rel[i] = rel[i * H_ + h];
    for (int i = tid; i < 1024; i += 256) s_msk[i] = mask[b * S_ + i];

    float acc_o[8][4];
#pragma unroll
    for (int a = 0; a < 8; a++) {
        acc_o[a][0] = acc_o[a][1] = acc_o[a][2] = acc_o[a][3] = 0.f;
    }
    float mrow[2] = {-1e30f, -1e30f}, lrow[2] = {0.f, 0.f};

    const uint32_t aoff = (uint32_t)(lane & 15) * FROWB + (uint32_t)(lane >> 4) * 16;
    const uint32_t boff = (uint32_t)(((lane >> 4) * 8) + (lane & 7)) * FROWB
                        + (uint32_t)((lane >> 3) & 1) * 16;
    const uint32_t uQh = ub + 0 * FTILE + (uint32_t)wid * 16 * FROWB + aoff;
    const uint32_t uQl = ub + 1 * FTILE + (uint32_t)wid * 16 * FROWB + aoff;
    const uint32_t vto = (uint32_t)(lane & 15) * FROWB + (uint32_t)(lane >> 4) * 16;

    for (int kt = 0; kt < 8; kt++) {
        CP_WAIT(0);
        __syncthreads();
        if (kt + 1 < 8) {
            const uint32_t stg = (uint32_t)((kt + 1) & 1) * FKV_STAGE;
            const size_t kg = ((size_t)b * S_ + (kt + 1) * 128) * D_ + h * 64;
#pragma unroll
            for (int l = 0; l < 16; l++) {
                int i = tid + l * 256;
                int t = i >> 10, j = i & 1023;
                int row = j >> 3, kc = j & 7;
                uint32_t dst = ub + 2 * FTILE + stg + t * FTILE + row * FROWB + kc * 16;
                CP_ASYNC16(dst, kvsrc[t] + kg + (size_t)row * D_ + kc * 8);
            }
            CP_COMMIT();
        }

        const uint32_t stg = (uint32_t)(kt & 1) * FKV_STAGE;
        const uint32_t uKh = ub + 2 * FTILE + stg + 0 * FTILE + boff;
        const uint32_t uKl = ub + 2 * FTILE + stg + 1 * FTILE + boff;
        const uint32_t uVh = ub + 2 * FTILE + stg + 2 * FTILE + vto;
        const uint32_t uVl = ub + 2 * FTILE + stg + 3 * FTILE + vto;

        // ---- S = Q.K^T (3-term bf16) ----
        float accs[16][4];
#pragma unroll
        for (int f = 0; f < 16; f++) {
            accs[f][0] = accs[f][1] = accs[f][2] = accs[f][3] = 0.f;
        }
#pragma unroll
        for (int ks = 0; ks < 4; ks++) {
            uint32_t aqh[4], aql4[4];
            ldmx4(aqh,  uQh + ks * 32);
            ldmx4(aql4, uQl + ks * 32);
#pragma unroll
            for (int g = 0; g < 8; g++) {
                uint32_t rkh[4], rkl[4];
                ldmx4(rkh, uKh + (uint32_t)g * 16 * FROWB + ks * 32);
                ldmx4(rkl, uKl + (uint32_t)g * 16 * FROWB + ks * 32);
                mma_bf16(accs[2 * g],     aqh,  rkh);
                mma_bf16(accs[2 * g + 1], aqh,  rkh + 2);
                mma_bf16(accs[2 * g],     aqh,  rkl);
                mma_bf16(accs[2 * g + 1], aqh,  rkl + 2);
                mma_bf16(accs[2 * g],     aql4, rkh);
                mma_bf16(accs[2 * g + 1], aql4, rkh + 2);
            }
        }

        // ---- bias + mask + online softmax ----
        const int rb0 = qt * 128 + wid * 16 + qr - kt * 128 + 1023;
        const int mb0 = kt * 128;
        float rmax[2] = {-1e30f, -1e30f};
#pragma unroll
        for (int f = 0; f < 16; f++) {
            int c0 = f * 8 + qc;
            float s0 = accs[f][0] * 0.125f + s_rel[rb0 - c0];
            float s1 = accs[f][1] * 0.125f + s_rel[rb0 - c0 - 1];
            float s2 = accs[f][2] * 0.125f + s_rel[rb0 + 8 - c0];
            float s3 = accs[f][3] * 0.125f + s_rel[rb0 + 8 - c0 - 1];
            if (s_msk[mb0 + c0] == 0)     { s0 = -1e9f; s2 = -1e9f; }
            if (s_msk[mb0 + c0 + 1] == 0) { s1 = -1e9f; s3 = -1e9f; }
            accs[f][0] = s0; accs[f][1] = s1; accs[f][2] = s2; accs[f][3] = s3;
            rmax[0] = fmaxf(rmax[0], fmaxf(s0, s1));
            rmax[1] = fmaxf(rmax[1], fmaxf(s2, s3));
        }
#pragma unroll
        for (int r = 0; r < 2; r++) {
            rmax[r] = fmaxf(rmax[r], __shfl_xor_sync(0xffffffff, rmax[r], 1));
            rmax[r] = fmaxf(rmax[r], __shfl_xor_sync(0xffffffff, rmax[r], 2));
        }
        float alpha[2];
#pragma unroll
        for (int r = 0; r < 2; r++) {
            float mn = fmaxf(mrow[r], rmax[r]);
            alpha[r] = __expf(mrow[r] - mn);
            mrow[r] = mn;
        }
        float rsum[2] = {0.f, 0.f};
#pragma unroll
        for (int f = 0; f < 16; f++) {
            float p0 = __expf(accs[f][0] - mrow[0]);
            float p1 = __expf(accs[f][1] - mrow[0]);
            float p2 = __expf(accs[f][2] - mrow[1]);
            float p3 = __expf(accs[f][3] - mrow[1]);
            accs[f][0] = p0; accs[f][1] = p1; accs[f][2] = p2; accs[f][3] = p3;
            rsum[0] += p0 + p1;
            rsum[1] += p2 + p3;
        }
#pragma unroll
        for (int r = 0; r < 2; r++) {
            rsum[r] += __shfl_xor_sync(0xffffffff, rsum[r], 1);
            rsum[r] += __shfl_xor_sync(0xffffffff, rsum[r], 2);
            lrow[r] = lrow[r] * alpha[r] + rsum[r];
        }
#pragma unroll
        for (int a = 0; a < 8; a++) {
            acc_o[a][0] *= alpha[0]; acc_o[a][1] *= alpha[0];
            acc_o[a][2] *= alpha[1]; acc_o[a][3] *= alpha[1];
        }

        // ---- O += P.V (3-term: Ph*Vh + Ph*Vl + Pl*Vh) ----
#pragma unroll
        for (int kc = 0; kc < 8; kc++) {
            const int f0 = 2 * kc, f1 = 2 * kc + 1;
            uint32_t aPh[4], aPl[4];
            aPh[0] = packbf(accs[f0][0], accs[f0][1]);
            aPh[1] = packbf(accs[f0][2], accs[f0][3]);
            aPh[2] = packbf(accs[f1][0], accs[f1][1]);
            aPh[3] = packbf(accs[f1][2], accs[f1][3]);
            aPl[0] = packbf(bfres(accs[f0][0]), bfres(accs[f0][1]));
            aPl[1] = packbf(bfres(accs[f0][2]), bfres(accs[f0][3]));
            aPl[2] = packbf(bfres(accs[f1][0]), bfres(accs[f1][1]));
            aPl[3] = packbf(bfres(accs[f1][2]), bfres(accs[f1][3]));
#pragma unroll
            for (int jg = 0; jg < 4; jg++) {
                uint32_t v4h[4], v4l[4];
                uint32_t off = (uint32_t)(kc * 16) * FROWB + jg * 32;
                ldmx4t(v4h, uVh + off);
                ldmx4t(v4l, uVl + off);
                mma_bf16(acc_o[2 * jg],     aPh, v4h);
                mma_bf16(acc_o[2 * jg + 1], aPh, v4h + 2);
                mma_bf16(acc_o[2 * jg],     aPh, v4l);
                mma_bf16(acc_o[2 * jg + 1], aPh, v4l + 2);
                mma_bf16(acc_o[2 * jg],     aPl, v4h);
                mma_bf16(acc_o[2 * jg + 1], aPl, v4h + 2);
            }
        }
    }

    // ---- epilogue ----
    const float inv0 = 1.f / lrow[0], inv1 = 1.f / lrow[1];
    const int row0 = qt * 128 + wid * 16 + qr;
#pragma unroll
    for (int a = 0; a < 8; a++) {
        int col = a * 8 + qc;
        size_t i0 = ((size_t)b * S_ + row0) * D_ + h * 64 + col;
        size_t i1 = ((size_t)b * S_ + row0 + 8) * D_ + h * 64 + col;
        float v00 = acc_o[a][0] * inv0, v01 = acc_o[a][1] * inv0;
        float v10 = acc_o[a][2] * inv1, v11 = acc_o[a][3] * inv1;
        bf16 h00 = __float2bfloat16(v00), h01 = __float2bfloat16(v01);
        bf16 h10 = __float2bfloat16(v10), h11 = __float2bfloat16(v11);
        *(__nv_bfloat162*)&ctxh[i0] = __nv_bfloat162(h00, h01);
        *(__nv_bfloat162*)&ctxh[i1] = __nv_bfloat162(h10, h11);
        *(__nv_bfloat162*)&ctxl[i0] = __nv_bfloat162(
            __float2bfloat16(v00 - __bfloat162float(h00)),
            __float2bfloat16(v01 - __bfloat162float(h01)));
        *(__nv_bfloat162*)&ctxl[i1] = __nv_bfloat162(
            __float2bfloat16(v10 - __bfloat162float(h10)),
            __float2bfloat16(v11 - __bfloat162float(h11)));
    }
}

// ---------------------------------------------------------------------------
// fp32 -> bf16 hi/lo split (elementwise, vectorized)
// ---------------------------------------------------------------------------
__global__ __launch_bounds__(256)
void split_kernel(const float* __restrict__ X, bf16* __restrict__ Xh,
                  bf16* __restrict__ Xl, size_t n4)
{
    size_t i = (size_t)blockIdx.x * 256 + threadIdx.x;
    if (i >= n4) return;
    float4 v = ((const float4*)X)[i];
    bf16 h0 = __float2bfloat16(v.x), h1 = __float2bfloat16(v.y);
    bf16 h2 = __float2bfloat16(v.z), h3 = __float2bfloat16(v.w);
    size_t o = i * 4;
    Xh[o] = h0; Xh[o+1] = h1; Xh[o+2] = h2; Xh[o+3] = h3;
    Xl[o]   = __float2bfloat16(v.x - __bfloat162float(h0));
    Xl[o+1] = __float2bfloat16(v.y - __bfloat162float(h1));
    Xl[o+2] = __float2bfloat16(v.z - __bfloat162float(h2));
    Xl[o+3] = __float2bfloat16(v.w - __bfloat162float(h3));
}

// ---------------------------------------------------------------------------
// All 6 weight transposes+splits in ONE launch.
// ---------------------------------------------------------------------------
__global__ __launch_bounds__(256)
void tsplit_all_kernel(const float* __restrict__ wq, const float* __restrict__ wk,
                       const float* __restrict__ wv, const float* __restrict__ wo,
                       const float* __restrict__ w1, const float* __restrict__ w2,
                       bf16* __restrict__ qTh, bf16* __restrict__ qTl,
                       bf16* __restrict__ kTh, bf16* __restrict__ kTl,
                       bf16* __restrict__ vTh, bf16* __restrict__ vTl,
                       bf16* __restrict__ oTh, bf16* __restrict__ oTl,
                       bf16* __restrict__ w1Th, bf16* __restrict__ w1Tl,
                       bf16* __restrict__ w2Th, bf16* __restrict__ w2Tl)
{
    const int idx = blockIdx.x;
    const float* W; bf16 *Th, *Tl;
    int K, N, bx, by;
    if (idx < 4096) {
        const int seg = idx >> 10, r = idx & 1023;
        bx = r & 31; by = r >> 5; K = D_; N = D_;
        W  = (seg == 0) ? wq  : (seg == 1) ? wk  : (seg == 2) ? wv  : wo;
        Th = (seg == 0) ? qTh : (seg == 1) ? kTh : (seg == 2) ? vTh : oTh;
        Tl = (seg == 0) ? qTl : (seg == 1) ? kTl : (seg == 2) ? vTl : oTl;
    } else if (idx < 8192) {
        const int r = idx - 4096;
        bx = r & 127; by = r >> 7; K = D_; N = DFF_;
        W = w1; Th = w1Th; Tl = w1Tl;
    } else {
        const int r = idx - 8192;
        bx = r & 31; by = r >> 5; K = DFF_; N = D_;
        W = w2; Th = w2Th; Tl = w2Tl;
    }

    __shared__ float t[32][33];
    const int k0 = by * 32, n0 = bx * 32;
    const int tx = threadIdx.x & 31, ty = threadIdx.x >> 5;
    for (int r = ty; r < 32; r += 8)
        t[r][tx] = W[(size_t)(k0 + r) * N + n0 + tx];
    __syncthreads();
    for (int r = ty; r < 32; r += 8) {
        float v = t[tx][r];
        bf16 h = __float2bfloat16(v);
        size_t oi = (size_t)(n0 + r) * K + k0 + tx;
        Th[oi] = h;
        Tl[oi] = __float2bfloat16(v - __bfloat162float(h));
    }
}

// ---------------------------------------------------------------------------
// out = LayerNorm(x + y) * g + b; optionally also emit bf16 hi/lo split
// ---------------------------------------------------------------------------
__global__ __launch_bounds__(256)
void add_ln_kernel(const float* __restrict__ x, const float* __restrict__ y,
                   const float* __restrict__ g, const float* __restrict__ b,
                   float* __restrict__ out, bf16* __restrict__ oh,
                   bf16* __restrict__ ol)
{
    __shared__ float red[256];
    const size_t base = (size_t)blockIdx.x * D_;
    const int tid = threadIdx.x;

    float v[4];
    float s = 0.f;
#pragma unroll
    for (int l = 0; l < 4; l++) {
        int i = tid + l * 256;
        v[l] = x[base + i] + y[base + i];
        s += v[l];
    }
    red[tid] = s; __syncthreads();
    for (int st = 128; st > 0; st >>= 1) {
        if (tid < st) red[tid] += red[tid + st];
        __syncthreads();
    }
    float mean = red[0] * (1.0f / D_); __syncthreads();

    float sq = 0.f;
#pragma unroll
    for (int l = 0; l < 4; l++) { float d = v[l] - mean; sq += d * d; }
    red[tid] = sq; __syncthreads();
    for (int st = 128; st > 0; st >>= 1) {
        if (tid < st) red[tid] += red[tid + st];
        __syncthreads();
    }
    float rstd = rsqrtf(red[0] * (1.0f / D_) + 1e-5f);

#pragma unroll
    for (int l = 0; l < 4; l++) {
        int i = tid + l * 256;
        float o = (v[l] - mean) * rstd * g[i] + b[i];
        out[base + i] = o;
        if (oh) {
            bf16 hh = __float2bfloat16(o);
            oh[base + i] = hh;
            ol[base + i] = __float2bfloat16(o - __bfloat162float(hh));
        }
    }
}

// ---------------------------------------------------------------------------
// Launch
// ---------------------------------------------------------------------------
extern "C" void kernel_launch(void* const* d_in, const int* in_sizes, int n_in,
                              void* d_out, int out_size)
{
    const float* x    = (const float*)d_in[0];
    const float* wq   = (const float*)d_in[1];
    const float* bq   = (const float*)d_in[2];
    const float* wk   = (const float*)d_in[3];
    const float* bk   = (const float*)d_in[4];
    const float* wv   = (const float*)d_in[5];
    const float* bv   = (const float*)d_in[6];
    const float* wo   = (const float*)d_in[7];
    const float* bo   = (const float*)d_in[8];
    const float* rel  = (const float*)d_in[9];
    const float* ln1g = (const float*)d_in[10];
    const float* ln1b = (const float*)d_in[11];
    const float* w1   = (const float*)d_in[12];
    const float* b1   = (const float*)d_in[13];
    const float* w2   = (const float*)d_in[14];
    const float* b2   = (const float*)d_in[15];
    const float* ln2g = (const float*)d_in[16];
    const float* ln2b = (const float*)d_in[17];
    const int*   mask = (const int*)  d_in[18];
    float* out = (float*)d_out;

    float *pt1, *px1;
    bf16 *pxh, *pxl, *pqh, *pql, *pkh, *pkl, *pvh, *pvl;
    bf16 *pctxh, *pctxl, *px1h, *px1l, *pffh, *pffl;
    bf16 *wqTh, *wqTl, *wkTh, *wkTl, *wvTh, *wvTl, *woTh, *woTl;
    bf16 *w1Th, *w1Tl, *w2Th, *w2Tl;
    cudaGetSymbolAddress((void**)&pt1,  g_t1);
    cudaGetSymbolAddress((void**)&px1,  g_x1);
    cudaGetSymbolAddress((void**)&pxh,  g_xh);
    cudaGetSymbolAddress((void**)&pxl,  g_xl);
    cudaGetSymbolAddress((void**)&pqh,  g_qh);
    cudaGetSymbolAddress((void**)&pql,  g_ql);
    cudaGetSymbolAddress((void**)&pkh,  g_kh);
    cudaGetSymbolAddress((void**)&pkl,  g_kl);
    cudaGetSymbolAddress((void**)&pvh,  g_vh);
    cudaGetSymbolAddress((void**)&pvl,  g_vl);
    cudaGetSymbolAddress((void**)&pctxh, g_ctxh);
    cudaGetSymbolAddress((void**)&pctxl, g_ctxl);
    cudaGetSymbolAddress((void**)&px1h, g_x1h);
    cudaGetSymbolAddress((void**)&px1l, g_x1l);
    cudaGetSymbolAddress((void**)&pffh, g_ffh);
    cudaGetSymbolAddress((void**)&pffl, g_ffl);
    cudaGetSymbolAddress((void**)&wqTh, g_wqTh);
    cudaGetSymbolAddress((void**)&wqTl, g_wqTl);
    cudaGetSymbolAddress((void**)&wkTh, g_wkTh);
    cudaGetSymbolAddress((void**)&wkTl, g_wkTl);
    cudaGetSymbolAddress((void**)&wvTh, g_wvTh);
    cudaGetSymbolAddress((void**)&wvTl, g_wvTl);
    cudaGetSymbolAddress((void**)&woTh, g_woTh);
    cudaGetSymbolAddress((void**)&woTl, g_woTl);
    cudaGetSymbolAddress((void**)&w1Th, g_w1Th);
    cudaGetSymbolAddress((void**)&w1Tl, g_w1Tl);
    cudaGetSymbolAddress((void**)&w2Th, g_w2Th);
    cudaGetSymbolAddress((void**)&w2Tl, g_w2Tl);

    cudaFuncSetAttribute(gemm_tc_kernel,
                         cudaFuncAttributeMaxDynamicSharedMemorySize, GEMM_SMEM);
    cudaFuncSetAttribute(flash_attn_kernel,
                         cudaFuncAttributeMaxDynamicSharedMemorySize, FLASH_SMEM);

    dim3 blk(256);

    // 1: input split
    split_kernel<<<(NR_ * D_ / 4 + 255) / 256, blk>>>(x, pxh, pxl, (size_t)NR_ * D_ / 4);
    // 2: all weight transposes+splits
    tsplit_all_kernel<<<12288, blk>>>(wq, wk, wv, wo, w1, w2,
                                      wqTh, wqTl, wkTh, wkTl, wvTh, wvTl,
                                      woTh, woTl, w1Th, w1Tl, w2Th, w2Tl);

    // 3-5: QKV projections -> bf16 hi/lo outputs
    dim3 gProj(D_ / 128, NR_ / 128);
    gemm_tc_kernel<<<gProj, blk, GEMM_SMEM>>>(pxh, pxl, wqTh, wqTl, bq, nullptr,
                                              pqh, pql, NR_, D_, D_, 0);
    gemm_tc_kernel<<<gProj, blk, GEMM_SMEM>>>(pxh, pxl, wkTh, wkTl, bk, nullptr,
                                              pkh, pkl, NR_, D_, D_, 0);
    gemm_tc_kernel<<<gProj, blk, GEMM_SMEM>>>(pxh, pxl, wvTh, wvTl, bv, nullptr,
                                              pvh, pvl, NR_, D_, D_, 0);

    // 6: fused flash attention
    flash_attn_kernel<<<dim3(S_ / 128, BH_), blk, FLASH_SMEM>>>(
        pqh, pql, pkh, pkl, pvh, pvl, rel, mask, pctxh, pctxl);

    // 7: O projection
    gemm_tc_kernel<<<gProj, blk, GEMM_SMEM>>>(pctxh, pctxl, woTh, woTl, bo, pt1,
                                              nullptr, nullptr, NR_, D_, D_, 0);

    // 8: x1 = LN(x + attn_out), with split
    add_ln_kernel<<<NR_, blk>>>(x, pt1, ln1g, ln1b, px1, px1h, px1l);

    // 9-10: FFN
    dim3 gF1(DFF_ / 128, NR_ / 128);
    gemm_tc_kernel<<<gF1, blk, GEMM_SMEM>>>(px1h, px1l, w1Th, w1Tl, b1, nullptr,
                                            pffh, pffl, NR_, DFF_, D_, 1);
    dim3 gF2(D_ / 128, NR_ / 128);
    gemm_tc_kernel<<<gF2, blk, GEMM_SMEM>>>(pffh, pffl, w2Th, w2Tl, b2, pt1,
                                            nullptr, nullptr, NR_, D_, DFF_, 0);

    // 11: out = LN(x1 + ff)
    add_ln_kernel<<<NR_, blk>>>(px1, pt1, ln2g, ln2b, out, nullptr, nullptr);
}

// round 10
// speedup vs baseline: 3.7909x; 1.0105x over previous
#include <cuda_runtime.h>
#include <cuda_bf16.h>
#include <math.h>
#include <stdint.h>

// Problem constants
#define B_   4
#define S_   1024
#define D_   1024
#define H_   16
#define DK_  64
#define DFF_ 4096
#define NR_  4096          // B*S rows
#define BH_  64            // B*H

typedef __nv_bfloat16 bf16;

// ---------------------------------------------------------------------------
// Scratch (device globals; .bss — no allocations)
// ---------------------------------------------------------------------------
__device__ float g_t1 [(size_t)NR_ * D_];
__device__ float g_x1 [(size_t)NR_ * D_];

__device__ bf16 g_xh  [(size_t)NR_ * D_];
__device__ bf16 g_xl  [(size_t)NR_ * D_];
__device__ bf16 g_qh  [(size_t)NR_ * D_];
__device__ bf16 g_ql  [(size_t)NR_ * D_];
__device__ bf16 g_kh  [(size_t)NR_ * D_];
__device__ bf16 g_kl  [(size_t)NR_ * D_];
__device__ bf16 g_vh  [(size_t)NR_ * D_];
__device__ bf16 g_vl  [(size_t)NR_ * D_];
__device__ bf16 g_ctxh[(size_t)NR_ * D_];
__device__ bf16 g_ctxl[(size_t)NR_ * D_];
__device__ bf16 g_x1h [(size_t)NR_ * D_];
__device__ bf16 g_x1l [(size_t)NR_ * D_];
__device__ bf16 g_ffh [(size_t)NR_ * DFF_];
__device__ bf16 g_ffl [(size_t)NR_ * DFF_];
// transposed+split weights
__device__ bf16 g_wqkvTh[(size_t)3 * D_ * D_];   // rows 0-1023 q, 1024-2047 k, 2048-3071 v
__device__ bf16 g_wqkvTl[(size_t)3 * D_ * D_];
__device__ bf16 g_woTh[(size_t)D_ * D_];
__device__ bf16 g_woTl[(size_t)D_ * D_];
__device__ bf16 g_w1Th[(size_t)DFF_ * D_];
__device__ bf16 g_w1Tl[(size_t)DFF_ * D_];
__device__ bf16 g_w2Th[(size_t)D_ * DFF_];
__device__ bf16 g_w2Tl[(size_t)D_ * DFF_];

// ---------------------------------------------------------------------------
// Warp-MMA / cp.async primitives
// ---------------------------------------------------------------------------
__device__ __forceinline__ uint32_t smem_to_u32(const void* p) {
    uint32_t a;
    asm("{ .reg .u64 t; cvta.to.shared.u64 t, %1; cvt.u32.u64 %0, t; }"
        : "=r"(a) : "l"(p));
    return a;
}

__device__ __forceinline__ void ldmx4(uint32_t* r, uint32_t addr) {
    asm volatile("ldmatrix.sync.aligned.m8n8.x4.shared.b16 {%0,%1,%2,%3}, [%4];"
                 : "=r"(r[0]), "=r"(r[1]), "=r"(r[2]), "=r"(r[3]) : "r"(addr));
}

__device__ __forceinline__ void ldmx4t(uint32_t* r, uint32_t addr) {
    asm volatile("ldmatrix.sync.aligned.m8n8.x4.trans.shared.b16 {%0,%1,%2,%3}, [%4];"
                 : "=r"(r[0]), "=r"(r[1]), "=r"(r[2]), "=r"(r[3]) : "r"(addr));
}

__device__ __forceinline__ void mma_bf16(float* c, const uint32_t* a,
                                         const uint32_t* b) {
    asm volatile(
        "mma.sync.aligned.m16n8k16.row.col.f32.bf16.bf16.f32 "
        "{%0,%1,%2,%3}, {%4,%5,%6,%7}, {%8,%9}, {%0,%1,%2,%3};"
        : "+f"(c[0]), "+f"(c[1]), "+f"(c[2]), "+f"(c[3])
        : "r"(a[0]), "r"(a[1]), "r"(a[2]), "r"(a[3]), "r"(b[0]), "r"(b[1]));
}

__device__ __forceinline__ uint32_t packbf(float lo, float hi) {
    uint32_t r;
    asm("cvt.rn.bf16x2.f32 %0, %1, %2;" : "=r"(r) : "f"(hi), "f"(lo));
    return r;
}
__device__ __forceinline__ float bfres(float x) {
    return x - __bfloat162float(__float2bfloat16(x));
}

#define CP_ASYNC16(dst, src) \
    asm volatile("cp.async.cg.shared.global [%0], [%1], 16;" \
                 :: "r"(dst), "l"(src) : "memory")
#define CP_COMMIT() asm volatile("cp.async.commit_group;" ::: "memory")
#define CP_WAIT(n)  asm volatile("cp.async.wait_group %0;" :: "n"(n) : "memory")

// ---------------------------------------------------------------------------
// GEMM core macros (shared by generic + fused-QKV kernels)
// K-chunk 32, 2-stage cp.async pipeline, 80B padded rows, 2 CTAs/SM.
// ---------------------------------------------------------------------------
#define GT_ROWB   80
#define GT_TILE   (128 * GT_ROWB)        // 10240
#define GT_STAGE  (4 * GT_TILE)          // 40960
#define GEMM_SMEM (2 * GT_STAGE)         // 81920

// issue one K-chunk's cp.async loads (chunk base k0) into stage `stg`
#define GEMM_ISSUE_CHUNK(stg, k0)                                              \
    do {                                                                       \
        _Pragma("unroll")                                                      \
        for (int l = 0; l < 8; l++) {                                          \
            int i = tid + l * 256;                                             \
            int t = i >> 9, j = i & 511;                                       \
            int row = j >> 2, kc = j & 3;                                      \
            uint32_t dst = sbase + (stg) + t * GT_TILE + row * GT_ROWB + kc * 16; \
            CP_ASYNC16(dst, srcs[t] + (size_t)row * K + (k0) + kc * 8);        \
        }                                                                      \
        CP_COMMIT();                                                           \
    } while (0)

// compute one K-chunk from stage `stg` (bLo loads hoisted next to bHi)
#define GEMM_COMPUTE_CHUNK(stg)                                                \
    do {                                                                       \
        const uint32_t aBaseHi = sbase + (stg) + 0 * GT_TILE + (uint32_t)warpM * 64 * GT_ROWB + aoff; \
        const uint32_t aBaseLo = sbase + (stg) + 1 * GT_TILE + (uint32_t)warpM * 64 * GT_ROWB + aoff; \
        const uint32_t bBaseHi = sbase + (stg) + 2 * GT_TILE + (uint32_t)warpN * 32 * GT_ROWB + boff; \
        const uint32_t bBaseLo = sbase + (stg) + 3 * GT_TILE + (uint32_t)warpN * 32 * GT_ROWB + boff; \
        _Pragma("unroll")                                                      \
        for (int ks = 0; ks < 2; ks++) {                                       \
            uint32_t af[4][4], bh_[4][2], bl_[4][2];                           \
            _Pragma("unroll")                                                  \
            for (int fm = 0; fm < 4; fm++)                                     \
                ldmx4(af[fm], aBaseHi + (uint32_t)fm * 16 * GT_ROWB + ks * 32);\
            _Pragma("unroll")                                                  \
            for (int g = 0; g < 2; g++) {                                      \
                uint32_t r[4];                                                 \
                ldmx4(r, bBaseHi + (uint32_t)g * 16 * GT_ROWB + ks * 32);      \
                bh_[g * 2][0] = r[0]; bh_[g * 2][1] = r[1];                    \
                bh_[g * 2 + 1][0] = r[2]; bh_[g * 2 + 1][1] = r[3];            \
            }                                                                  \
            _Pragma("unroll")                                                  \
            for (int g = 0; g < 2; g++) {                                      \
                uint32_t r[4];                                                 \
                ldmx4(r, bBaseLo + (uint32_t)g * 16 * GT_ROWB + ks * 32);      \
                bl_[g * 2][0] = r[0]; bl_[g * 2][1] = r[1];                    \
                bl_[g * 2 + 1][0] = r[2]; bl_[g * 2 + 1][1] = r[3];            \
            }                                                                  \
            _Pragma("unroll")                                                  \
            for (int fm = 0; fm < 4; fm++)                                     \
                _Pragma("unroll")                                              \
                for (int fn = 0; fn < 4; fn++)                                 \
                    mma_bf16(acc[fm][fn], af[fm], bh_[fn]);                    \
            _Pragma("unroll")                                                  \
            for (int fm = 0; fm < 4; fm++)                                     \
                _Pragma("unroll")                                              \
                for (int fn = 0; fn < 4; fn++)                                 \
                    mma_bf16(acc[fm][fn], af[fm], bl_[fn]);                    \
            _Pragma("unroll")                                                  \
            for (int fm = 0; fm < 4; fm++)                                     \
                ldmx4(af[fm], aBaseLo + (uint32_t)fm * 16 * GT_ROWB + ks * 32);\
            _Pragma("unroll")                                                  \
            for (int fm = 0; fm < 4; fm++)                                     \
                _Pragma("unroll")                                              \
                for (int fn = 0; fn < 4; fn++)                                 \
                    mma_bf16(acc[fm][fn], af[fm], bh_[fn]);                    \
        }                                                                      \
    } while (0)

// ---------------------------------------------------------------------------
// Generic GEMM: C[M,N] = A[M,K] @ B^T + bias (3-term bf16 split)
// ---------------------------------------------------------------------------
__global__ __launch_bounds__(256, 2)
void gemm_tc_kernel(const bf16* __restrict__ Ahi, const bf16* __restrict__ Alo,
                    const bf16* __restrict__ Bhi, const bf16* __restrict__ Blo,
                    const float* __restrict__ bias,
                    float* __restrict__ Cf,
                    bf16* __restrict__ Chi, bf16* __restrict__ Clo,
                    int M, int N, int K, int relu)
{
    extern __shared__ char smem[];
    const uint32_t sbase = smem_to_u32(smem);

    const int tid  = threadIdx.x;
    const int wid  = tid >> 5;
    const int lane = tid & 31;
    const int warpM = wid >> 2;
    const int warpN = wid & 3;
    const int m0 = blockIdx.y * 128;
    const int n0 = blockIdx.x * 128;

    const bf16* srcs[4] = { Ahi + (size_t)m0 * K, Alo + (size_t)m0 * K,
                            Bhi + (size_t)n0 * K, Blo + (size_t)n0 * K };

    float acc[4][4][4];
#pragma unroll
    for (int i = 0; i < 4; i++)
#pragma unroll
        for (int j = 0; j < 4; j++)
#pragma unroll
            for (int r = 0; r < 4; r++) acc[i][j][r] = 0.f;

    const uint32_t aoff = (uint32_t)(lane & 15) * GT_ROWB + (uint32_t)(lane >> 4) * 16;
    const uint32_t boff = (uint32_t)(((lane >> 4) * 8) + (lane & 7)) * GT_ROWB
                        + (uint32_t)((lane >> 3) & 1) * 16;

    const int nchunk = K >> 5;
    GEMM_ISSUE_CHUNK(0u, 0);

    for (int s = 0; s < nchunk; s++) {
        CP_WAIT(0);
        __syncthreads();
        if (s + 1 < nchunk)
            GEMM_ISSUE_CHUNK((uint32_t)((s + 1) & 1) * GT_STAGE, (s + 1) << 5);
        GEMM_COMPUTE_CHUNK((uint32_t)(s & 1) * GT_STAGE);
    }

    const int qr = lane >> 2;
    const int qc = (lane & 3) * 2;
#pragma unroll
    for (int fm = 0; fm < 4; fm++) {
#pragma unroll
        for (int fn = 0; fn < 4; fn++) {
            float* a = acc[fm][fn];
            int row = m0 + warpM * 64 + fm * 16 + qr;
            int col = n0 + warpN * 32 + fn * 8 + qc;
            float b0 = bias[col], b1 = bias[col + 1];
            float v00 = a[0] + b0, v01 = a[1] + b1;
            float v10 = a[2] + b0, v11 = a[3] + b1;
            if (relu) {
                v00 = fmaxf(v00, 0.f); v01 = fmaxf(v01, 0.f);
                v10 = fmaxf(v10, 0.f); v11 = fmaxf(v11, 0.f);
            }
            size_t i0 = (size_t)row * N + col;
            size_t i1 = (size_t)(row + 8) * N + col;
            if (Cf) {
                *(float2*)&Cf[i0] = make_float2(v00, v01);
                *(float2*)&Cf[i1] = make_float2(v10, v11);
            }
            if (Chi) {
                bf16 h00 = __float2bfloat16(v00), h01 = __float2bfloat16(v01);
                bf16 h10 = __float2bfloat16(v10), h11 = __float2bfloat16(v11);
                *(__nv_bfloat162*)&Chi[i0] = __nv_bfloat162(h00, h01);
                *(__nv_bfloat162*)&Chi[i1] = __nv_bfloat162(h10, h11);
                *(__nv_bfloat162*)&Clo[i0] = __nv_bfloat162(
                    __float2bfloat16(v00 - __bfloat162float(h00)),
                    __float2bfloat16(v01 - __bfloat162float(h01)));
                *(__nv_bfloat162*)&Clo[i1] = __nv_bfloat162(
                    __float2bfloat16(v10 - __bfloat162float(h10)),
                    __float2bfloat16(v11 - __bfloat162float(h11)));
            }
        }
    }
}

// ---------------------------------------------------------------------------
// Fused QKV GEMM: B = packed W^T [3072,1024]; out segment decoded from n0.
// Grid (24, 32). Outputs bf16 hi/lo into q/k/v buffers (each [4096,1024]).
// ---------------------------------------------------------------------------
__global__ __launch_bounds__(256, 2)
void gemm_qkv_kernel(const bf16* __restrict__ Ahi, const bf16* __restrict__ Alo,
                     const bf16* __restrict__ Bhi, const bf16* __restrict__ Blo,
                     const float* __restrict__ bq, const float* __restrict__ bk,
                     const float* __restrict__ bv,
                     bf16* __restrict__ qh, bf16* __restrict__ ql,
                     bf16* __restrict__ kh, bf16* __restrict__ kl,
                     bf16* __restrict__ vh, bf16* __restrict__ vl)
{
    extern __shared__ char smem[];
    const uint32_t sbase = smem_to_u32(smem);
    const int K = D_;

    const int tid  = threadIdx.x;
    const int wid  = tid >> 5;
    const int lane = tid & 31;
    const int warpM = wid >> 2;
    const int warpN = wid & 3;
    const int m0 = blockIdx.y * 128;
    const int n0g = blockIdx.x * 128;            // global packed col (0..3071)
    const int seg = n0g >> 10;
    const int n0 = n0g & 1023;                   // col within segment

    const float* bias = (seg == 0) ? bq : (seg == 1) ? bk : bv;
    bf16* Chi = (seg == 0) ? qh : (seg == 1) ? kh : vh;
    bf16* Clo = (seg == 0) ? ql : (seg == 1) ? kl : vl;

    const bf16* srcs[4] = { Ahi + (size_t)m0 * K, Alo + (size_t)m0 * K,
                            Bhi + (size_t)n0g * K, Blo + (size_t)n0g * K };

    float acc[4][4][4];
#pragma unroll
    for (int i = 0; i < 4; i++)
#pragma unroll
        for (int j = 0; j < 4; j++)
#pragma unroll
            for (int r = 0; r < 4; r++) acc[i][j][r] = 0.f;

    const uint32_t aoff = (uint32_t)(lane & 15) * GT_ROWB + (uint32_t)(lane >> 4) * 16;
    const uint32_t boff = (uint32_t)(((lane >> 4) * 8) + (lane & 7)) * GT_ROWB
                        + (uint32_t)((lane >> 3) & 1) * 16;

    const int nchunk = K >> 5;
    GEMM_ISSUE_CHUNK(0u, 0);

    for (int s = 0; s < nchunk; s++) {
        CP_WAIT(0);
        __syncthreads();
        if (s + 1 < nchunk)
            GEMM_ISSUE_CHUNK((uint32_t)((s + 1) & 1) * GT_STAGE, (s + 1) << 5);
        GEMM_COMPUTE_CHUNK((uint32_t)(s & 1) * GT_STAGE);
    }

    const int qr = lane >> 2;
    const int qc = (lane & 3) * 2;
#pragma unroll
    for (int fm = 0; fm < 4; fm++) {
#pragma unroll
        for (int fn = 0; fn < 4; fn++) {
            float* a = acc[fm][fn];
            int row = m0 + warpM * 64 + fm * 16 + qr;
            int col = n0 + warpN * 32 + fn * 8 + qc;
            float b0 = bias[col], b1 = bias[col + 1];
            float v00 = a[0] + b0, v01 = a[1] + b1;
            float v10 = a[2] + b0, v11 = a[3] + b1;
            size_t i0 = (size_t)row * D_ + col;
            size_t i1 = (size_t)(row + 8) * D_ + col;
            bf16 h00 = __float2bfloat16(v00), h01 = __float2bfloat16(v01);
            bf16 h10 = __float2bfloat16(v10), h11 = __float2bfloat16(v11);
            *(__nv_bfloat162*)&Chi[i0] = __nv_bfloat162(h00, h01);
            *(__nv_bfloat162*)&Chi[i1] = __nv_bfloat162(h10, h11);
            *(__nv_bfloat162*)&Clo[i0] = __nv_bfloat162(
                __float2bfloat16(v00 - __bfloat162float(h00)),
                __float2bfloat16(v01 - __bfloat162float(h01)));
            *(__nv_bfloat162*)&Clo[i1] = __nv_bfloat162(
                __float2bfloat16(v10 - __bfloat162float(h10)),
                __float2bfloat16(v11 - __bfloat162float(h11)));
        }
    }
}

// ---------------------------------------------------------------------------
// Fused flash attention, 2-stage cp.async K/V pipeline, ONE barrier per tile.
// ---------------------------------------------------------------------------
#define FROWB 144
#define FTILE (128 * FROWB)                      // 18432
#define FKV_STAGE (4 * FTILE)                    // 73728
#define FLASH_SMEM (10 * FTILE + 8192 + 4096)    // 196608

__global__ __launch_bounds__(256)
void flash_attn_kernel(const bf16* __restrict__ qh, const bf16* __restrict__ ql,
                       const bf16* __restrict__ kh, const bf16* __restrict__ kl,
                       const bf16* __restrict__ vh, const bf16* __restrict__ vl,
                       const float* __restrict__ rel, const int* __restrict__ mask,
                       bf16* __restrict__ ctxh, bf16* __restrict__ ctxl)
{
    extern __shared__ char smem[];
    const int qt = blockIdx.x;
    const int bhid = blockIdx.y;
    const int b = bhid >> 4, h = bhid & 15;
    const int tid = threadIdx.x, wid = tid >> 5, lane = tid & 31;
    const int qr = lane >> 2, qc = (lane & 3) * 2;

    const uint32_t ub = smem_to_u32(smem);
    float* s_rel = (float*)(smem + 10 * FTILE);
    int*   s_msk = (int*)(smem + 10 * FTILE + 8192);

    const bf16* kvsrc[4] = { kh, kl, vh, vl };

    {
        const size_t kg = ((size_t)b * S_) * D_ + h * 64;
#pragma unroll
        for (int l = 0; l < 16; l++) {
            int i = tid + l * 256;
            int t = i >> 10, j = i & 1023;
            int row = j >> 3, kc = j & 7;
            uint32_t dst = ub + 2 * FTILE + t * FTILE + row * FROWB + kc * 16;
            CP_ASYNC16(dst, kvsrc[t] + kg + (size_t)row * D_ + kc * 8);
        }
        CP_COMMIT();
    }

    const size_t qg = ((size_t)b * S_ + qt * 128) * D_ + h * 64;
#pragma unroll
    for (int l = 0; l < 8; l++) {
        int i = tid + l * 256;
        int t = i >> 10, j = i & 1023;
        int row = j >> 3, kc = j & 7;
        const bf16* src = t ? ql : qh;
        *(float4*)(smem + t * FTILE + row * FROWB + kc * 16) =
            *(const float4*)(src + qg + (size_t)row * D_ + kc * 8);
    }
    for (int i = tid; i < 2047; i += 256) s_rel[i] = rel[i * H_ + h];
    for (int i = tid; i < 1024; i += 256) s_msk[i] = mask[b * S_ + i];

    float acc_o[8][4];
#pragma unroll
    for (int a = 0; a < 8; a++) {
        acc_o[a][0] = acc_o[a][1] = acc_o[a][2] = acc_o[a][3] = 0.f;
    }
    float mrow[2] = {-1e30f, -1e30f}, lrow[2] = {0.f, 0.f};

    const uint32_t aoff = (uint32_t)(lane & 15) * FROWB + (uint32_t)(lane >> 4) * 16;
    const uint32_t boff = (uint32_t)(((lane >> 4) * 8) + (lane & 7)) * FROWB
                        + (uint32_t)((lane >> 3) & 1) * 16;
    const uint32_t uQh = ub + 0 * FTILE + (uint32_t)wid * 16 * FROWB + aoff;
    const uint32_t uQl = ub + 1 * FTILE + (uint32_t)wid * 16 * FROWB + aoff;
    const uint32_t vto = (uint32_t)(lane & 15) * FROWB + (uint32_t)(lane >> 4) * 16;

    for (int kt = 0; kt < 8; kt++) {
        CP_WAIT(0);
        __syncthreads();
        if (kt + 1 < 8) {
            const uint32_t stg = (uint32_t)((kt + 1) & 1) * FKV_STAGE;
            const size_t kg = ((size_t)b * S_ + (kt + 1) * 128) * D_ + h * 64;
#pragma unroll
            for (int l = 0; l < 16; l++) {
                int i = tid + l * 256;
                int t = i >> 10, j = i & 1023;
                int row = j >> 3, kc = j & 7;
                uint32_t dst = ub + 2 * FTILE + stg + t * FTILE + row * FROWB + kc * 16;
                CP_ASYNC16(dst, kvsrc[t] + kg + (size_t)row * D_ + kc * 8);
            }
            CP_COMMIT();
        }

        const uint32_t stg = (uint32_t)(kt & 1) * FKV_STAGE;
        const uint32_t uKh = ub + 2 * FTILE + stg + 0 * FTILE + boff;
        const uint32_t uKl = ub + 2 * FTILE + stg + 1 * FTILE + boff;
        const uint32_t uVh = ub + 2 * FTILE + stg + 2 * FTILE + vto;
        const uint32_t uVl = ub + 2 * FTILE + stg + 3 * FTILE + vto;

        float accs[16][4];
#pragma unroll
        for (int f = 0; f < 16; f++) {
            accs[f][0] = accs[f][1] = accs[f][2] = accs[f][3] = 0.f;
        }
#pragma unroll
        for (int ks = 0; ks < 4; ks++) {
            uint32_t aqh[4], aql4[4];
            ldmx4(aqh,  uQh + ks * 32);
            ldmx4(aql4, uQl + ks * 32);
#pragma unroll
            for (int g = 0; g < 8; g++) {
                uint32_t rkh[4], rkl[4];
                ldmx4(rkh, uKh + (uint32_t)g * 16 * FROWB + ks * 32);
                ldmx4(rkl, uKl + (uint32_t)g * 16 * FROWB + ks * 32);
                mma_bf16(accs[2 * g],     aqh,  rkh);
                mma_bf16(accs[2 * g + 1], aqh,  rkh + 2);
                mma_bf16(accs[2 * g],     aqh,  rkl);
                mma_bf16(accs[2 * g + 1], aqh,  rkl + 2);
                mma_bf16(accs[2 * g],     aql4, rkh);
                mma_bf16(accs[2 * g + 1], aql4, rkh + 2);
            }
        }

        const int rb0 = qt * 128 + wid * 16 + qr - kt * 128 + 1023;
        const int mb0 = kt * 128;
        float rmax[2] = {-1e30f, -1e30f};
#pragma unroll
        for (int f = 0; f < 16; f++) {
            int c0 = f * 8 + qc;
            float s0 = accs[f][0] * 0.125f + s_rel[rb0 - c0];
            float s1 = accs[f][1] * 0.125f + s_rel[rb0 - c0 - 1];
            float s2 = accs[f][2] * 0.125f + s_rel[rb0 + 8 - c0];
            float s3 = accs[f][3] * 0.125f + s_rel[rb0 + 8 - c0 - 1];
            if (s_msk[mb0 + c0] == 0)     { s0 = -1e9f; s2 = -1e9f; }
            if (s_msk[mb0 + c0 + 1] == 0) { s1 = -1e9f; s3 = -1e9f; }
            accs[f][0] = s0; accs[f][1] = s1; accs[f][2] = s2; accs[f][3] = s3;
            rmax[0] = fmaxf(rmax[0], fmaxf(s0, s1));
            rmax[1] = fmaxf(rmax[1], fmaxf(s2, s3));
        }
#pragma unroll
        for (int r = 0; r < 2; r++) {
            rmax[r] = fmaxf(rmax[r], __shfl_xor_sync(0xffffffff, rmax[r], 1));
            rmax[r] = fmaxf(rmax[r], __shfl_xor_sync(0xffffffff, rmax[r], 2));
        }
        float alpha[2];
#pragma unroll
        for (int r = 0; r < 2; r++) {
            float mn = fmaxf(mrow[r], rmax[r]);
            alpha[r] = __expf(mrow[r] - mn);
            mrow[r] = mn;
        }
        float rsum[2] = {0.f, 0.f};
#pragma unroll
        for (int f = 0; f < 16; f++) {
            float p0 = __expf(accs[f][0] - mrow[0]);
            float p1 = __expf(accs[f][1] - mrow[0]);
            float p2 = __expf(accs[f][2] - mrow[1]);
            float p3 = __expf(accs[f][3] - mrow[1]);
            accs[f][0] = p0; accs[f][1] = p1; accs[f][2] = p2; accs[f][3] = p3;
            rsum[0] += p0 + p1;
            rsum[1] += p2 + p3;
        }
#pragma unroll
        for (int r = 0; r < 2; r++) {
            rsum[r] += __shfl_xor_sync(0xffffffff, rsum[r], 1);
            rsum[r] += __shfl_xor_sync(0xffffffff, rsum[r], 2);
            lrow[r] = lrow[r] * alpha[r] + rsum[r];
        }
#pragma unroll
        for (int a = 0; a < 8; a++) {
            acc_o[a][0] *= alpha[0]; acc_o[a][1] *= alpha[0];
            acc_o[a][2] *= alpha[1]; acc_o[a][3] *= alpha[1];
        }

#pragma unroll
        for (int kc = 0; kc < 8; kc++) {
            const int f0 = 2 * kc, f1 = 2 * kc + 1;
            uint32_t aPh[4], aPl[4];
            aPh[0] = packbf(accs[f0][0], accs[f0][1]);
            aPh[1] = packbf(accs[f0][2], accs[f0][3]);
            aPh[2] = packbf(accs[f1][0], accs[f1][1]);
            aPh[3] = packbf(accs[f1][2], accs[f1][3]);
            aPl[0] = packbf(bfres(accs[f0][0]), bfres(accs[f0][1]));
            aPl[1] = packbf(bfres(accs[f0][2]), bfres(accs[f0][3]));
            aPl[2] = packbf(bfres(accs[f1][0]), bfres(accs[f1][1]));
            aPl[3] = packbf(bfres(accs[f1][2]), bfres(accs[f1][3]));
#pragma unroll
            for (int jg = 0; jg < 4; jg++) {
                uint32_t v4h[4], v4l[4];
                uint32_t off = (uint32_t)(kc * 16) * FROWB + jg * 32;
                ldmx4t(v4h, uVh + off);
                ldmx4t(v4l, uVl + off);
                mma_bf16(acc_o[2 * jg],     aPh, v4h);
                mma_bf16(acc_o[2 * jg + 1], aPh, v4h + 2);
                mma_bf16(acc_o[2 * jg],     aPh, v4l);
                mma_bf16(acc_o[2 * jg + 1], aPh, v4l + 2);
                mma_bf16(acc_o[2 * jg],     aPl, v4h);
                mma_bf16(acc_o[2 * jg + 1], aPl, v4h + 2);
            }
        }
    }

    const float inv0 = 1.f / lrow[0], inv1 = 1.f / lrow[1];
    const int row0 = qt * 128 + wid * 16 + qr;
#pragma unroll
    for (int a = 0; a < 8; a++) {
        int col = a * 8 + qc;
        size_t i0 = ((size_t)b * S_ + row0) * D_ + h * 64 + col;
        size_t i1 = ((size_t)b * S_ + row0 + 8) * D_ + h * 64 + col;
        float v00 = acc_o[a][0] * inv0, v01 = acc_o[a][1] * inv0;
        float v10 = acc_o[a][2] * inv1, v11 = acc_o[a][3] * inv1;
        bf16 h00 = __float2bfloat16(v00), h01 = __float2bfloat16(v01);
        bf16 h10 = __float2bfloat16(v10), h11 = __float2bfloat16(v11);
        *(__nv_bfloat162*)&ctxh[i0] = __nv_bfloat162(h00, h01);
        *(__nv_bfloat162*)&ctxh[i1] = __nv_bfloat162(h10, h11);
        *(__nv_bfloat162*)&ctxl[i0] = __nv_bfloat162(
            __float2bfloat16(v00 - __bfloat162float(h00)),
            __float2bfloat16(v01 - __bfloat162float(h01)));
        *(__nv_bfloat162*)&ctxl[i1] = __nv_bfloat162(
            __float2bfloat16(v10 - __bfloat162float(h10)),
            __float2bfloat16(v11 - __bfloat162float(h11)));
    }
}

// ---------------------------------------------------------------------------
// fp32 -> bf16 hi/lo split (elementwise, vectorized)
// ---------------------------------------------------------------------------
__global__ __launch_bounds__(256)
void split_kernel(const float* __restrict__ X, bf16* __restrict__ Xh,
                  bf16* __restrict__ Xl, size_t n4)
{
    size_t i = (size_t)blockIdx.x * 256 + threadIdx.x;
    if (i >= n4) return;
    float4 v = ((const float4*)X)[i];
    bf16 h0 = __float2bfloat16(v.x), h1 = __float2bfloat16(v.y);
    bf16 h2 = __float2bfloat16(v.z), h3 = __float2bfloat16(v.w);
    size_t o = i * 4;
    Xh[o] = h0; Xh[o+1] = h1; Xh[o+2] = h2; Xh[o+3] = h3;
    Xl[o]   = __float2bfloat16(v.x - __bfloat162float(h0));
    Xl[o+1] = __float2bfloat16(v.y - __bfloat162float(h1));
    Xl[o+2] = __float2bfloat16(v.z - __bfloat162float(h2));
    Xl[o+3] = __float2bfloat16(v.w - __bfloat162float(h3));
}

// ---------------------------------------------------------------------------
// All weight transposes+splits in ONE launch. 64(k)x32(n) tiles, bf162 stores.
// Blocks: [0,1536) qkv (512 each -> packed buffer), [1536,2048) wo,
//         [2048,4096) w1 (K=1024,N=4096), [4096,6144) w2 (K=4096,N=1024)
// ---------------------------------------------------------------------------
__global__ __launch_bounds__(256)
void tsplit_all_kernel(const float* __restrict__ wq, const float* __restrict__ wk,
                       const float* __restrict__ wv, const float* __restrict__ wo,
                       const float* __restrict__ w1, const float* __restrict__ w2,
                       bf16* __restrict__ qkvTh, bf16* __restrict__ qkvTl,
                       bf16* __restrict__ oTh, bf16* __restrict__ oTl,
                       bf16* __restrict__ w1Th, bf16* __restrict__ w1Tl,
                       bf16* __restrict__ w2Th, bf16* __restrict__ w2Tl)
{
    const int idx = blockIdx.x;
    const float* W; bf16 *Th, *Tl;
    int K, N, bx, by;
    if (idx < 1536) {
        const int seg = idx / 512, r = idx % 512;
        bx = r & 31; by = r >> 5; K = D_; N = D_;       // by 0..15 (16 k-tiles)
        W  = (seg == 0) ? wq : (seg == 1) ? wk : wv;
        Th = qkvTh + (size_t)seg * D_ * D_;
        Tl = qkvTl + (size_t)seg * D_ * D_;
    } else if (idx < 2048) {
        const int r = idx - 1536;
        bx = r & 31; by = r >> 5; K = D_; N = D_;
        W = wo; Th = oTh; Tl = oTl;
    } else if (idx < 4096) {
        const int r = idx - 2048;
        bx = r & 127; by = r >> 7; K = D_; N = DFF_;    // by 0..15
        W = w1; Th = w1Th; Tl = w1Tl;
    } else {
        const int r = idx - 4096;
        bx = r & 31; by = r >> 5; K = DFF_; N = D_;     // by 0..63
        W = w2; Th = w2Th; Tl = w2Tl;
    }

    __shared__ float t[64][33];
    const int k0 = by * 64, n0 = bx * 32;
    const int tx = threadIdx.x & 31, ty = threadIdx.x >> 5;
    for (int r = ty; r < 64; r += 8)
        t[r][tx] = W[(size_t)(k0 + r) * N + n0 + tx];
    __syncthreads();
    for (int rr = ty; rr < 32; rr += 8) {      // rr = n index
        float v0 = t[2 * tx][rr];
        float v1 = t[2 * tx + 1][rr];
        bf16 h0 = __float2bfloat16(v0);
        bf16 h1 = __float2bfloat16(v1);
        size_t oi = (size_t)(n0 + rr) * K + k0 + 2 * tx;
        *(__nv_bfloat162*)&Th[oi] = __nv_bfloat162(h0, h1);
        *(__nv_bfloat162*)&Tl[oi] = __nv_bfloat162(
            __float2bfloat16(v0 - __bfloat162float(h0)),
            __float2bfloat16(v1 - __bfloat162float(h1)));
    }
}

// ---------------------------------------------------------------------------
// out = LayerNorm(x + y) * g + b; optionally also emit bf16 hi/lo split
// ---------------------------------------------------------------------------
__global__ __launch_bounds__(256)
void add_ln_kernel(const float* __restrict__ x, const float* __restrict__ y,
                   const float* __restrict__ g, const float* __restrict__ b,
                   float* __restrict__ out, bf16* __restrict__ oh,
                   bf16* __restrict__ ol)
{
    __shared__ float red[256];
    const size_t base = (size_t)blockIdx.x * D_;
    const int tid = threadIdx.x;

    float v[4];
    float s = 0.f;
#pragma unroll
    for (int l = 0; l < 4; l++) {
        int i = tid + l * 256;
        v[l] = x[base + i] + y[base + i];
        s += v[l];
    }
    red[tid] = s; __syncthreads();
    for (int st = 128; st > 0; st >>= 1) {
        if (tid < st) red[tid] += red[tid + st];
        __syncthreads();
    }
    float mean = red[0] * (1.0f / D_); __syncthreads();

    float sq = 0.f;
#pragma unroll
    for (int l = 0; l < 4; l++) { float d = v[l] - mean; sq += d * d; }
    red[tid] = sq; __syncthreads();
    for (int st = 128; st > 0; st >>= 1) {
        if (tid < st) red[tid] += red[tid + st];
        __syncthreads();
    }
    float rstd = rsqrtf(red[0] * (1.0f / D_) + 1e-5f);

#pragma unroll
    for (int l = 0; l < 4; l++) {
        int i = tid + l * 256;
        float o = (v[l] - mean) * rstd * g[i] + b[i];
        out[base + i] = o;
        if (oh) {
            bf16 hh = __float2bfloat16(o);
            oh[base + i] = hh;
            ol[base + i] = __float2bfloat16(o - __bfloat162float(hh));
        }
    }
}

// ---------------------------------------------------------------------------
// Launch
// ---------------------------------------------------------------------------
extern "C" void kernel_launch(void* const* d_in, const int* in_sizes, int n_in,
                              void* d_out, int out_size)
{
    const float* x    = (const float*)d_in[0];
    const float* wq   = (const float*)d_in[1];
    const float* bq   = (const float*)d_in[2];
    const float* wk   = (const float*)d_in[3];
    const float* bk   = (const float*)d_in[4];
    const float* wv   = (const float*)d_in[5];
    const float* bv   = (const float*)d_in[6];
    const float* wo   = (const float*)d_in[7];
    const float* bo   = (const float*)d_in[8];
    const float* rel  = (const float*)d_in[9];
    const float* ln1g = (const float*)d_in[10];
    const float* ln1b = (const float*)d_in[11];
    const float* w1   = (const float*)d_in[12];
    const float* b1   = (const float*)d_in[13];
    const float* w2   = (const float*)d_in[14];
    const float* b2   = (const float*)d_in[15];
    const float* ln2g = (const float*)d_in[16];
    const float* ln2b = (const float*)d_in[17];
    const int*   mask = (const int*)  d_in[18];
    float* out = (float*)d_out;

    float *pt1, *px1;
    bf16 *pxh, *pxl, *pqh, *pql, *pkh, *pkl, *pvh, *pvl;
    bf16 *pctxh, *pctxl, *px1h, *px1l, *pffh, *pffl;
    bf16 *wqkvTh, *wqkvTl, *woTh, *woTl, *w1Th, *w1Tl, *w2Th, *w2Tl;
    cudaGetSymbolAddress((void**)&pt1,  g_t1);
    cudaGetSymbolAddress((void**)&px1,  g_x1);
    cudaGetSymbolAddress((void**)&pxh,  g_xh);
    cudaGetSymbolAddress((void**)&pxl,  g_xl);
    cudaGetSymbolAddress((void**)&pqh,  g_qh);
    cudaGetSymbolAddress((void**)&pql,  g_ql);
    cudaGetSymbolAddress((void**)&pkh,  g_kh);
    cudaGetSymbolAddress((void**)&pkl,  g_kl);
    cudaGetSymbolAddress((void**)&pvh,  g_vh);
    cudaGetSymbolAddress((void**)&pvl,  g_vl);
    cudaGetSymbolAddress((void**)&pctxh, g_ctxh);
    cudaGetSymbolAddress((void**)&pctxl, g_ctxl);
    cudaGetSymbolAddress((void**)&px1h, g_x1h);
    cudaGetSymbolAddress((void**)&px1l, g_x1l);
    cudaGetSymbolAddress((void**)&pffh, g_ffh);
    cudaGetSymbolAddress((void**)&pffl, g_ffl);
    cudaGetSymbolAddress((void**)&wqkvTh, g_wqkvTh);
    cudaGetSymbolAddress((void**)&wqkvTl, g_wqkvTl);
    cudaGetSymbolAddress((void**)&woTh, g_woTh);
    cudaGetSymbolAddress((void**)&woTl, g_woTl);
    cudaGetSymbolAddress((void**)&w1Th, g_w1Th);
    cudaGetSymbolAddress((void**)&w1Tl, g_w1Tl);
    cudaGetSymbolAddress((void**)&w2Th, g_w2Th);
    cudaGetSymbolAddress((void**)&w2Tl, g_w2Tl);

    cudaFuncSetAttribute(gemm_tc_kernel,
                         cudaFuncAttributeMaxDynamicSharedMemorySize, GEMM_SMEM);
    cudaFuncSetAttribute(gemm_qkv_kernel,
                         cudaFuncAttributeMaxDynamicSharedMemorySize, GEMM_SMEM);
    cudaFuncSetAttribute(flash_attn_kernel,
                         cudaFuncAttributeMaxDynamicSharedMemorySize, FLASH_SMEM);

    dim3 blk(256);

    // 1: input split
    split_kernel<<<(NR_ * D_ / 4 + 255) / 256, blk>>>(x, pxh, pxl, (size_t)NR_ * D_ / 4);
    // 2: all weight transposes+splits
    tsplit_all_kernel<<<6144, blk>>>(wq, wk, wv, wo, w1, w2,
                                     wqkvTh, wqkvTl, woTh, woTl,
                                     w1Th, w1Tl, w2Th, w2Tl);

    // 3: fused QKV projection (N=3072 packed)
    gemm_qkv_kernel<<<dim3(24, NR_ / 128), blk, GEMM_SMEM>>>(
        pxh, pxl, wqkvTh, wqkvTl, bq, bk, bv,
        pqh, pql, pkh, pkl, pvh, pvl);

    // 4: fused flash attention
    flash_attn_kernel<<<dim3(S_ / 128, BH_), blk, FLASH_SMEM>>>(
        pqh, pql, pkh, pkl, pvh, pvl, rel, mask, pctxh, pctxl);

    // 5: O projection
    dim3 gProj(D_ / 128, NR_ / 128);
    gemm_tc_kernel<<<gProj, blk, GEMM_SMEM>>>(pctxh, pctxl, woTh, woTl, bo, pt1,
                                              nullptr, nullptr, NR_, D_, D_, 0);

    // 6: x1 = LN(x + attn_out), with split
    add_ln_kernel<<<NR_, blk>>>(x, pt1, ln1g, ln1b, px1, px1h, px1l);

    // 7-8: FFN
    dim3 gF1(DFF_ / 128, NR_ / 128);
    gemm_tc_kernel<<<gF1, blk, GEMM_SMEM>>>(px1h, px1l, w1Th, w1Tl, b1, nullptr,
                                            pffh, pffl, NR_, DFF_, D_, 1);
    dim3 gF2(D_ / 128, NR_ / 128);
    gemm_tc_kernel<<<gF2, blk, GEMM_SMEM>>>(pffh, pffl, w2Th, w2Tl, b2, pt1,
                                            nullptr, nullptr, NR_, D_, DFF_, 0);

    // 9: out = LN(x1 + ff)
    add_ln_kernel<<<NR_, blk>>>(px1, pt1, ln2g, ln2b, out, nullptr, nullptr);
}